// round 1
// baseline (speedup 1.0000x reference)
#include <cuda_runtime.h>
#include <math.h>

// ---------------- problem dims ----------------
#define TB 2048      // B*S tokens
#define SEQ 1024
#define BATCH 2
#define DIM 768
#define NH 12
#define HD 64
#define DLAT 192
#define DFF 3072
#define NE 8
#define NV 32000
#define NLAYER 2

// ---------------- scratch (device globals; no allocation) ----------------
__device__ float g_x[TB * DIM];
__device__ float g_h[TB * DIM];
__device__ float g_q[TB * DIM];
__device__ float g_k[TB * DIM];
__device__ float g_v[TB * DIM];
__device__ float g_lat[TB * DLAT];
__device__ float g_ao[TB * DIM];
__device__ float g_logits[TB * NE];
__device__ float g_tw[TB * 2];
__device__ int   g_te[TB * 2];
__device__ int   g_counts[NE];
__device__ int   g_offsets[NE];
__device__ int   g_cursor[NE];
__device__ int   g_rowtok[2 * TB];
__device__ float g_roww[2 * TB];
__device__ int   g_perm[2 * TB];
__device__ float g_xe[2 * TB * DIM];
__device__ float g_hff[2 * TB * DFF];
__device__ float g_yff[2 * TB * DIM];

// ---------------- embedding gather ----------------
__global__ void embed_kernel(const int* __restrict__ ids, const float* __restrict__ emb) {
    int t = blockIdx.x;
    const float* src = emb + (size_t)ids[t] * DIM;
    for (int d = threadIdx.x; d < DIM; d += blockDim.x)
        g_x[t * DIM + d] = src[d];
}

// ---------------- layernorm (row = token, 256 threads, 3 elems/thread) ----
__global__ void ln_kernel(const float* __restrict__ x, const float* __restrict__ g,
                          const float* __restrict__ b, float* __restrict__ out) {
    int row = blockIdx.x;
    int t = threadIdx.x;
    const float* xr = x + (size_t)row * DIM;
    float v0 = xr[t], v1 = xr[t + 256], v2 = xr[t + 512];
    __shared__ float red[256];
    red[t] = v0 + v1 + v2;
    __syncthreads();
    for (int o = 128; o > 0; o >>= 1) { if (t < o) red[t] += red[t + o]; __syncthreads(); }
    float mean = red[0] * (1.0f / DIM);
    __syncthreads();
    float d0 = v0 - mean, d1 = v1 - mean, d2 = v2 - mean;
    red[t] = d0 * d0 + d1 * d1 + d2 * d2;
    __syncthreads();
    for (int o = 128; o > 0; o >>= 1) { if (t < o) red[t] += red[t + o]; __syncthreads(); }
    float rstd = rsqrtf(red[0] * (1.0f / DIM) + 1e-6f);
    float* orow = out + (size_t)row * DIM;
    orow[t]       = d0 * rstd * g[t]       + b[t];
    orow[t + 256] = d1 * rstd * g[t + 256] + b[t + 256];
    orow[t + 512] = d2 * rstd * g[t + 512] + b[t + 512];
}

// ---------------- gelu (JAX approximate=True / tanh form) ----------------
__device__ __forceinline__ float gelu_f(float x) {
    const float k0 = 0.7978845608028654f;
    float x3 = x * x * x;
    return 0.5f * x * (1.0f + tanhf(k0 * (x + 0.044715f * x3)));
}

#define FLAG_ACC 1
#define FLAG_GELU 2

// ---------------- generic SGEMM: C(=|+=) act(A[MxK] @ B[KxN] + bias) --------
// Requires: M,N multiples of 64, K multiple of 16. 256 threads, 64x64 tile.
__global__ void sgemm_kernel(const float* __restrict__ A, const float* __restrict__ Bm,
                             const float* __restrict__ bias, float* __restrict__ C,
                             int M, int N, int K, int flags) {
    __shared__ float As[16][64];
    __shared__ float Bs[16][68];
    int tid = threadIdx.x;
    int m0 = blockIdx.y * 64, n0 = blockIdx.x * 64;
    int tx = tid & 15, ty = tid >> 4;
    int arow = tid >> 2, acol = (tid & 3) * 4;
    int brow = tid >> 4, bcol = (tid & 15) * 4;
    float c[4][4] = {};
    for (int kt = 0; kt < K; kt += 16) {
        float4 a = *(const float4*)(A + (size_t)(m0 + arow) * K + kt + acol);
        As[acol + 0][arow] = a.x; As[acol + 1][arow] = a.y;
        As[acol + 2][arow] = a.z; As[acol + 3][arow] = a.w;
        *(float4*)&Bs[brow][bcol] =
            *(const float4*)(Bm + (size_t)(kt + brow) * N + n0 + bcol);
        __syncthreads();
#pragma unroll
        for (int k = 0; k < 16; k++) {
            float4 ra4 = *(const float4*)&As[k][ty * 4];
            float4 rb4 = *(const float4*)&Bs[k][tx * 4];
            float ra[4] = {ra4.x, ra4.y, ra4.z, ra4.w};
            float rb[4] = {rb4.x, rb4.y, rb4.z, rb4.w};
#pragma unroll
            for (int i = 0; i < 4; i++)
#pragma unroll
                for (int j = 0; j < 4; j++) c[i][j] += ra[i] * rb[j];
        }
        __syncthreads();
    }
#pragma unroll
    for (int i = 0; i < 4; i++) {
        int m = m0 + ty * 4 + i;
#pragma unroll
        for (int j = 0; j < 4; j++) {
            int n = n0 + tx * 4 + j;
            float val = c[i][j];
            if (bias) val += bias[n];
            if (flags & FLAG_GELU) val = gelu_f(val);
            float* cp = C + (size_t)m * N + n;
            if (flags & FLAG_ACC) *cp += val; else *cp = val;
        }
    }
}

// ---------------- MoE segmented SGEMM (blockIdx.z = expert) -----------------
__global__ void sgemm_moe_kernel(const float* __restrict__ Abase, const float* __restrict__ Bbase,
                                 const float* __restrict__ biasbase, float* __restrict__ Cbase,
                                 int N, int K, int flags) {
    __shared__ float As[16][64];
    __shared__ float Bs[16][68];
    int e = blockIdx.z;
    int cnt = g_counts[e];
    int m0 = blockIdx.y * 64;
    if (m0 >= cnt) return;
    int off = g_offsets[e];
    const float* A = Abase + (size_t)off * K;
    const float* Bm = Bbase + (size_t)e * K * N;
    const float* bias = biasbase + (size_t)e * N;
    float* C = Cbase + (size_t)off * N;

    int tid = threadIdx.x;
    int n0 = blockIdx.x * 64;
    int tx = tid & 15, ty = tid >> 4;
    int arow = tid >> 2, acol = (tid & 3) * 4;
    int brow = tid >> 4, bcol = (tid & 15) * 4;
    float c[4][4] = {};
    bool avalid = (m0 + arow) < cnt;
    for (int kt = 0; kt < K; kt += 16) {
        float4 a = make_float4(0.f, 0.f, 0.f, 0.f);
        if (avalid) a = *(const float4*)(A + (size_t)(m0 + arow) * K + kt + acol);
        As[acol + 0][arow] = a.x; As[acol + 1][arow] = a.y;
        As[acol + 2][arow] = a.z; As[acol + 3][arow] = a.w;
        *(float4*)&Bs[brow][bcol] =
            *(const float4*)(Bm + (size_t)(kt + brow) * N + n0 + bcol);
        __syncthreads();
#pragma unroll
        for (int k = 0; k < 16; k++) {
            float4 ra4 = *(const float4*)&As[k][ty * 4];
            float4 rb4 = *(const float4*)&Bs[k][tx * 4];
            float ra[4] = {ra4.x, ra4.y, ra4.z, ra4.w};
            float rb[4] = {rb4.x, rb4.y, rb4.z, rb4.w};
#pragma unroll
            for (int i = 0; i < 4; i++)
#pragma unroll
                for (int j = 0; j < 4; j++) c[i][j] += ra[i] * rb[j];
        }
        __syncthreads();
    }
#pragma unroll
    for (int i = 0; i < 4; i++) {
        int m = m0 + ty * 4 + i;
        if (m >= cnt) continue;
#pragma unroll
        for (int j = 0; j < 4; j++) {
            int n = n0 + tx * 4 + j;
            float val = c[i][j] + bias[n];
            if (flags & FLAG_GELU) val = gelu_f(val);
            C[(size_t)m * N + n] = val;
        }
    }
}

// ---------------- RoPE on q and k (in place) ----------------
__global__ void rope_kernel() {
    int idx = blockIdx.x * blockDim.x + threadIdx.x;
    if (idx >= TB * NH * 32) return;
    int j = idx & 31;
    int h = (idx >> 5) % NH;
    int t = idx / (32 * NH);
    int s = t % SEQ;
    float inv = powf(10000.0f, -(float)j * (1.0f / 32.0f));
    float ang = (float)s * inv;
    float sn, cs;
    sincosf(ang, &sn, &cs);
    int base = t * DIM + h * HD;
    float a = g_q[base + j], b2 = g_q[base + 32 + j];
    g_q[base + j]      = a * cs - b2 * sn;
    g_q[base + 32 + j] = b2 * cs + a * sn;
    a = g_k[base + j]; b2 = g_k[base + 32 + j];
    g_k[base + j]      = a * cs - b2 * sn;
    g_k[base + 32 + j] = b2 * cs + a * sn;
}

// ---------------- attention: one warp per (b,h,q), online softmax -----------
__global__ void attn_kernel() {
    int gw = (blockIdx.x * blockDim.x + threadIdx.x) >> 5;
    int lane = threadIdx.x & 31;
    if (gw >= BATCH * NH * SEQ) return;
    int qi = gw % SEQ;
    int h = (gw / SEQ) % NH;
    int b = gw / (SEQ * NH);
    int t = b * SEQ + qi;
    const float* qp = g_q + (size_t)t * DIM + h * HD;
    float q0 = qp[lane] * 0.125f, q1 = qp[lane + 32] * 0.125f;
    float m = -1e30f, l = 0.f, a0 = 0.f, a1 = 0.f;
    size_t krow = (size_t)b * SEQ * DIM + h * HD;
    for (int s = 0; s <= qi; s++) {
        const float* kp = g_k + krow + (size_t)s * DIM;
        float d = q0 * kp[lane] + q1 * kp[lane + 32];
#pragma unroll
        for (int o = 16; o; o >>= 1) d += __shfl_xor_sync(0xffffffffu, d, o);
        float mn = fmaxf(m, d);
        float p = 0.f, corr = 0.f;
        if (lane == 0) { p = __expf(d - mn); corr = __expf(m - mn); }
        p    = __shfl_sync(0xffffffffu, p, 0);
        corr = __shfl_sync(0xffffffffu, corr, 0);
        const float* vp = g_v + krow + (size_t)s * DIM;
        l  = l  * corr + p;
        a0 = a0 * corr + p * vp[lane];
        a1 = a1 * corr + p * vp[lane + 32];
        m = mn;
    }
    float inv = 1.0f / l;
    float* op = g_ao + (size_t)t * DIM + h * HD;
    op[lane] = a0 * inv;
    op[lane + 32] = a1 * inv;
}

// ---------------- MoE gate logits: h2 @ Wg, 8 threads/token -----------------
__global__ void gate_kernel(const float* __restrict__ Wg) {
    int tid = threadIdx.x;
    int tok = blockIdx.x * 32 + (tid >> 3);
    int e = tid & 7;
    const float* hr = g_h + (size_t)tok * DIM;
    float s = 0.f;
    for (int d = 0; d < DIM; d++) s += hr[d] * Wg[d * NE + e];
    g_logits[tok * NE + e] = s;
}

__global__ void zero_kernel() {
    if (threadIdx.x < NE) g_counts[threadIdx.x] = 0;
}

// softmax over 8, top-2 (first index on ties, like lax.top_k), normalized w
__global__ void topk_kernel() {
    int t = blockIdx.x * blockDim.x + threadIdx.x;
    if (t >= TB) return;
    float lg[NE];
    float m = -1e30f;
#pragma unroll
    for (int e = 0; e < NE; e++) { lg[e] = g_logits[t * NE + e]; m = fmaxf(m, lg[e]); }
    float ssum = 0.f;
#pragma unroll
    for (int e = 0; e < NE; e++) { lg[e] = expf(lg[e] - m); ssum += lg[e]; }
    int i0 = 0;
#pragma unroll
    for (int e = 1; e < NE; e++) if (lg[e] > lg[i0]) i0 = e;
    int i1 = (i0 == 0) ? 1 : 0;
#pragma unroll
    for (int e = 0; e < NE; e++) if (e != i0 && e != i1 && lg[e] > lg[i1]) i1 = e;
    float v0 = lg[i0] / ssum, v1 = lg[i1] / ssum;
    float winv = 1.0f / (v0 + v1);
    g_te[2 * t] = i0; g_te[2 * t + 1] = i1;
    g_tw[2 * t] = v0 * winv; g_tw[2 * t + 1] = v1 * winv;
    atomicAdd(&g_counts[i0], 1);
    atomicAdd(&g_counts[i1], 1);
}

__global__ void scan_kernel() {
    int acc = 0;
    for (int e = 0; e < NE; e++) {
        g_offsets[e] = acc;
        acc += g_counts[e];
        g_cursor[e] = 0;
    }
}

__global__ void assign_kernel() {
    int t = blockIdx.x * blockDim.x + threadIdx.x;
    if (t >= TB) return;
    for (int kk = 0; kk < 2; kk++) {
        int e = g_te[2 * t + kk];
        int pos = g_offsets[e] + atomicAdd(&g_cursor[e], 1);
        g_rowtok[pos] = t;
        g_roww[pos] = g_tw[2 * t + kk];
        g_perm[2 * t + kk] = pos;
    }
}

__global__ void gather_kernel() {
    int r = blockIdx.x;
    int t = g_rowtok[r];
    for (int d = threadIdx.x; d < DIM; d += blockDim.x)
        g_xe[(size_t)r * DIM + d] = g_h[(size_t)t * DIM + d];
}

// x[t] += w0*yff[r0] + w1*yff[r1]   (deterministic, no atomics)
__global__ void scatter_kernel() {
    int t = blockIdx.x;
    int r0 = g_perm[2 * t], r1 = g_perm[2 * t + 1];
    float w0 = g_roww[r0], w1 = g_roww[r1];
    for (int d = threadIdx.x; d < DIM; d += blockDim.x)
        g_x[(size_t)t * DIM + d] += w0 * g_yff[(size_t)r0 * DIM + d]
                                  + w1 * g_yff[(size_t)r1 * DIM + d];
}

// ---------------- host orchestration ----------------
extern "C" void kernel_launch(void* const* d_in, const int* in_sizes, int n_in,
                              void* d_out, int out_size) {
    (void)in_sizes; (void)n_in; (void)out_size;
    const int*   ids   = (const int*)  d_in[0];
    const float* emb   = (const float*)d_in[1];
    const float* ln1_g = (const float*)d_in[2];
    const float* ln1_b = (const float*)d_in[3];
    const float* ln2_g = (const float*)d_in[4];
    const float* ln2_b = (const float*)d_in[5];
    const float* Wq    = (const float*)d_in[6];
    const float* Wkv   = (const float*)d_in[7];
    const float* Wk    = (const float*)d_in[8];
    const float* Wv    = (const float*)d_in[9];
    const float* Wo    = (const float*)d_in[10];
    const float* Wg    = (const float*)d_in[11];
    const float* W1    = (const float*)d_in[12];
    const float* b1    = (const float*)d_in[13];
    const float* W2    = (const float*)d_in[14];
    const float* b2    = (const float*)d_in[15];
    const float* lnf_g = (const float*)d_in[16];
    const float* lnf_b = (const float*)d_in[17];
    const float* Wout  = (const float*)d_in[18];

    float *px, *ph, *pq, *pk, *pv, *plat, *pao, *pxe, *phff, *pyff;
    cudaGetSymbolAddress((void**)&px,   g_x);
    cudaGetSymbolAddress((void**)&ph,   g_h);
    cudaGetSymbolAddress((void**)&pq,   g_q);
    cudaGetSymbolAddress((void**)&pk,   g_k);
    cudaGetSymbolAddress((void**)&pv,   g_v);
    cudaGetSymbolAddress((void**)&plat, g_lat);
    cudaGetSymbolAddress((void**)&pao,  g_ao);
    cudaGetSymbolAddress((void**)&pxe,  g_xe);
    cudaGetSymbolAddress((void**)&phff, g_hff);
    cudaGetSymbolAddress((void**)&pyff, g_yff);

    embed_kernel<<<TB, 256>>>(ids, emb);

    for (int l = 0; l < NLAYER; l++) {
        // --- attention block ---
        ln_kernel<<<TB, 256>>>(px, ln1_g + l * DIM, ln1_b + l * DIM, ph);
        sgemm_kernel<<<dim3(DIM / 64, TB / 64), 256>>>(ph, Wq + (size_t)l * DIM * DIM, nullptr, pq,
                                                       TB, DIM, DIM, 0);
        sgemm_kernel<<<dim3(DLAT / 64, TB / 64), 256>>>(ph, Wkv + (size_t)l * DIM * DLAT, nullptr, plat,
                                                        TB, DLAT, DIM, 0);
        sgemm_kernel<<<dim3(DIM / 64, TB / 64), 256>>>(plat, Wk + (size_t)l * DLAT * DIM, nullptr, pk,
                                                       TB, DIM, DLAT, 0);
        sgemm_kernel<<<dim3(DIM / 64, TB / 64), 256>>>(plat, Wv + (size_t)l * DLAT * DIM, nullptr, pv,
                                                       TB, DIM, DLAT, 0);
        rope_kernel<<<(TB * NH * 32 + 255) / 256, 256>>>();
        attn_kernel<<<(BATCH * NH * SEQ * 32 + 255) / 256, 256>>>();
        sgemm_kernel<<<dim3(DIM / 64, TB / 64), 256>>>(pao, Wo + (size_t)l * DIM * DIM, nullptr, px,
                                                       TB, DIM, DIM, FLAG_ACC);

        // --- MoE block ---
        ln_kernel<<<TB, 256>>>(px, ln2_g + l * DIM, ln2_b + l * DIM, ph);
        gate_kernel<<<TB / 32, 256>>>(Wg + (size_t)l * DIM * NE);
        zero_kernel<<<1, 32>>>();
        topk_kernel<<<TB / 256, 256>>>();
        scan_kernel<<<1, 1>>>();
        assign_kernel<<<TB / 256, 256>>>();
        gather_kernel<<<2 * TB, 256>>>();
        sgemm_moe_kernel<<<dim3(DFF / 64, TB / 64, NE), 256>>>(
            pxe, W1 + (size_t)l * NE * DIM * DFF, b1 + (size_t)l * NE * DFF, phff,
            DFF, DIM, FLAG_GELU);
        sgemm_moe_kernel<<<dim3(DIM / 64, TB / 64, NE), 256>>>(
            phff, W2 + (size_t)l * NE * DFF * DIM, b2 + (size_t)l * NE * DIM, pyff,
            DIM, DFF, 0);
        scatter_kernel<<<TB, 256>>>();
    }

    // --- final LN + LM head ---
    ln_kernel<<<TB, 256>>>(px, lnf_g, lnf_b, ph);
    sgemm_kernel<<<dim3(NV / 64, TB / 64), 256>>>(ph, Wout, nullptr, (float*)d_out,
                                                  TB, NV, DIM, 0);
}

// round 2
// speedup vs baseline: 1.2238x; 1.2238x over previous
#include <cuda_runtime.h>
#include <math.h>

// ---------------- problem dims ----------------
#define TB 2048      // B*S tokens
#define SEQ 1024
#define BATCH 2
#define DIM 768
#define NH 12
#define HD 64
#define DLAT 192
#define DFF 3072
#define NE 8
#define NV 32000
#define NLAYER 2

#define FLAG_ACC 1
#define FLAG_GELU 2

// ---------------- scratch (device globals; no allocation) ----------------
__device__ float g_x[TB * DIM];
__device__ float g_h[TB * DIM];
__device__ float g_q[TB * DIM];
__device__ float g_k[TB * DIM];
__device__ float g_v[TB * DIM];
__device__ float g_lat[TB * DLAT];
__device__ float g_ao[TB * DIM];
__device__ float g_logits[TB * NE];
__device__ float g_tw[TB * 2];
__device__ int   g_te[TB * 2];
__device__ int   g_counts[NE];
__device__ int   g_offsets[NE];
__device__ int   g_cursor[NE];
__device__ int   g_rowtok[2 * TB];
__device__ float g_roww[2 * TB];
__device__ int   g_perm[2 * TB];
__device__ float g_xe[2 * TB * DIM];
__device__ float g_hff[2 * TB * DFF];
__device__ float g_yff[2 * TB * DIM];

// ---------------- embedding gather ----------------
__global__ void embed_kernel(const int* __restrict__ ids, const float* __restrict__ emb) {
    int t = blockIdx.x;
    const float* src = emb + (size_t)ids[t] * DIM;
    for (int d = threadIdx.x; d < DIM; d += blockDim.x)
        g_x[t * DIM + d] = src[d];
}

// ---------------- layernorm ----------------
__global__ void ln_kernel(const float* __restrict__ x, const float* __restrict__ g,
                          const float* __restrict__ b, float* __restrict__ out) {
    int row = blockIdx.x;
    int t = threadIdx.x;
    const float* xr = x + (size_t)row * DIM;
    float v0 = xr[t], v1 = xr[t + 256], v2 = xr[t + 512];
    __shared__ float red[256];
    red[t] = v0 + v1 + v2;
    __syncthreads();
    for (int o = 128; o > 0; o >>= 1) { if (t < o) red[t] += red[t + o]; __syncthreads(); }
    float mean = red[0] * (1.0f / DIM);
    __syncthreads();
    float d0 = v0 - mean, d1 = v1 - mean, d2 = v2 - mean;
    red[t] = d0 * d0 + d1 * d1 + d2 * d2;
    __syncthreads();
    for (int o = 128; o > 0; o >>= 1) { if (t < o) red[t] += red[t + o]; __syncthreads(); }
    float rstd = rsqrtf(red[0] * (1.0f / DIM) + 1e-6f);
    float* orow = out + (size_t)row * DIM;
    orow[t]       = d0 * rstd * g[t]       + b[t];
    orow[t + 256] = d1 * rstd * g[t + 256] + b[t + 256];
    orow[t + 512] = d2 * rstd * g[t + 512] + b[t + 512];
}

// ---------------- gelu (tanh form, matches JAX) ----------------
__device__ __forceinline__ float gelu_f(float x) {
    const float k0 = 0.7978845608028654f;
    float x3 = x * x * x;
    return 0.5f * x * (1.0f + tanhf(k0 * (x + 0.044715f * x3)));
}

// =====================================================================
//                 TF32x3 tensor-core GEMM (mma.sync)
// CTA tile 128x128, BK=16, 8 warps (2x4), warp tile 64x32, dbl-buffered
// =====================================================================
#define BM 128
#define BN 128
#define BK 16
#define AS_STRIDE 20     // conflict-free for fragment rows (20r mod 32 disjoint)
#define BS_STRIDE 136    // conflict-free for fragment k (8k+n disjoint)

__device__ __forceinline__ float f2tf32(float x) {
    float r; asm("cvt.rna.tf32.f32 %0, %1;" : "=f"(r) : "f"(x)); return r;
}

__device__ __forceinline__ void mma8(float d[4], const float a[4], const float b[2]) {
    asm volatile(
        "mma.sync.aligned.m16n8k8.row.col.f32.tf32.tf32.f32 "
        "{%0,%1,%2,%3},{%4,%5,%6,%7},{%8,%9},{%0,%1,%2,%3};"
        : "+f"(d[0]), "+f"(d[1]), "+f"(d[2]), "+f"(d[3])
        : "r"(__float_as_uint(a[0])), "r"(__float_as_uint(a[1])),
          "r"(__float_as_uint(a[2])), "r"(__float_as_uint(a[3])),
          "r"(__float_as_uint(b[0])), "r"(__float_as_uint(b[1])));
}

// A: [Mv x K] row-major (base), B: [K x N] row-major, C: [.. x N] at same base as A rows.
// Block computes C[m0:m0+128, n0:n0+128]. Rows >= Mv are skipped/zero.
__device__ __forceinline__ void mma_tile(
    const float* __restrict__ A, const float* __restrict__ B,
    const float* __restrict__ bias, float* __restrict__ C,
    int Mv, int N, int K, int m0, int n0, int flags)
{
    __shared__ float As[2][BM][AS_STRIDE];
    __shared__ float Bs[2][BK][BS_STRIDE];

    int tid = threadIdx.x;
    int lane = tid & 31;
    int warp = tid >> 5;
    int wm = (warp >> 2) * 64;   // warp m offset within tile
    int wn = (warp & 3) * 32;    // warp n offset within tile

    // gmem load mapping
    int ar = tid >> 1;            // 0..127
    int ac = (tid & 1) * 8;       // 0 or 8
    int br = tid >> 4;            // 0..15
    int bc = (tid & 15) * 8;      // 0..120

    float4 ra0, ra1, rb0, rb1;
    int agr = m0 + ar;
    bool avalid = agr < Mv;
    const int nk = K / BK;

    float acc[4][4][4];
#pragma unroll
    for (int i = 0; i < 4; i++)
#pragma unroll
        for (int j = 0; j < 4; j++)
#pragma unroll
            for (int q = 0; q < 4; q++) acc[i][j][q] = 0.f;

    // prologue: load tile 0
    {
        const float* pa = A + (size_t)agr * K + ac;
        if (avalid) { ra0 = *(const float4*)pa; ra1 = *(const float4*)(pa + 4); }
        else { ra0 = make_float4(0,0,0,0); ra1 = ra0; }
        const float* pb = B + (size_t)br * N + n0 + bc;
        rb0 = *(const float4*)pb; rb1 = *(const float4*)(pb + 4);
        *(float4*)&As[0][ar][ac]     = ra0;
        *(float4*)&As[0][ar][ac + 4] = ra1;
        *(float4*)&Bs[0][br][bc]     = rb0;
        *(float4*)&Bs[0][br][bc + 4] = rb1;
    }

    int row = lane >> 2;      // fragment row / B-col selector
    int col = lane & 3;       // fragment col / B-k selector

    for (int t = 0; t < nk; t++) {
        __syncthreads();
        int s = t & 1;
        if (t + 1 < nk) {
            int kt = (t + 1) * BK;
            const float* pa = A + (size_t)agr * K + kt + ac;
            if (avalid) { ra0 = *(const float4*)pa; ra1 = *(const float4*)(pa + 4); }
            else { ra0 = make_float4(0,0,0,0); ra1 = ra0; }
            const float* pb = B + (size_t)(kt + br) * N + n0 + bc;
            rb0 = *(const float4*)pb; rb1 = *(const float4*)(pb + 4);
        }
#pragma unroll
        for (int ks = 0; ks < 2; ks++) {
            int k0 = ks * 8;
            float ahi[4][4], alo[4][4];
#pragma unroll
            for (int mt = 0; mt < 4; mt++) {
                int m = wm + mt * 16 + row;
                float x0 = As[s][m][k0 + col];
                float x1 = As[s][m + 8][k0 + col];
                float x2 = As[s][m][k0 + col + 4];
                float x3 = As[s][m + 8][k0 + col + 4];
                ahi[mt][0] = f2tf32(x0); alo[mt][0] = f2tf32(x0 - ahi[mt][0]);
                ahi[mt][1] = f2tf32(x1); alo[mt][1] = f2tf32(x1 - ahi[mt][1]);
                ahi[mt][2] = f2tf32(x2); alo[mt][2] = f2tf32(x2 - ahi[mt][2]);
                ahi[mt][3] = f2tf32(x3); alo[mt][3] = f2tf32(x3 - ahi[mt][3]);
            }
            float bhi[4][2], blo[4][2];
#pragma unroll
            for (int nt = 0; nt < 4; nt++) {
                int n = wn + nt * 8 + row;
                float y0 = Bs[s][k0 + col][n];
                float y1 = Bs[s][k0 + col + 4][n];
                bhi[nt][0] = f2tf32(y0); blo[nt][0] = f2tf32(y0 - bhi[nt][0]);
                bhi[nt][1] = f2tf32(y1); blo[nt][1] = f2tf32(y1 - bhi[nt][1]);
            }
#pragma unroll
            for (int mt = 0; mt < 4; mt++)
#pragma unroll
                for (int nt = 0; nt < 4; nt++) mma8(acc[mt][nt], ahi[mt], bhi[nt]);
#pragma unroll
            for (int mt = 0; mt < 4; mt++)
#pragma unroll
                for (int nt = 0; nt < 4; nt++) mma8(acc[mt][nt], ahi[mt], blo[nt]);
#pragma unroll
            for (int mt = 0; mt < 4; mt++)
#pragma unroll
                for (int nt = 0; nt < 4; nt++) mma8(acc[mt][nt], alo[mt], bhi[nt]);
        }
        if (t + 1 < nk) {
            __syncthreads();
            int s2 = (t + 1) & 1;
            *(float4*)&As[s2][ar][ac]     = ra0;
            *(float4*)&As[s2][ar][ac + 4] = ra1;
            *(float4*)&Bs[s2][br][bc]     = rb0;
            *(float4*)&Bs[s2][br][bc + 4] = rb1;
        }
    }

    // epilogue
#pragma unroll
    for (int mt = 0; mt < 4; mt++) {
#pragma unroll
        for (int h = 0; h < 2; h++) {
            int r = m0 + wm + mt * 16 + row + h * 8;
            if (r >= Mv) continue;
#pragma unroll
            for (int nt = 0; nt < 4; nt++) {
#pragma unroll
                for (int j = 0; j < 2; j++) {
                    int c = n0 + wn + nt * 8 + col * 2 + j;
                    float val = acc[mt][nt][h * 2 + j];
                    if (bias) val += bias[c];
                    if (flags & FLAG_GELU) val = gelu_f(val);
                    float* cp = C + (size_t)r * N + c;
                    if (flags & FLAG_ACC) *cp += val; else *cp = val;
                }
            }
        }
    }
}

__global__ void __launch_bounds__(256, 1) mma_gemm_kernel(
    const float* __restrict__ A, const float* __restrict__ B,
    const float* __restrict__ bias, float* __restrict__ C,
    int M, int N, int K, int flags)
{
    mma_tile(A, B, bias, C, M, N, K, blockIdx.y * BM, blockIdx.x * BN, flags);
}

__global__ void __launch_bounds__(256, 1) mma_moe_kernel(
    const float* __restrict__ Ab, const float* __restrict__ Bb,
    const float* __restrict__ biasb, float* __restrict__ Cb,
    int N, int K, int flags)
{
    int e = blockIdx.z;
    int cnt = g_counts[e];
    int m0 = blockIdx.y * BM;
    if (m0 >= cnt) return;
    int off = g_offsets[e];
    mma_tile(Ab + (size_t)off * K, Bb + (size_t)e * K * N,
             biasb + (size_t)e * N, Cb + (size_t)off * N,
             cnt, N, K, m0, blockIdx.x * BN, flags);
}

// ---------------- fp32 SGEMM (only for Wkv: N=192) ----------------
__global__ void sgemm_kernel(const float* __restrict__ A, const float* __restrict__ Bm,
                             const float* __restrict__ bias, float* __restrict__ C,
                             int M, int N, int K, int flags) {
    __shared__ float As[16][64];
    __shared__ float Bs[16][68];
    int tid = threadIdx.x;
    int m0 = blockIdx.y * 64, n0 = blockIdx.x * 64;
    int tx = tid & 15, ty = tid >> 4;
    int arow = tid >> 2, acol = (tid & 3) * 4;
    int brow = tid >> 4, bcol = (tid & 15) * 4;
    float c[4][4] = {};
    for (int kt = 0; kt < K; kt += 16) {
        float4 a = *(const float4*)(A + (size_t)(m0 + arow) * K + kt + acol);
        As[acol + 0][arow] = a.x; As[acol + 1][arow] = a.y;
        As[acol + 2][arow] = a.z; As[acol + 3][arow] = a.w;
        *(float4*)&Bs[brow][bcol] =
            *(const float4*)(Bm + (size_t)(kt + brow) * N + n0 + bcol);
        __syncthreads();
#pragma unroll
        for (int k = 0; k < 16; k++) {
            float4 ra4 = *(const float4*)&As[k][ty * 4];
            float4 rb4 = *(const float4*)&Bs[k][tx * 4];
            float ra[4] = {ra4.x, ra4.y, ra4.z, ra4.w};
            float rb[4] = {rb4.x, rb4.y, rb4.z, rb4.w};
#pragma unroll
            for (int i = 0; i < 4; i++)
#pragma unroll
                for (int j = 0; j < 4; j++) c[i][j] += ra[i] * rb[j];
        }
        __syncthreads();
    }
#pragma unroll
    for (int i = 0; i < 4; i++) {
        int m = m0 + ty * 4 + i;
#pragma unroll
        for (int j = 0; j < 4; j++) {
            int n = n0 + tx * 4 + j;
            float val = c[i][j];
            if (bias) val += bias[n];
            if (flags & FLAG_GELU) val = gelu_f(val);
            float* cp = C + (size_t)m * N + n;
            if (flags & FLAG_ACC) *cp += val; else *cp = val;
        }
    }
}

// ---------------- RoPE on q and k (in place) ----------------
__global__ void rope_kernel() {
    int idx = blockIdx.x * blockDim.x + threadIdx.x;
    if (idx >= TB * NH * 32) return;
    int j = idx & 31;
    int h = (idx >> 5) % NH;
    int t = idx / (32 * NH);
    int s = t % SEQ;
    float inv = powf(10000.0f, -(float)j * (1.0f / 32.0f));
    float ang = (float)s * inv;
    float sn, cs;
    sincosf(ang, &sn, &cs);
    int base = t * DIM + h * HD;
    float a = g_q[base + j], b2 = g_q[base + 32 + j];
    g_q[base + j]      = a * cs - b2 * sn;
    g_q[base + 32 + j] = b2 * cs + a * sn;
    a = g_k[base + j]; b2 = g_k[base + 32 + j];
    g_k[base + j]      = a * cs - b2 * sn;
    g_k[base + 32 + j] = b2 * cs + a * sn;
}

// ---------------- attention: one warp per (b,h,q), online softmax -----------
__global__ void attn_kernel() {
    int gw = (blockIdx.x * blockDim.x + threadIdx.x) >> 5;
    int lane = threadIdx.x & 31;
    if (gw >= BATCH * NH * SEQ) return;
    int qi = gw % SEQ;
    int h = (gw / SEQ) % NH;
    int b = gw / (SEQ * NH);
    int t = b * SEQ + qi;
    const float* qp = g_q + (size_t)t * DIM + h * HD;
    float q0 = qp[lane] * 0.125f, q1 = qp[lane + 32] * 0.125f;
    float m = -1e30f, l = 0.f, a0 = 0.f, a1 = 0.f;
    size_t krow = (size_t)b * SEQ * DIM + h * HD;
    for (int s = 0; s <= qi; s++) {
        const float* kp = g_k + krow + (size_t)s * DIM;
        float d = q0 * kp[lane] + q1 * kp[lane + 32];
#pragma unroll
        for (int o = 16; o; o >>= 1) d += __shfl_xor_sync(0xffffffffu, d, o);
        float mn = fmaxf(m, d);
        float p = 0.f, corr = 0.f;
        if (lane == 0) { p = __expf(d - mn); corr = __expf(m - mn); }
        p    = __shfl_sync(0xffffffffu, p, 0);
        corr = __shfl_sync(0xffffffffu, corr, 0);
        const float* vp = g_v + krow + (size_t)s * DIM;
        l  = l  * corr + p;
        a0 = a0 * corr + p * vp[lane];
        a1 = a1 * corr + p * vp[lane + 32];
        m = mn;
    }
    float inv = 1.0f / l;
    float* op = g_ao + (size_t)t * DIM + h * HD;
    op[lane] = a0 * inv;
    op[lane + 32] = a1 * inv;
}

// ---------------- MoE gate logits: warp per (token,expert) ------------------
__global__ void gate_kernel(const float* __restrict__ Wg) {
    int tok = blockIdx.x;
    int e = threadIdx.x >> 5;
    int lane = threadIdx.x & 31;
    const float* hr = g_h + (size_t)tok * DIM;
    float s = 0.f;
    for (int d = lane; d < DIM; d += 32) s += hr[d] * Wg[d * NE + e];
#pragma unroll
    for (int o = 16; o; o >>= 1) s += __shfl_xor_sync(0xffffffffu, s, o);
    if (lane == 0) g_logits[tok * NE + e] = s;
}

__global__ void zero_kernel() {
    if (threadIdx.x < NE) g_counts[threadIdx.x] = 0;
}

// softmax over 8, top-2 (first index on ties), normalized weights
__global__ void topk_kernel() {
    int t = blockIdx.x * blockDim.x + threadIdx.x;
    if (t >= TB) return;
    float lg[NE];
    float m = -1e30f;
#pragma unroll
    for (int e = 0; e < NE; e++) { lg[e] = g_logits[t * NE + e]; m = fmaxf(m, lg[e]); }
    float ssum = 0.f;
#pragma unroll
    for (int e = 0; e < NE; e++) { lg[e] = expf(lg[e] - m); ssum += lg[e]; }
    int i0 = 0;
#pragma unroll
    for (int e = 1; e < NE; e++) if (lg[e] > lg[i0]) i0 = e;
    int i1 = (i0 == 0) ? 1 : 0;
#pragma unroll
    for (int e = 0; e < NE; e++) if (e != i0 && e != i1 && lg[e] > lg[i1]) i1 = e;
    float v0 = lg[i0] / ssum, v1 = lg[i1] / ssum;
    float winv = 1.0f / (v0 + v1);
    g_te[2 * t] = i0; g_te[2 * t + 1] = i1;
    g_tw[2 * t] = v0 * winv; g_tw[2 * t + 1] = v1 * winv;
    atomicAdd(&g_counts[i0], 1);
    atomicAdd(&g_counts[i1], 1);
}

__global__ void scan_kernel() {
    int acc = 0;
    for (int e = 0; e < NE; e++) {
        g_offsets[e] = acc;
        acc += g_counts[e];
        g_cursor[e] = 0;
    }
}

__global__ void assign_kernel() {
    int t = blockIdx.x * blockDim.x + threadIdx.x;
    if (t >= TB) return;
    for (int kk = 0; kk < 2; kk++) {
        int e = g_te[2 * t + kk];
        int pos = g_offsets[e] + atomicAdd(&g_cursor[e], 1);
        g_rowtok[pos] = t;
        g_roww[pos] = g_tw[2 * t + kk];
        g_perm[2 * t + kk] = pos;
    }
}

__global__ void gather_kernel() {
    int r = blockIdx.x;
    int t = g_rowtok[r];
    for (int d = threadIdx.x; d < DIM; d += blockDim.x)
        g_xe[(size_t)r * DIM + d] = g_h[(size_t)t * DIM + d];
}

// x[t] += w0*yff[r0] + w1*yff[r1]
__global__ void scatter_kernel() {
    int t = blockIdx.x;
    int r0 = g_perm[2 * t], r1 = g_perm[2 * t + 1];
    float w0 = g_roww[r0], w1 = g_roww[r1];
    for (int d = threadIdx.x; d < DIM; d += blockDim.x)
        g_x[(size_t)t * DIM + d] += w0 * g_yff[(size_t)r0 * DIM + d]
                                  + w1 * g_yff[(size_t)r1 * DIM + d];
}

// ---------------- host orchestration ----------------
extern "C" void kernel_launch(void* const* d_in, const int* in_sizes, int n_in,
                              void* d_out, int out_size) {
    (void)in_sizes; (void)n_in; (void)out_size;
    const int*   ids   = (const int*)  d_in[0];
    const float* emb   = (const float*)d_in[1];
    const float* ln1_g = (const float*)d_in[2];
    const float* ln1_b = (const float*)d_in[3];
    const float* ln2_g = (const float*)d_in[4];
    const float* ln2_b = (const float*)d_in[5];
    const float* Wq    = (const float*)d_in[6];
    const float* Wkv   = (const float*)d_in[7];
    const float* Wk    = (const float*)d_in[8];
    const float* Wv    = (const float*)d_in[9];
    const float* Wo    = (const float*)d_in[10];
    const float* Wg    = (const float*)d_in[11];
    const float* W1    = (const float*)d_in[12];
    const float* b1    = (const float*)d_in[13];
    const float* W2    = (const float*)d_in[14];
    const float* b2    = (const float*)d_in[15];
    const float* lnf_g = (const float*)d_in[16];
    const float* lnf_b = (const float*)d_in[17];
    const float* Wout  = (const float*)d_in[18];

    float *px, *ph, *pq, *pk, *pv, *plat, *pao, *pxe, *phff, *pyff;
    cudaGetSymbolAddress((void**)&px,   g_x);
    cudaGetSymbolAddress((void**)&ph,   g_h);
    cudaGetSymbolAddress((void**)&pq,   g_q);
    cudaGetSymbolAddress((void**)&pk,   g_k);
    cudaGetSymbolAddress((void**)&pv,   g_v);
    cudaGetSymbolAddress((void**)&plat, g_lat);
    cudaGetSymbolAddress((void**)&pao,  g_ao);
    cudaGetSymbolAddress((void**)&pxe,  g_xe);
    cudaGetSymbolAddress((void**)&phff, g_hff);
    cudaGetSymbolAddress((void**)&pyff, g_yff);

    embed_kernel<<<TB, 256>>>(ids, emb);

    for (int l = 0; l < NLAYER; l++) {
        // --- attention block ---
        ln_kernel<<<TB, 256>>>(px, ln1_g + l * DIM, ln1_b + l * DIM, ph);
        mma_gemm_kernel<<<dim3(DIM / BN, TB / BM), 256>>>(
            ph, Wq + (size_t)l * DIM * DIM, nullptr, pq, TB, DIM, DIM, 0);
        sgemm_kernel<<<dim3(DLAT / 64, TB / 64), 256>>>(
            ph, Wkv + (size_t)l * DIM * DLAT, nullptr, plat, TB, DLAT, DIM, 0);
        mma_gemm_kernel<<<dim3(DIM / BN, TB / BM), 256>>>(
            plat, Wk + (size_t)l * DLAT * DIM, nullptr, pk, TB, DIM, DLAT, 0);
        mma_gemm_kernel<<<dim3(DIM / BN, TB / BM), 256>>>(
            plat, Wv + (size_t)l * DLAT * DIM, nullptr, pv, TB, DIM, DLAT, 0);
        rope_kernel<<<(TB * NH * 32 + 255) / 256, 256>>>();
        attn_kernel<<<(BATCH * NH * SEQ * 32 + 255) / 256, 256>>>();
        mma_gemm_kernel<<<dim3(DIM / BN, TB / BM), 256>>>(
            pao, Wo + (size_t)l * DIM * DIM, nullptr, px, TB, DIM, DIM, FLAG_ACC);

        // --- MoE block ---
        ln_kernel<<<TB, 256>>>(px, ln2_g + l * DIM, ln2_b + l * DIM, ph);
        gate_kernel<<<TB, 256>>>(Wg + (size_t)l * DIM * NE);
        zero_kernel<<<1, 32>>>();
        topk_kernel<<<TB / 256, 256>>>();
        scan_kernel<<<1, 1>>>();
        assign_kernel<<<TB / 256, 256>>>();
        gather_kernel<<<2 * TB, 256>>>();
        mma_moe_kernel<<<dim3(DFF / BN, 2 * TB / BM, NE), 256>>>(
            pxe, W1 + (size_t)l * NE * DIM * DFF, b1 + (size_t)l * NE * DFF, phff,
            DFF, DIM, FLAG_GELU);
        mma_moe_kernel<<<dim3(DIM / BN, 2 * TB / BM, NE), 256>>>(
            phff, W2 + (size_t)l * NE * DFF * DIM, b2 + (size_t)l * NE * DIM, pyff,
            DIM, DFF, 0);
        scatter_kernel<<<TB, 256>>>();
    }

    // --- final LN + LM head ---
    ln_kernel<<<TB, 256>>>(px, lnf_g, lnf_b, ph);
    mma_gemm_kernel<<<dim3(NV / BN, TB / BM), 256>>>(
        ph, Wout, nullptr, (float*)d_out, TB, NV, DIM, 0);
}

// round 4
// speedup vs baseline: 1.5671x; 1.2805x over previous
#include <cuda_runtime.h>
#include <cuda_bf16.h>
#include <math.h>
#include <stdint.h>

// ---------------- problem dims ----------------
#define TB 2048      // B*S tokens
#define SEQ 1024
#define BATCH 2
#define DIM 768
#define NH 12
#define HD 64
#define DLAT 192
#define DFF 3072
#define NE 8
#define NV 32000
#define NLAYER 2

#define FLAG_ACC 1
#define FLAG_GELU 2

// ---------------- scratch (device globals; no allocation) ----------------
__device__ float g_x[TB * DIM];
__device__ float g_h[TB * DIM];
__device__ float g_q[TB * DIM];
__device__ float g_k[TB * DIM];
__device__ float g_v[TB * DIM];
__device__ float g_lat[TB * DLAT];
__device__ float g_ao[TB * DIM];
__device__ float g_logits[TB * NE];
__device__ float g_tw[TB * 2];
__device__ int   g_te[TB * 2];
__device__ int   g_counts[NE];
__device__ int   g_offsets[NE];
__device__ int   g_cursor[NE];
__device__ int   g_rowtok[2 * TB];
__device__ float g_roww[2 * TB];
__device__ int   g_perm[2 * TB];
__device__ float g_xe[2 * TB * DIM];
__device__ float g_hff[2 * TB * DFF];
__device__ float g_yff[2 * TB * DIM];

// ---------------- helpers ----------------
__device__ __forceinline__ uint32_t pack_bf2(float a, float b) {
    __nv_bfloat162 h = __floats2bfloat162_rn(a, b);
    return *(uint32_t*)&h;
}
// split x = hi + lo with hi = bf16(x)
__device__ __forceinline__ void split_bf(float x, float& hi, float& lo) {
    __nv_bfloat16 h = __float2bfloat16_rn(x);
    hi = __bfloat162float(h);
    lo = x - hi;
}

// gelu (tanh form, matches JAX approximate)
__device__ __forceinline__ float gelu_f(float x) {
    const float k0 = 0.7978845608028654f;
    float x3 = x * x * x;
    return 0.5f * x * (1.0f + tanhf(k0 * (x + 0.044715f * x3)));
}

__device__ __forceinline__ void mma16(float d[4], const uint32_t a[4], const uint32_t b[2]) {
    asm volatile(
        "mma.sync.aligned.m16n8k16.row.col.f32.bf16.bf16.f32 "
        "{%0,%1,%2,%3},{%4,%5,%6,%7},{%8,%9},{%0,%1,%2,%3};"
        : "+f"(d[0]), "+f"(d[1]), "+f"(d[2]), "+f"(d[3])
        : "r"(a[0]), "r"(a[1]), "r"(a[2]), "r"(a[3]),
          "r"(b[0]), "r"(b[1]));
}

// =====================================================================
//        bf16x3 mma.sync GEMM (m16n8k16), 128x128 tile, BK=32
// smem: k-packed bf16x2 rows, stride 20 u32 (conflict-free fragments),
// hi/lo split at smem-store time, double-buffered, reg-prefetched gmem.
// Per-stage layout (u32 units): Ah +0, Al +2560, Bh +5120, Bl +7680.
// Stage stride 10240 u32 (40KB); total dynamic smem 80KB.
// =====================================================================
#define STG 10240
#define RST 20
#define GEMM_SMEM_BYTES (2 * STG * 4)

__device__ __forceinline__ void bf16x3_tile(
    const float* __restrict__ A, const float* __restrict__ B,
    const float* __restrict__ bias, float* __restrict__ C,
    int Mv, int N, int K, int m0, int n0, int flags)
{
    extern __shared__ uint32_t smu[];
    int tid = threadIdx.x, lane = tid & 31, warp = tid >> 5;
    int wm = (warp >> 2) * 64, wn = (warp & 3) * 32;
    int row = lane >> 2, cc = lane & 3;

    float acc[4][4][4];
#pragma unroll
    for (int i = 0; i < 4; i++)
#pragma unroll
        for (int j = 0; j < 4; j++)
#pragma unroll
            for (int q = 0; q < 4; q++) acc[i][j][q] = 0.f;

    const int nk = K / 32;

    // prefetch registers
    float2 pa[8];
    float pb0[8], pb1[8];

    // ---- gmem load for chunk c into regs ----
    auto load_gmem = [&](int c) {
        int kc = c * 32;
#pragma unroll
        for (int it = 0; it < 8; it++) {
            int idx = tid + it * 256;
            int m = idx >> 4, kp = idx & 15;
            int gm = m0 + m;
            pa[it] = (gm < Mv) ? *(const float2*)(A + (size_t)gm * K + kc + kp * 2)
                               : make_float2(0.f, 0.f);
        }
#pragma unroll
        for (int it = 0; it < 8; it++) {
            int idx = tid + it * 256;
            int n = idx & 127, kp = idx >> 7;
            const float* bp = B + (size_t)(kc + 2 * kp) * N + n0 + n;
            pb0[it] = bp[0];
            pb1[it] = bp[N];
        }
    };

    // ---- split + store regs into smem stage ----
    auto store_smem = [&](int c) {
        uint32_t* st = smu + (c & 1) * STG;
#pragma unroll
        for (int it = 0; it < 8; it++) {
            int idx = tid + it * 256;
            int m = idx >> 4, kp = idx & 15;
            float h0, l0, h1, l1;
            split_bf(pa[it].x, h0, l0);
            split_bf(pa[it].y, h1, l1);
            st[m * RST + kp]        = pack_bf2(h0, h1);
            st[2560 + m * RST + kp] = pack_bf2(l0, l1);
        }
#pragma unroll
        for (int it = 0; it < 8; it++) {
            int idx = tid + it * 256;
            int n = idx & 127, kp = idx >> 7;
            float h0, l0, h1, l1;
            split_bf(pb0[it], h0, l0);
            split_bf(pb1[it], h1, l1);
            st[5120 + n * RST + kp] = pack_bf2(h0, h1);
            st[7680 + n * RST + kp] = pack_bf2(l0, l1);
        }
    };

    load_gmem(0);
    store_smem(0);

    for (int c = 0; c < nk; c++) {
        __syncthreads();
        int s = c & 1;
        if (c + 1 < nk) load_gmem(c + 1);

        const uint32_t* sp = smu + s * STG;
#pragma unroll
        for (int ss = 0; ss < 2; ss++) {
            int kb = ss * 8;
            uint32_t ah[4][4], al[4][4];
#pragma unroll
            for (int mt = 0; mt < 4; mt++) {
                int mb = (wm + mt * 16 + row) * RST + kb + cc;
                ah[mt][0] = sp[mb];
                ah[mt][1] = sp[mb + 8 * RST];
                ah[mt][2] = sp[mb + 4];
                ah[mt][3] = sp[mb + 8 * RST + 4];
                al[mt][0] = sp[2560 + mb];
                al[mt][1] = sp[2560 + mb + 8 * RST];
                al[mt][2] = sp[2560 + mb + 4];
                al[mt][3] = sp[2560 + mb + 8 * RST + 4];
            }
            uint32_t bh[4][2], bl[4][2];
#pragma unroll
            for (int nt = 0; nt < 4; nt++) {
                int nb = (wn + nt * 8 + row) * RST + kb + cc;
                bh[nt][0] = sp[5120 + nb];
                bh[nt][1] = sp[5120 + nb + 4];
                bl[nt][0] = sp[7680 + nb];
                bl[nt][1] = sp[7680 + nb + 4];
            }
#pragma unroll
            for (int mt = 0; mt < 4; mt++)
#pragma unroll
                for (int nt = 0; nt < 4; nt++) mma16(acc[mt][nt], ah[mt], bh[nt]);
#pragma unroll
            for (int mt = 0; mt < 4; mt++)
#pragma unroll
                for (int nt = 0; nt < 4; nt++) mma16(acc[mt][nt], ah[mt], bl[nt]);
#pragma unroll
            for (int mt = 0; mt < 4; mt++)
#pragma unroll
                for (int nt = 0; nt < 4; nt++) mma16(acc[mt][nt], al[mt], bh[nt]);
        }

        if (c + 1 < nk) {
            __syncthreads();
            store_smem(c + 1);
        }
    }

    // ---- epilogue ----
#pragma unroll
    for (int mt = 0; mt < 4; mt++) {
#pragma unroll
        for (int h = 0; h < 2; h++) {
            int r = m0 + wm + mt * 16 + row + h * 8;
            if (r >= Mv) continue;
#pragma unroll
            for (int nt = 0; nt < 4; nt++) {
#pragma unroll
                for (int j = 0; j < 2; j++) {
                    int cn = n0 + wn + nt * 8 + cc * 2 + j;
                    float val = acc[mt][nt][h * 2 + j];
                    if (bias) val += bias[cn];
                    if (flags & FLAG_GELU) val = gelu_f(val);
                    float* cp = C + (size_t)r * N + cn;
                    if (flags & FLAG_ACC) *cp += val; else *cp = val;
                }
            }
        }
    }
}

__global__ void __launch_bounds__(256, 1) bf16_gemm_kernel(
    const float* __restrict__ A, const float* __restrict__ B,
    const float* __restrict__ bias, float* __restrict__ C,
    int M, int N, int K, int flags)
{
    bf16x3_tile(A, B, bias, C, M, N, K, blockIdx.y * 128, blockIdx.x * 128, flags);
}

__global__ void __launch_bounds__(256, 1) bf16_moe_kernel(
    const float* __restrict__ Ab, const float* __restrict__ Bb,
    const float* __restrict__ biasb, float* __restrict__ Cb,
    int N, int K, int flags)
{
    int e = blockIdx.z;
    int cnt = g_counts[e];
    int m0 = blockIdx.y * 128;
    if (m0 >= cnt) return;
    int off = g_offsets[e];
    bf16x3_tile(Ab + (size_t)off * K, Bb + (size_t)e * K * N,
                biasb + (size_t)e * N, Cb + (size_t)off * N,
                cnt, N, K, m0, blockIdx.x * 128, flags);
}

// ---------------- embedding gather ----------------
__global__ void embed_kernel(const int* __restrict__ ids, const float* __restrict__ emb) {
    int t = blockIdx.x;
    const float* src = emb + (size_t)ids[t] * DIM;
    for (int d = threadIdx.x; d < DIM; d += blockDim.x)
        g_x[t * DIM + d] = src[d];
}

// ---------------- layernorm ----------------
__global__ void ln_kernel(const float* __restrict__ x, const float* __restrict__ g,
                          const float* __restrict__ b, float* __restrict__ out) {
    int row = blockIdx.x;
    int t = threadIdx.x;
    const float* xr = x + (size_t)row * DIM;
    float v0 = xr[t], v1 = xr[t + 256], v2 = xr[t + 512];
    __shared__ float red[256];
    red[t] = v0 + v1 + v2;
    __syncthreads();
    for (int o = 128; o > 0; o >>= 1) { if (t < o) red[t] += red[t + o]; __syncthreads(); }
    float mean = red[0] * (1.0f / DIM);
    __syncthreads();
    float d0 = v0 - mean, d1 = v1 - mean, d2 = v2 - mean;
    red[t] = d0 * d0 + d1 * d1 + d2 * d2;
    __syncthreads();
    for (int o = 128; o > 0; o >>= 1) { if (t < o) red[t] += red[t + o]; __syncthreads(); }
    float rstd = rsqrtf(red[0] * (1.0f / DIM) + 1e-6f);
    float* orow = out + (size_t)row * DIM;
    orow[t]       = d0 * rstd * g[t]       + b[t];
    orow[t + 256] = d1 * rstd * g[t + 256] + b[t + 256];
    orow[t + 512] = d2 * rstd * g[t + 512] + b[t + 512];
}

// ---------------- fp32 SGEMM (only for Wkv: N=192) ----------------
__global__ void sgemm_kernel(const float* __restrict__ A, const float* __restrict__ Bm,
                             const float* __restrict__ bias, float* __restrict__ C,
                             int M, int N, int K, int flags) {
    __shared__ float As[16][64];
    __shared__ float Bs[16][68];
    int tid = threadIdx.x;
    int m0 = blockIdx.y * 64, n0 = blockIdx.x * 64;
    int tx = tid & 15, ty = tid >> 4;
    int arow = tid >> 2, acol = (tid & 3) * 4;
    int brow = tid >> 4, bcol = (tid & 15) * 4;
    float c[4][4] = {};
    for (int kt = 0; kt < K; kt += 16) {
        float4 a = *(const float4*)(A + (size_t)(m0 + arow) * K + kt + acol);
        As[acol + 0][arow] = a.x; As[acol + 1][arow] = a.y;
        As[acol + 2][arow] = a.z; As[acol + 3][arow] = a.w;
        *(float4*)&Bs[brow][bcol] =
            *(const float4*)(Bm + (size_t)(kt + brow) * N + n0 + bcol);
        __syncthreads();
#pragma unroll
        for (int k = 0; k < 16; k++) {
            float4 ra4 = *(const float4*)&As[k][ty * 4];
            float4 rb4 = *(const float4*)&Bs[k][tx * 4];
            float ra[4] = {ra4.x, ra4.y, ra4.z, ra4.w};
            float rb[4] = {rb4.x, rb4.y, rb4.z, rb4.w};
#pragma unroll
            for (int i = 0; i < 4; i++)
#pragma unroll
                for (int j = 0; j < 4; j++) c[i][j] += ra[i] * rb[j];
        }
        __syncthreads();
    }
#pragma unroll
    for (int i = 0; i < 4; i++) {
        int m = m0 + ty * 4 + i;
#pragma unroll
        for (int j = 0; j < 4; j++) {
            int n = n0 + tx * 4 + j;
            float val = c[i][j];
            if (bias) val += bias[n];
            if (flags & FLAG_GELU) val = gelu_f(val);
            float* cp = C + (size_t)m * N + n;
            if (flags & FLAG_ACC) *cp += val; else *cp = val;
        }
    }
}

// ---------------- RoPE on q and k (in place) ----------------
__global__ void rope_kernel() {
    int idx = blockIdx.x * blockDim.x + threadIdx.x;
    if (idx >= TB * NH * 32) return;
    int j = idx & 31;
    int h = (idx >> 5) % NH;
    int t = idx / (32 * NH);
    int s = t % SEQ;
    float inv = powf(10000.0f, -(float)j * (1.0f / 32.0f));
    float ang = (float)s * inv;
    float sn, cs;
    sincosf(ang, &sn, &cs);
    int base = t * DIM + h * HD;
    float a = g_q[base + j], b2 = g_q[base + 32 + j];
    g_q[base + j]      = a * cs - b2 * sn;
    g_q[base + 32 + j] = b2 * cs + a * sn;
    a = g_k[base + j]; b2 = g_k[base + 32 + j];
    g_k[base + j]      = a * cs - b2 * sn;
    g_k[base + 32 + j] = b2 * cs + a * sn;
}

// ---------------- attention: one warp per (b,h,q), online softmax -----------
__global__ void attn_kernel() {
    int gw = (blockIdx.x * blockDim.x + threadIdx.x) >> 5;
    int lane = threadIdx.x & 31;
    if (gw >= BATCH * NH * SEQ) return;
    int qi = gw % SEQ;
    int h = (gw / SEQ) % NH;
    int b = gw / (SEQ * NH);
    int t = b * SEQ + qi;
    const float* qp = g_q + (size_t)t * DIM + h * HD;
    float q0 = qp[lane] * 0.125f, q1 = qp[lane + 32] * 0.125f;
    float m = -1e30f, l = 0.f, a0 = 0.f, a1 = 0.f;
    size_t krow = (size_t)b * SEQ * DIM + h * HD;
    for (int s = 0; s <= qi; s++) {
        const float* kp = g_k + krow + (size_t)s * DIM;
        float d = q0 * kp[lane] + q1 * kp[lane + 32];
#pragma unroll
        for (int o = 16; o; o >>= 1) d += __shfl_xor_sync(0xffffffffu, d, o);
        float mn = fmaxf(m, d);
        float p = 0.f, corr = 0.f;
        if (lane == 0) { p = __expf(d - mn); corr = __expf(m - mn); }
        p    = __shfl_sync(0xffffffffu, p, 0);
        corr = __shfl_sync(0xffffffffu, corr, 0);
        const float* vp = g_v + krow + (size_t)s * DIM;
        l  = l  * corr + p;
        a0 = a0 * corr + p * vp[lane];
        a1 = a1 * corr + p * vp[lane + 32];
        m = mn;
    }
    float inv = 1.0f / l;
    float* op = g_ao + (size_t)t * DIM + h * HD;
    op[lane] = a0 * inv;
    op[lane + 32] = a1 * inv;
}

// ---------------- MoE gate logits: warp per (token,expert) ------------------
__global__ void gate_kernel(const float* __restrict__ Wg) {
    int tok = blockIdx.x;
    int e = threadIdx.x >> 5;
    int lane = threadIdx.x & 31;
    const float* hr = g_h + (size_t)tok * DIM;
    float s = 0.f;
    for (int d = lane; d < DIM; d += 32) s += hr[d] * Wg[d * NE + e];
#pragma unroll
    for (int o = 16; o; o >>= 1) s += __shfl_xor_sync(0xffffffffu, s, o);
    if (lane == 0) g_logits[tok * NE + e] = s;
}

__global__ void zero_kernel() {
    if (threadIdx.x < NE) g_counts[threadIdx.x] = 0;
}

// softmax over 8, top-2 (first index on ties), normalized weights
__global__ void topk_kernel() {
    int t = blockIdx.x * blockDim.x + threadIdx.x;
    if (t >= TB) return;
    float lg[NE];
    float m = -1e30f;
#pragma unroll
    for (int e = 0; e < NE; e++) { lg[e] = g_logits[t * NE + e]; m = fmaxf(m, lg[e]); }
    float ssum = 0.f;
#pragma unroll
    for (int e = 0; e < NE; e++) { lg[e] = expf(lg[e] - m); ssum += lg[e]; }
    int i0 = 0;
#pragma unroll
    for (int e = 1; e < NE; e++) if (lg[e] > lg[i0]) i0 = e;
    int i1 = (i0 == 0) ? 1 : 0;
#pragma unroll
    for (int e = 0; e < NE; e++) if (e != i0 && e != i1 && lg[e] > lg[i1]) i1 = e;
    float v0 = lg[i0] / ssum, v1 = lg[i1] / ssum;
    float winv = 1.0f / (v0 + v1);
    g_te[2 * t] = i0; g_te[2 * t + 1] = i1;
    g_tw[2 * t] = v0 * winv; g_tw[2 * t + 1] = v1 * winv;
    atomicAdd(&g_counts[i0], 1);
    atomicAdd(&g_counts[i1], 1);
}

__global__ void scan_kernel() {
    int acc = 0;
    for (int e = 0; e < NE; e++) {
        g_offsets[e] = acc;
        acc += g_counts[e];
        g_cursor[e] = 0;
    }
}

__global__ void assign_kernel() {
    int t = blockIdx.x * blockDim.x + threadIdx.x;
    if (t >= TB) return;
    for (int kk = 0; kk < 2; kk++) {
        int e = g_te[2 * t + kk];
        int pos = g_offsets[e] + atomicAdd(&g_cursor[e], 1);
        g_rowtok[pos] = t;
        g_roww[pos] = g_tw[2 * t + kk];
        g_perm[2 * t + kk] = pos;
    }
}

__global__ void gather_kernel() {
    int r = blockIdx.x;
    int t = g_rowtok[r];
    for (int d = threadIdx.x; d < DIM; d += blockDim.x)
        g_xe[(size_t)r * DIM + d] = g_h[(size_t)t * DIM + d];
}

// x[t] += w0*yff[r0] + w1*yff[r1]
__global__ void scatter_kernel() {
    int t = blockIdx.x;
    int r0 = g_perm[2 * t], r1 = g_perm[2 * t + 1];
    float w0 = g_roww[r0], w1 = g_roww[r1];
    for (int d = threadIdx.x; d < DIM; d += blockDim.x)
        g_x[(size_t)t * DIM + d] += w0 * g_yff[(size_t)r0 * DIM + d]
                                  + w1 * g_yff[(size_t)r1 * DIM + d];
}

// ---------------- host orchestration ----------------
extern "C" void kernel_launch(void* const* d_in, const int* in_sizes, int n_in,
                              void* d_out, int out_size) {
    (void)in_sizes; (void)n_in; (void)out_size;
    const int*   ids   = (const int*)  d_in[0];
    const float* emb   = (const float*)d_in[1];
    const float* ln1_g = (const float*)d_in[2];
    const float* ln1_b = (const float*)d_in[3];
    const float* ln2_g = (const float*)d_in[4];
    const float* ln2_b = (const float*)d_in[5];
    const float* Wq    = (const float*)d_in[6];
    const float* Wkv   = (const float*)d_in[7];
    const float* Wk    = (const float*)d_in[8];
    const float* Wv    = (const float*)d_in[9];
    const float* Wo    = (const float*)d_in[10];
    const float* Wg    = (const float*)d_in[11];
    const float* W1    = (const float*)d_in[12];
    const float* b1    = (const float*)d_in[13];
    const float* W2    = (const float*)d_in[14];
    const float* b2    = (const float*)d_in[15];
    const float* lnf_g = (const float*)d_in[16];
    const float* lnf_b = (const float*)d_in[17];
    const float* Wout  = (const float*)d_in[18];

    cudaFuncSetAttribute(bf16_gemm_kernel,
                         cudaFuncAttributeMaxDynamicSharedMemorySize, GEMM_SMEM_BYTES);
    cudaFuncSetAttribute(bf16_moe_kernel,
                         cudaFuncAttributeMaxDynamicSharedMemorySize, GEMM_SMEM_BYTES);

    float *px, *ph, *pq, *pk, *pv, *plat, *pao, *pxe, *phff, *pyff;
    cudaGetSymbolAddress((void**)&px,   g_x);
    cudaGetSymbolAddress((void**)&ph,   g_h);
    cudaGetSymbolAddress((void**)&pq,   g_q);
    cudaGetSymbolAddress((void**)&pk,   g_k);
    cudaGetSymbolAddress((void**)&pv,   g_v);
    cudaGetSymbolAddress((void**)&plat, g_lat);
    cudaGetSymbolAddress((void**)&pao,  g_ao);
    cudaGetSymbolAddress((void**)&pxe,  g_xe);
    cudaGetSymbolAddress((void**)&phff, g_hff);
    cudaGetSymbolAddress((void**)&pyff, g_yff);

    embed_kernel<<<TB, 256>>>(ids, emb);

    for (int l = 0; l < NLAYER; l++) {
        // --- attention block ---
        ln_kernel<<<TB, 256>>>(px, ln1_g + l * DIM, ln1_b + l * DIM, ph);
        bf16_gemm_kernel<<<dim3(DIM / 128, TB / 128), 256, GEMM_SMEM_BYTES>>>(
            ph, Wq + (size_t)l * DIM * DIM, nullptr, pq, TB, DIM, DIM, 0);
        sgemm_kernel<<<dim3(DLAT / 64, TB / 64), 256>>>(
            ph, Wkv + (size_t)l * DIM * DLAT, nullptr, plat, TB, DLAT, DIM, 0);
        bf16_gemm_kernel<<<dim3(DIM / 128, TB / 128), 256, GEMM_SMEM_BYTES>>>(
            plat, Wk + (size_t)l * DLAT * DIM, nullptr, pk, TB, DIM, DLAT, 0);
        bf16_gemm_kernel<<<dim3(DIM / 128, TB / 128), 256, GEMM_SMEM_BYTES>>>(
            plat, Wv + (size_t)l * DLAT * DIM, nullptr, pv, TB, DIM, DLAT, 0);
        rope_kernel<<<(TB * NH * 32 + 255) / 256, 256>>>();
        attn_kernel<<<(BATCH * NH * SEQ * 32 + 255) / 256, 256>>>();
        bf16_gemm_kernel<<<dim3(DIM / 128, TB / 128), 256, GEMM_SMEM_BYTES>>>(
            pao, Wo + (size_t)l * DIM * DIM, nullptr, px, TB, DIM, DIM, FLAG_ACC);

        // --- MoE block ---
        ln_kernel<<<TB, 256>>>(px, ln2_g + l * DIM, ln2_b + l * DIM, ph);
        gate_kernel<<<TB, 256>>>(Wg + (size_t)l * DIM * NE);
        zero_kernel<<<1, 32>>>();
        topk_kernel<<<TB / 256, 256>>>();
        scan_kernel<<<1, 1>>>();
        assign_kernel<<<TB / 256, 256>>>();
        gather_kernel<<<2 * TB, 256>>>();
        bf16_moe_kernel<<<dim3(DFF / 128, 2 * TB / 128, NE), 256, GEMM_SMEM_BYTES>>>(
            pxe, W1 + (size_t)l * NE * DIM * DFF, b1 + (size_t)l * NE * DFF, phff,
            DFF, DIM, FLAG_GELU);
        bf16_moe_kernel<<<dim3(DIM / 128, 2 * TB / 128, NE), 256, GEMM_SMEM_BYTES>>>(
            phff, W2 + (size_t)l * NE * DFF * DIM, b2 + (size_t)l * NE * DIM, pyff,
            DIM, DFF, 0);
        scatter_kernel<<<TB, 256>>>();
    }

    // --- final LN + LM head ---
    ln_kernel<<<TB, 256>>>(px, lnf_g, lnf_b, ph);
    bf16_gemm_kernel<<<dim3(NV / 128, TB / 128), 256, GEMM_SMEM_BYTES>>>(
        ph, Wout, nullptr, (float*)d_out, TB, NV, DIM, 0);
}

// round 5
// speedup vs baseline: 1.8600x; 1.1869x over previous
#include <cuda_runtime.h>
#include <cuda_bf16.h>
#include <math.h>
#include <stdint.h>

// ---------------- problem dims ----------------
#define TB 2048      // B*S tokens
#define SEQ 1024
#define BATCH 2
#define DIM 768
#define NH 12
#define HD 64
#define DLAT 192
#define DFF 3072
#define NE 8
#define NV 32000
#define NLAYER 2

#define FLAG_ACC 1
#define FLAG_GELU 2

// ---------------- scratch (device globals; no allocation) ----------------
__device__ float g_x[TB * DIM];
__device__ float g_h[TB * DIM];
__device__ float g_q[TB * DIM];
__device__ float g_k[TB * DIM];
__device__ float g_v[TB * DIM];
__device__ float g_lat[TB * DLAT];
__device__ float g_ao[TB * DIM];
__device__ float g_logits[TB * NE];
__device__ float g_tw[TB * 2];
__device__ int   g_te[TB * 2];
__device__ int   g_counts[NE];
__device__ int   g_offsets[NE];
__device__ int   g_cursor[NE];
__device__ int   g_rowtok[2 * TB];
__device__ float g_roww[2 * TB];
__device__ int   g_perm[2 * TB];
__device__ float g_hff[2 * TB * DFF];
__device__ float g_yff[2 * TB * DIM];

// ---------------- helpers ----------------
__device__ __forceinline__ uint32_t pack_bf2(float a, float b) {
    __nv_bfloat162 h = __floats2bfloat162_rn(a, b);
    return *(uint32_t*)&h;
}
__device__ __forceinline__ void split_bf(float x, float& hi, float& lo) {
    __nv_bfloat16 h = __float2bfloat16_rn(x);
    hi = __bfloat162float(h);
    lo = x - hi;
}
__device__ __forceinline__ float gelu_f(float x) {
    const float k0 = 0.7978845608028654f;
    float x3 = x * x * x;
    return 0.5f * x * (1.0f + tanhf(k0 * (x + 0.044715f * x3)));
}
__device__ __forceinline__ void mma16(float d[4], const uint32_t a[4], const uint32_t b[2]) {
    asm volatile(
        "mma.sync.aligned.m16n8k16.row.col.f32.bf16.bf16.f32 "
        "{%0,%1,%2,%3},{%4,%5,%6,%7},{%8,%9},{%0,%1,%2,%3};"
        : "+f"(d[0]), "+f"(d[1]), "+f"(d[2]), "+f"(d[3])
        : "r"(a[0]), "r"(a[1]), "r"(a[2]), "r"(a[3]),
          "r"(b[0]), "r"(b[1]));
}

// =====================================================================
//        bf16x3 mma.sync GEMM (m16n8k16), 128x128 tile, BK=32
// single-sync double-buffered pipeline, optional A-row indirection,
// column guards (N need not be a multiple of 128).
// Per-stage (u32): Ah +0, Al +2560, Bh +5120, Bl +7680; stage 10240 u32.
// =====================================================================
#define STG 10240
#define RST 20
#define GEMM_SMEM_BYTES (2 * STG * 4)

__device__ __forceinline__ void bf16x3_tile(
    const float* __restrict__ A, const int* __restrict__ Aidx,
    const float* __restrict__ B,
    const float* __restrict__ bias, float* __restrict__ C,
    int Mv, int N, int K, int m0, int n0, int flags)
{
    extern __shared__ uint32_t smu[];
    int tid = threadIdx.x, lane = tid & 31, warp = tid >> 5;
    int wm = (warp >> 2) * 64, wn = (warp & 3) * 32;
    int row = lane >> 2, cc = lane & 3;

    float acc[4][4][4];
#pragma unroll
    for (int i = 0; i < 4; i++)
#pragma unroll
        for (int j = 0; j < 4; j++)
#pragma unroll
            for (int q = 0; q < 4; q++) acc[i][j][q] = 0.f;

    const int nk = K / 32;

    // precompute A row pointers (with optional indirection) + validity
    const float* arp[8];
    bool aval[8], bval[8];
#pragma unroll
    for (int it = 0; it < 8; it++) {
        int idx = tid + it * 256;
        int mm = idx >> 4;
        int gm = m0 + mm;
        aval[it] = gm < Mv;
        int r = aval[it] ? (Aidx ? Aidx[gm] : gm) : 0;
        arp[it] = A + (size_t)r * K + (idx & 15) * 2;
        bval[it] = (n0 + (idx & 127)) < N;
    }

    float2 pa[8];
    float pb0[8], pb1[8];

    auto load_gmem = [&](int c) {
        int kc = c * 32;
#pragma unroll
        for (int it = 0; it < 8; it++)
            pa[it] = aval[it] ? *(const float2*)(arp[it] + kc) : make_float2(0.f, 0.f);
#pragma unroll
        for (int it = 0; it < 8; it++) {
            int idx = tid + it * 256;
            int n = idx & 127, kp = idx >> 7;
            if (bval[it]) {
                const float* bp = B + (size_t)(kc + 2 * kp) * N + n0 + n;
                pb0[it] = bp[0];
                pb1[it] = bp[N];
            } else { pb0[it] = 0.f; pb1[it] = 0.f; }
        }
    };

    auto store_smem = [&](int c) {
        uint32_t* st = smu + (c & 1) * STG;
#pragma unroll
        for (int it = 0; it < 8; it++) {
            int idx = tid + it * 256;
            int m = idx >> 4, kp = idx & 15;
            float h0, l0, h1, l1;
            split_bf(pa[it].x, h0, l0);
            split_bf(pa[it].y, h1, l1);
            st[m * RST + kp]        = pack_bf2(h0, h1);
            st[2560 + m * RST + kp] = pack_bf2(l0, l1);
        }
#pragma unroll
        for (int it = 0; it < 8; it++) {
            int idx = tid + it * 256;
            int n = idx & 127, kp = idx >> 7;
            float h0, l0, h1, l1;
            split_bf(pb0[it], h0, l0);
            split_bf(pb1[it], h1, l1);
            st[5120 + n * RST + kp] = pack_bf2(h0, h1);
            st[7680 + n * RST + kp] = pack_bf2(l0, l1);
        }
    };

    load_gmem(0);
    store_smem(0);

    for (int c = 0; c < nk; c++) {
        __syncthreads();
        if (c + 1 < nk) load_gmem(c + 1);

        const uint32_t* sp = smu + (c & 1) * STG;
#pragma unroll
        for (int ss = 0; ss < 2; ss++) {
            int kb = ss * 8;
            uint32_t ah[4][4], al[4][4];
#pragma unroll
            for (int mt = 0; mt < 4; mt++) {
                int mb = (wm + mt * 16 + row) * RST + kb + cc;
                ah[mt][0] = sp[mb];
                ah[mt][1] = sp[mb + 8 * RST];
                ah[mt][2] = sp[mb + 4];
                ah[mt][3] = sp[mb + 8 * RST + 4];
                al[mt][0] = sp[2560 + mb];
                al[mt][1] = sp[2560 + mb + 8 * RST];
                al[mt][2] = sp[2560 + mb + 4];
                al[mt][3] = sp[2560 + mb + 8 * RST + 4];
            }
            uint32_t bh[4][2], bl[4][2];
#pragma unroll
            for (int nt = 0; nt < 4; nt++) {
                int nb = (wn + nt * 8 + row) * RST + kb + cc;
                bh[nt][0] = sp[5120 + nb];
                bh[nt][1] = sp[5120 + nb + 4];
                bl[nt][0] = sp[7680 + nb];
                bl[nt][1] = sp[7680 + nb + 4];
            }
#pragma unroll
            for (int mt = 0; mt < 4; mt++)
#pragma unroll
                for (int nt = 0; nt < 4; nt++) mma16(acc[mt][nt], ah[mt], bh[nt]);
#pragma unroll
            for (int mt = 0; mt < 4; mt++)
#pragma unroll
                for (int nt = 0; nt < 4; nt++) mma16(acc[mt][nt], ah[mt], bl[nt]);
#pragma unroll
            for (int mt = 0; mt < 4; mt++)
#pragma unroll
                for (int nt = 0; nt < 4; nt++) mma16(acc[mt][nt], al[mt], bh[nt]);
        }

        if (c + 1 < nk) store_smem(c + 1);
    }

    // ---- epilogue ----
#pragma unroll
    for (int mt = 0; mt < 4; mt++) {
#pragma unroll
        for (int h = 0; h < 2; h++) {
            int r = m0 + wm + mt * 16 + row + h * 8;
            if (r >= Mv) continue;
#pragma unroll
            for (int nt = 0; nt < 4; nt++) {
#pragma unroll
                for (int j = 0; j < 2; j++) {
                    int cn = n0 + wn + nt * 8 + cc * 2 + j;
                    if (cn >= N) continue;
                    float val = acc[mt][nt][h * 2 + j];
                    if (bias) val += bias[cn];
                    if (flags & FLAG_GELU) val = gelu_f(val);
                    float* cp = C + (size_t)r * N + cn;
                    if (flags & FLAG_ACC) *cp += val; else *cp = val;
                }
            }
        }
    }
}

__global__ void __launch_bounds__(256, 1) bf16_gemm_kernel(
    const float* __restrict__ A, const float* __restrict__ B,
    const float* __restrict__ bias, float* __restrict__ C,
    int M, int N, int K, int flags)
{
    bf16x3_tile(A, nullptr, B, bias, C, M, N, K,
                blockIdx.y * 128, blockIdx.x * 128, flags);
}

// MoE GEMM1: A rows gathered from g_h via g_rowtok (fused gather)
__global__ void __launch_bounds__(256, 1) bf16_moe1_kernel(
    const float* __restrict__ Ah, const float* __restrict__ Bb,
    const float* __restrict__ biasb, float* __restrict__ Cb,
    int N, int K, int flags)
{
    int e = blockIdx.z;
    int cnt = g_counts[e];
    int m0 = blockIdx.y * 128;
    if (m0 >= cnt) return;
    int off = g_offsets[e];
    bf16x3_tile(Ah, g_rowtok + off, Bb + (size_t)e * K * N,
                biasb + (size_t)e * N, Cb + (size_t)off * N,
                cnt, N, K, m0, blockIdx.x * 128, flags);
}

// MoE GEMM2: contiguous A
__global__ void __launch_bounds__(256, 1) bf16_moe2_kernel(
    const float* __restrict__ Ab, const float* __restrict__ Bb,
    const float* __restrict__ biasb, float* __restrict__ Cb,
    int N, int K, int flags)
{
    int e = blockIdx.z;
    int cnt = g_counts[e];
    int m0 = blockIdx.y * 128;
    if (m0 >= cnt) return;
    int off = g_offsets[e];
    bf16x3_tile(Ab + (size_t)off * K, nullptr, Bb + (size_t)e * K * N,
                biasb + (size_t)e * N, Cb + (size_t)off * N,
                cnt, N, K, m0, blockIdx.x * 128, flags);
}

// ---------------- embedding gather ----------------
__global__ void embed_kernel(const int* __restrict__ ids, const float* __restrict__ emb) {
    int t = blockIdx.x;
    const float* src = emb + (size_t)ids[t] * DIM;
    for (int d = threadIdx.x; d < DIM; d += blockDim.x)
        g_x[t * DIM + d] = src[d];
}

// ---------------- layernorm ----------------
__global__ void ln_kernel(const float* __restrict__ x, const float* __restrict__ g,
                          const float* __restrict__ b, float* __restrict__ out) {
    int row = blockIdx.x;
    int t = threadIdx.x;
    const float* xr = x + (size_t)row * DIM;
    float v0 = xr[t], v1 = xr[t + 256], v2 = xr[t + 512];
    __shared__ float red[256];
    red[t] = v0 + v1 + v2;
    __syncthreads();
    for (int o = 128; o > 0; o >>= 1) { if (t < o) red[t] += red[t + o]; __syncthreads(); }
    float mean = red[0] * (1.0f / DIM);
    __syncthreads();
    float d0 = v0 - mean, d1 = v1 - mean, d2 = v2 - mean;
    red[t] = d0 * d0 + d1 * d1 + d2 * d2;
    __syncthreads();
    for (int o = 128; o > 0; o >>= 1) { if (t < o) red[t] += red[t + o]; __syncthreads(); }
    float rstd = rsqrtf(red[0] * (1.0f / DIM) + 1e-6f);
    float* orow = out + (size_t)row * DIM;
    orow[t]       = d0 * rstd * g[t]       + b[t];
    orow[t + 256] = d1 * rstd * g[t + 256] + b[t + 256];
    orow[t + 512] = d2 * rstd * g[t + 512] + b[t + 512];
}

// ---------------- RoPE on q and k (in place) ----------------
__global__ void rope_kernel() {
    int idx = blockIdx.x * blockDim.x + threadIdx.x;
    if (idx >= TB * NH * 32) return;
    int j = idx & 31;
    int h = (idx >> 5) % NH;
    int t = idx / (32 * NH);
    int s = t % SEQ;
    float inv = powf(10000.0f, -(float)j * (1.0f / 32.0f));
    float ang = (float)s * inv;
    float sn, cs;
    sincosf(ang, &sn, &cs);
    int base = t * DIM + h * HD;
    float a = g_q[base + j], b2 = g_q[base + 32 + j];
    g_q[base + j]      = a * cs - b2 * sn;
    g_q[base + 32 + j] = b2 * cs + a * sn;
    a = g_k[base + j]; b2 = g_k[base + 32 + j];
    g_k[base + j]      = a * cs - b2 * sn;
    g_k[base + 32 + j] = b2 * cs + a * sn;
}

// ---- attention: one warp per (b,h,q), 4 k-positions per iteration ----
// lane = (g,j): group g (of 8 lanes) computes the dot for s0+g over its
// 8 dims; 3-shfl group reduce, 4-shfl gather, one rescale per 4 positions.
__global__ void attn_kernel() {
    int gw = (blockIdx.x * blockDim.x + threadIdx.x) >> 5;
    int lane = threadIdx.x & 31;
    if (gw >= BATCH * NH * SEQ) return;
    int qi = gw % SEQ;
    int h = (gw / SEQ) % NH;
    int b = gw / (SEQ * NH);
    int t = b * SEQ + qi;
    int g = lane >> 3, j = lane & 7;

    const float* qp = g_q + (size_t)t * DIM + h * HD + j * 8;
    float ql[8];
#pragma unroll
    for (int i = 0; i < 8; i++) ql[i] = qp[i] * 0.125f;

    size_t base = (size_t)b * SEQ * DIM + h * HD;
    const float* kb = g_k + base;
    const float* vb = g_v + base;

    float m = -1e30f, l = 0.f, a0 = 0.f, a1 = 0.f;

    for (int s0 = 0; s0 <= qi; s0 += 4) {
        int s = s0 + g;
        int sc = s > qi ? qi : s;
        const float* kp = kb + (size_t)sc * DIM + j * 8;
        float4 k0 = *(const float4*)kp;
        float4 k1 = *(const float4*)(kp + 4);
        float d = ql[0] * k0.x + ql[1] * k0.y + ql[2] * k0.z + ql[3] * k0.w
                + ql[4] * k1.x + ql[5] * k1.y + ql[6] * k1.z + ql[7] * k1.w;
        d += __shfl_xor_sync(0xffffffffu, d, 1);
        d += __shfl_xor_sync(0xffffffffu, d, 2);
        d += __shfl_xor_sync(0xffffffffu, d, 4);
        if (s > qi) d = -1e30f;
        float d0 = __shfl_sync(0xffffffffu, d, j);
        float d1 = __shfl_sync(0xffffffffu, d, 8 + j);
        float d2 = __shfl_sync(0xffffffffu, d, 16 + j);
        float d3 = __shfl_sync(0xffffffffu, d, 24 + j);
        float mn = fmaxf(fmaxf(fmaxf(fmaxf(m, d0), d1), d2), d3);
        float corr = __expf(m - mn);
        float p0 = __expf(d0 - mn);
        float p1 = __expf(d1 - mn);
        float p2 = __expf(d2 - mn);
        float p3 = __expf(d3 - mn);
        int s1 = s0 + 1 > qi ? qi : s0 + 1;
        int s2 = s0 + 2 > qi ? qi : s0 + 2;
        int s3 = s0 + 3 > qi ? qi : s0 + 3;
        const float* v0p = vb + (size_t)s0 * DIM;
        const float* v1p = vb + (size_t)s1 * DIM;
        const float* v2p = vb + (size_t)s2 * DIM;
        const float* v3p = vb + (size_t)s3 * DIM;
        l  = l  * corr + (p0 + p1 + p2 + p3);
        a0 = a0 * corr + p0 * v0p[lane] + p1 * v1p[lane]
                       + p2 * v2p[lane] + p3 * v3p[lane];
        a1 = a1 * corr + p0 * v0p[lane + 32] + p1 * v1p[lane + 32]
                       + p2 * v2p[lane + 32] + p3 * v3p[lane + 32];
        m = mn;
    }
    float inv = 1.0f / l;
    float* op = g_ao + (size_t)t * DIM + h * HD;
    op[lane] = a0 * inv;
    op[lane + 32] = a1 * inv;
}

// ---------------- MoE gate logits: warp per (token,expert) ------------------
__global__ void gate_kernel(const float* __restrict__ Wg) {
    int tok = blockIdx.x;
    int e = threadIdx.x >> 5;
    int lane = threadIdx.x & 31;
    const float* hr = g_h + (size_t)tok * DIM;
    float s = 0.f;
    for (int d = lane; d < DIM; d += 32) s += hr[d] * Wg[d * NE + e];
#pragma unroll
    for (int o = 16; o; o >>= 1) s += __shfl_xor_sync(0xffffffffu, s, o);
    if (lane == 0) g_logits[tok * NE + e] = s;
}

__global__ void zero_kernel() {
    if (threadIdx.x < NE) g_counts[threadIdx.x] = 0;
}

__global__ void topk_kernel() {
    int t = blockIdx.x * blockDim.x + threadIdx.x;
    if (t >= TB) return;
    float lg[NE];
    float m = -1e30f;
#pragma unroll
    for (int e = 0; e < NE; e++) { lg[e] = g_logits[t * NE + e]; m = fmaxf(m, lg[e]); }
    float ssum = 0.f;
#pragma unroll
    for (int e = 0; e < NE; e++) { lg[e] = expf(lg[e] - m); ssum += lg[e]; }
    int i0 = 0;
#pragma unroll
    for (int e = 1; e < NE; e++) if (lg[e] > lg[i0]) i0 = e;
    int i1 = (i0 == 0) ? 1 : 0;
#pragma unroll
    for (int e = 0; e < NE; e++) if (e != i0 && e != i1 && lg[e] > lg[i1]) i1 = e;
    float v0 = lg[i0] / ssum, v1 = lg[i1] / ssum;
    float winv = 1.0f / (v0 + v1);
    g_te[2 * t] = i0; g_te[2 * t + 1] = i1;
    g_tw[2 * t] = v0 * winv; g_tw[2 * t + 1] = v1 * winv;
    atomicAdd(&g_counts[i0], 1);
    atomicAdd(&g_counts[i1], 1);
}

__global__ void scan_kernel() {
    int acc = 0;
    for (int e = 0; e < NE; e++) {
        g_offsets[e] = acc;
        acc += g_counts[e];
        g_cursor[e] = 0;
    }
}

__global__ void assign_kernel() {
    int t = blockIdx.x * blockDim.x + threadIdx.x;
    if (t >= TB) return;
    for (int kk = 0; kk < 2; kk++) {
        int e = g_te[2 * t + kk];
        int pos = g_offsets[e] + atomicAdd(&g_cursor[e], 1);
        g_rowtok[pos] = t;
        g_roww[pos] = g_tw[2 * t + kk];
        g_perm[2 * t + kk] = pos;
    }
}

// x[t] += w0*yff[r0] + w1*yff[r1]
__global__ void scatter_kernel() {
    int t = blockIdx.x;
    int r0 = g_perm[2 * t], r1 = g_perm[2 * t + 1];
    float w0 = g_roww[r0], w1 = g_roww[r1];
    for (int d = threadIdx.x; d < DIM; d += blockDim.x)
        g_x[(size_t)t * DIM + d] += w0 * g_yff[(size_t)r0 * DIM + d]
                                  + w1 * g_yff[(size_t)r1 * DIM + d];
}

// ---------------- host orchestration ----------------
extern "C" void kernel_launch(void* const* d_in, const int* in_sizes, int n_in,
                              void* d_out, int out_size) {
    (void)in_sizes; (void)n_in; (void)out_size;
    const int*   ids   = (const int*)  d_in[0];
    const float* emb   = (const float*)d_in[1];
    const float* ln1_g = (const float*)d_in[2];
    const float* ln1_b = (const float*)d_in[3];
    const float* ln2_g = (const float*)d_in[4];
    const float* ln2_b = (const float*)d_in[5];
    const float* Wq    = (const float*)d_in[6];
    const float* Wkv   = (const float*)d_in[7];
    const float* Wk    = (const float*)d_in[8];
    const float* Wv    = (const float*)d_in[9];
    const float* Wo    = (const float*)d_in[10];
    const float* Wg    = (const float*)d_in[11];
    const float* W1    = (const float*)d_in[12];
    const float* b1    = (const float*)d_in[13];
    const float* W2    = (const float*)d_in[14];
    const float* b2    = (const float*)d_in[15];
    const float* lnf_g = (const float*)d_in[16];
    const float* lnf_b = (const float*)d_in[17];
    const float* Wout  = (const float*)d_in[18];

    cudaFuncSetAttribute(bf16_gemm_kernel,
                         cudaFuncAttributeMaxDynamicSharedMemorySize, GEMM_SMEM_BYTES);
    cudaFuncSetAttribute(bf16_moe1_kernel,
                         cudaFuncAttributeMaxDynamicSharedMemorySize, GEMM_SMEM_BYTES);
    cudaFuncSetAttribute(bf16_moe2_kernel,
                         cudaFuncAttributeMaxDynamicSharedMemorySize, GEMM_SMEM_BYTES);

    float *px, *ph, *pq, *pk, *pv, *plat, *pao, *phff, *pyff;
    cudaGetSymbolAddress((void**)&px,   g_x);
    cudaGetSymbolAddress((void**)&ph,   g_h);
    cudaGetSymbolAddress((void**)&pq,   g_q);
    cudaGetSymbolAddress((void**)&pk,   g_k);
    cudaGetSymbolAddress((void**)&pv,   g_v);
    cudaGetSymbolAddress((void**)&plat, g_lat);
    cudaGetSymbolAddress((void**)&pao,  g_ao);
    cudaGetSymbolAddress((void**)&phff, g_hff);
    cudaGetSymbolAddress((void**)&pyff, g_yff);

    embed_kernel<<<TB, 256>>>(ids, emb);

    for (int l = 0; l < NLAYER; l++) {
        // --- attention block ---
        ln_kernel<<<TB, 256>>>(px, ln1_g + l * DIM, ln1_b + l * DIM, ph);
        bf16_gemm_kernel<<<dim3(DIM / 128, TB / 128), 256, GEMM_SMEM_BYTES>>>(
            ph, Wq + (size_t)l * DIM * DIM, nullptr, pq, TB, DIM, DIM, 0);
        bf16_gemm_kernel<<<dim3((DLAT + 127) / 128, TB / 128), 256, GEMM_SMEM_BYTES>>>(
            ph, Wkv + (size_t)l * DIM * DLAT, nullptr, plat, TB, DLAT, DIM, 0);
        bf16_gemm_kernel<<<dim3(DIM / 128, TB / 128), 256, GEMM_SMEM_BYTES>>>(
            plat, Wk + (size_t)l * DLAT * DIM, nullptr, pk, TB, DIM, DLAT, 0);
        bf16_gemm_kernel<<<dim3(DIM / 128, TB / 128), 256, GEMM_SMEM_BYTES>>>(
            plat, Wv + (size_t)l * DLAT * DIM, nullptr, pv, TB, DIM, DLAT, 0);
        rope_kernel<<<(TB * NH * 32 + 255) / 256, 256>>>();
        attn_kernel<<<(BATCH * NH * SEQ * 32 + 255) / 256, 256>>>();
        bf16_gemm_kernel<<<dim3(DIM / 128, TB / 128), 256, GEMM_SMEM_BYTES>>>(
            pao, Wo + (size_t)l * DIM * DIM, nullptr, px, TB, DIM, DIM, FLAG_ACC);

        // --- MoE block ---
        ln_kernel<<<TB, 256>>>(px, ln2_g + l * DIM, ln2_b + l * DIM, ph);
        gate_kernel<<<TB, 256>>>(Wg + (size_t)l * DIM * NE);
        zero_kernel<<<1, 32>>>();
        topk_kernel<<<TB / 256, 256>>>();
        scan_kernel<<<1, 1>>>();
        assign_kernel<<<TB / 256, 256>>>();
        bf16_moe1_kernel<<<dim3(DFF / 128, 2 * TB / 128, NE), 256, GEMM_SMEM_BYTES>>>(
            ph, W1 + (size_t)l * NE * DIM * DFF, b1 + (size_t)l * NE * DFF, phff,
            DFF, DIM, FLAG_GELU);
        bf16_moe2_kernel<<<dim3(DIM / 128, 2 * TB / 128, NE), 256, GEMM_SMEM_BYTES>>>(
            phff, W2 + (size_t)l * NE * DFF * DIM, b2 + (size_t)l * NE * DIM, pyff,
            DIM, DFF, 0);
        scatter_kernel<<<TB, 256>>>();
    }

    // --- final LN + LM head ---
    ln_kernel<<<TB, 256>>>(px, lnf_g, lnf_b, ph);
    bf16_gemm_kernel<<<dim3(NV / 128, TB / 128), 256, GEMM_SMEM_BYTES>>>(
        ph, Wout, nullptr, (float*)d_out, TB, NV, DIM, 0);
}

// round 6
// speedup vs baseline: 1.9535x; 1.0502x over previous
#include <cuda_runtime.h>
#include <cuda_bf16.h>
#include <math.h>
#include <stdint.h>

// ---------------- problem dims ----------------
#define TB 2048      // B*S tokens
#define SEQ 1024
#define BATCH 2
#define DIM 768
#define NH 12
#define HD 64
#define DLAT 192
#define DFF 3072
#define NE 8
#define NV 32000
#define NLAYER 2

#define FLAG_ACC 1
#define FLAG_GELU 2

// ---------------- scratch (device globals; no allocation) ----------------
__device__ float g_x[TB * DIM];
__device__ float g_h[TB * DIM];
__device__ float g_q[TB * DIM];
__device__ float g_k[TB * DIM];
__device__ float g_v[TB * DIM];
__device__ float g_lat[TB * DLAT];
__device__ float g_ao[TB * DIM];
__device__ float g_logits[TB * NE];
__device__ float g_tw[TB * 2];
__device__ int   g_te[TB * 2];
__device__ int   g_counts[NE];
__device__ int   g_offsets[NE];
__device__ int   g_cursor[NE];
__device__ int   g_rowtok[2 * TB];
__device__ float g_roww[2 * TB];
__device__ int   g_perm[2 * TB];
__device__ float g_hff[2 * TB * DFF];
__device__ float g_yff[2 * TB * DIM];

// ---------------- helpers ----------------
__device__ __forceinline__ uint32_t smem_u32(const void* p) {
    uint32_t a;
    asm("{ .reg .u64 t; cvta.to.shared.u64 t, %1; cvt.u32.u64 %0, t; }" : "=r"(a) : "l"(p));
    return a;
}
__device__ __forceinline__ uint32_t pack_bf2(float a, float b) {
    __nv_bfloat162 h = __floats2bfloat162_rn(a, b);
    return *(uint32_t*)&h;
}
__device__ __forceinline__ void split_bf(float x, float& hi, float& lo) {
    __nv_bfloat16 h = __float2bfloat16_rn(x);
    hi = __bfloat162float(h);
    lo = x - hi;
}
__device__ __forceinline__ float gelu_f(float x) {
    const float k0 = 0.7978845608028654f;
    float x3 = x * x * x;
    return 0.5f * x * (1.0f + tanhf(k0 * (x + 0.044715f * x3)));
}
__device__ __forceinline__ void mma16(float d[4], const uint32_t a[4], const uint32_t b[2]) {
    asm volatile(
        "mma.sync.aligned.m16n8k16.row.col.f32.bf16.bf16.f32 "
        "{%0,%1,%2,%3},{%4,%5,%6,%7},{%8,%9},{%0,%1,%2,%3};"
        : "+f"(d[0]), "+f"(d[1]), "+f"(d[2]), "+f"(d[3])
        : "r"(a[0]), "r"(a[1]), "r"(a[2]), "r"(a[3]),
          "r"(b[0]), "r"(b[1]));
}
__device__ __forceinline__ void ldsm4(uint32_t r[4], uint32_t addr) {
    asm volatile("ldmatrix.sync.aligned.m8n8.x4.shared.b16 {%0,%1,%2,%3}, [%4];"
                 : "=r"(r[0]), "=r"(r[1]), "=r"(r[2]), "=r"(r[3]) : "r"(addr));
}

// =====================================================================
//   bf16x3 mma.sync GEMM (m16n8k16) with ldmatrix fragment loads
// CTA tile 128 x BN2, BK=32, 8 warps (4 m x 2 n), warp tile 32 x BN2/2.
// smem rows stride RST=20 u32 (conflict-free LDS *and* LDSM phases).
// Per-stage (u32): Ah +0 (2560), Al +2560, Bh +5120 (BN2*20), Bl after.
// =====================================================================
#define RST 20

template<int BN2>
__device__ __forceinline__ void bf16x3_tile(
    const float* __restrict__ A, const int* __restrict__ Aidx,
    const float* __restrict__ B,
    const float* __restrict__ bias, float* __restrict__ C,
    int Mv, int N, int K, int m0, int n0, int flags)
{
    constexpr int NT = BN2 / 16;              // n-fragments per warp
    constexpr int NIT = BN2 / 16;             // B gmem iters
    constexpr int AL_U = 2560;
    constexpr int BH_U = 5120;
    constexpr int BL_U = 5120 + BN2 * RST;
    constexpr int STG_U = 5120 + 2 * BN2 * RST;

    extern __shared__ uint32_t smu[];
    const uint32_t sb0 = smem_u32(smu);
    int tid = threadIdx.x, lane = tid & 31, warp = tid >> 5;
    int wm = (warp >> 1) * 32, wn = (warp & 1) * (BN2 / 2);

    float acc[2][NT][4];
#pragma unroll
    for (int i = 0; i < 2; i++)
#pragma unroll
        for (int j = 0; j < NT; j++)
#pragma unroll
            for (int q = 0; q < 4; q++) acc[i][j][q] = 0.f;

    const int nk = K / 32;

    // A row pointers (optional indirection) + validity
    const float* arp[8];
    bool aval[8], bval[NIT];
#pragma unroll
    for (int it = 0; it < 8; it++) {
        int idx = tid + it * 256;
        int mm = idx >> 4;
        int gm = m0 + mm;
        aval[it] = gm < Mv;
        int r = aval[it] ? (Aidx ? Aidx[gm] : gm) : 0;
        arp[it] = A + (size_t)r * K + (idx & 15) * 2;
    }
#pragma unroll
    for (int it = 0; it < NIT; it++) {
        int idx = tid + it * 256;
        bval[it] = (n0 + (idx & (BN2 - 1))) < N;
    }

    float2 pa[8];
    float pb0[NIT], pb1[NIT];

    auto load_gmem = [&](int c) {
        int kc = c * 32;
#pragma unroll
        for (int it = 0; it < 8; it++)
            pa[it] = aval[it] ? *(const float2*)(arp[it] + kc) : make_float2(0.f, 0.f);
#pragma unroll
        for (int it = 0; it < NIT; it++) {
            int idx = tid + it * 256;
            int n = idx & (BN2 - 1), kp = idx / BN2;
            if (bval[it]) {
                const float* bp = B + (size_t)(kc + 2 * kp) * N + n0 + n;
                pb0[it] = bp[0];
                pb1[it] = bp[N];
            } else { pb0[it] = 0.f; pb1[it] = 0.f; }
        }
    };

    auto store_smem = [&](int c) {
        uint32_t* st = smu + (c & 1) * STG_U;
#pragma unroll
        for (int it = 0; it < 8; it++) {
            int idx = tid + it * 256;
            int m = idx >> 4, kp = idx & 15;
            float h0, l0, h1, l1;
            split_bf(pa[it].x, h0, l0);
            split_bf(pa[it].y, h1, l1);
            st[m * RST + kp]        = pack_bf2(h0, h1);
            st[AL_U + m * RST + kp] = pack_bf2(l0, l1);
        }
#pragma unroll
        for (int it = 0; it < NIT; it++) {
            int idx = tid + it * 256;
            int n = idx & (BN2 - 1), kp = idx / BN2;
            float h0, l0, h1, l1;
            split_bf(pb0[it], h0, l0);
            split_bf(pb1[it], h1, l1);
            st[BH_U + n * RST + kp] = pack_bf2(h0, h1);
            st[BL_U + n * RST + kp] = pack_bf2(l0, l1);
        }
    };

    // per-lane ldmatrix address components (row part constant across chunks)
    int arow = wm + (lane & 15);              // + mt*16
    uint32_t acolx = (lane >> 4) << 2;        // +4 u32 for k-high tiles
    int brow = wn + ((lane & 16) >> 1) + (lane & 7);   // + ntp*16
    uint32_t bcolx = (lane & 8) >> 1;         // +4 u32 for k-high reg pair

    load_gmem(0);
    store_smem(0);

    for (int c = 0; c < nk; c++) {
        __syncthreads();
        if (c + 1 < nk) load_gmem(c + 1);

        uint32_t sbase = sb0 + (c & 1) * (STG_U * 4);
#pragma unroll
        for (int ss = 0; ss < 2; ss++) {
            int kb = ss * 8;
            uint32_t ah[2][4], al[2][4];
#pragma unroll
            for (int mt = 0; mt < 2; mt++) {
                uint32_t aoff = sbase + ((arow + mt * 16) * RST + kb + acolx) * 4;
                ldsm4(ah[mt], aoff);
                ldsm4(al[mt], aoff + AL_U * 4);
            }
            uint32_t bh[NT][2], bl[NT][2];
#pragma unroll
            for (int ntp = 0; ntp < NT / 2; ntp++) {
                uint32_t boff = sbase + (BH_U + (brow + ntp * 16) * RST + kb + bcolx) * 4;
                ldsm4(&bh[2 * ntp][0], boff);
                ldsm4(&bl[2 * ntp][0], boff + (BL_U - BH_U) * 4);
            }
#pragma unroll
            for (int mt = 0; mt < 2; mt++)
#pragma unroll
                for (int nt = 0; nt < NT; nt++) mma16(acc[mt][nt], ah[mt], bh[nt]);
#pragma unroll
            for (int mt = 0; mt < 2; mt++)
#pragma unroll
                for (int nt = 0; nt < NT; nt++) mma16(acc[mt][nt], ah[mt], bl[nt]);
#pragma unroll
            for (int mt = 0; mt < 2; mt++)
#pragma unroll
                for (int nt = 0; nt < NT; nt++) mma16(acc[mt][nt], al[mt], bh[nt]);
        }

        if (c + 1 < nk) store_smem(c + 1);
    }

    // ---- epilogue ----
    int row = lane >> 2, cc = lane & 3;
#pragma unroll
    for (int mt = 0; mt < 2; mt++) {
#pragma unroll
        for (int h = 0; h < 2; h++) {
            int r = m0 + wm + mt * 16 + row + h * 8;
            if (r >= Mv) continue;
#pragma unroll
            for (int nt = 0; nt < NT; nt++) {
#pragma unroll
                for (int j = 0; j < 2; j++) {
                    int cn = n0 + wn + nt * 8 + cc * 2 + j;
                    if (cn >= N) continue;
                    float val = acc[mt][nt][h * 2 + j];
                    if (bias) val += bias[cn];
                    if (flags & FLAG_GELU) val = gelu_f(val);
                    float* cp = C + (size_t)r * N + cn;
                    if (flags & FLAG_ACC) *cp += val; else *cp = val;
                }
            }
        }
    }
}

#define SMEM64  ((5120 + 2 * 64 * RST) * 2 * 4)
#define SMEM128 ((5120 + 2 * 128 * RST) * 2 * 4)

__global__ void __launch_bounds__(256, 2) gemm64_kernel(
    const float* __restrict__ A, const float* __restrict__ B,
    const float* __restrict__ bias, float* __restrict__ C,
    int M, int N, int K, int flags)
{
    bf16x3_tile<64>(A, nullptr, B, bias, C, M, N, K,
                    blockIdx.y * 128, blockIdx.x * 64, flags);
}

__global__ void __launch_bounds__(256, 1) gemm128_kernel(
    const float* __restrict__ A, const float* __restrict__ B,
    const float* __restrict__ bias, float* __restrict__ C,
    int M, int N, int K, int flags)
{
    bf16x3_tile<128>(A, nullptr, B, bias, C, M, N, K,
                     blockIdx.y * 128, blockIdx.x * 128, flags);
}

// MoE GEMM1: A rows gathered from g_h via g_rowtok (fused gather)
__global__ void __launch_bounds__(256, 1) moe1_kernel(
    const float* __restrict__ Ah, const float* __restrict__ Bb,
    const float* __restrict__ biasb, float* __restrict__ Cb,
    int N, int K, int flags)
{
    int e = blockIdx.z;
    int cnt = g_counts[e];
    int m0 = blockIdx.y * 128;
    if (m0 >= cnt) return;
    int off = g_offsets[e];
    bf16x3_tile<128>(Ah, g_rowtok + off, Bb + (size_t)e * K * N,
                     biasb + (size_t)e * N, Cb + (size_t)off * N,
                     cnt, N, K, m0, blockIdx.x * 128, flags);
}

__global__ void __launch_bounds__(256, 1) moe2_kernel(
    const float* __restrict__ Ab, const float* __restrict__ Bb,
    const float* __restrict__ biasb, float* __restrict__ Cb,
    int N, int K, int flags)
{
    int e = blockIdx.z;
    int cnt = g_counts[e];
    int m0 = blockIdx.y * 128;
    if (m0 >= cnt) return;
    int off = g_offsets[e];
    bf16x3_tile<128>(Ab + (size_t)off * K, nullptr, Bb + (size_t)e * K * N,
                     biasb + (size_t)e * N, Cb + (size_t)off * N,
                     cnt, N, K, m0, blockIdx.x * 128, flags);
}

// ---------------- embedding gather ----------------
__global__ void embed_kernel(const int* __restrict__ ids, const float* __restrict__ emb) {
    int t = blockIdx.x;
    const float* src = emb + (size_t)ids[t] * DIM;
    for (int d = threadIdx.x; d < DIM; d += blockDim.x)
        g_x[t * DIM + d] = src[d];
}

// ---------------- layernorm ----------------
__global__ void ln_kernel(const float* __restrict__ x, const float* __restrict__ g,
                          const float* __restrict__ b, float* __restrict__ out) {
    int row = blockIdx.x;
    int t = threadIdx.x;
    const float* xr = x + (size_t)row * DIM;
    float v0 = xr[t], v1 = xr[t + 256], v2 = xr[t + 512];
    __shared__ float red[256];
    red[t] = v0 + v1 + v2;
    __syncthreads();
    for (int o = 128; o > 0; o >>= 1) { if (t < o) red[t] += red[t + o]; __syncthreads(); }
    float mean = red[0] * (1.0f / DIM);
    __syncthreads();
    float d0 = v0 - mean, d1 = v1 - mean, d2 = v2 - mean;
    red[t] = d0 * d0 + d1 * d1 + d2 * d2;
    __syncthreads();
    for (int o = 128; o > 0; o >>= 1) { if (t < o) red[t] += red[t + o]; __syncthreads(); }
    float rstd = rsqrtf(red[0] * (1.0f / DIM) + 1e-6f);
    float* orow = out + (size_t)row * DIM;
    orow[t]       = d0 * rstd * g[t]       + b[t];
    orow[t + 256] = d1 * rstd * g[t + 256] + b[t + 256];
    orow[t + 512] = d2 * rstd * g[t + 512] + b[t + 512];
}

// ---------------- RoPE on q and k (in place) ----------------
__global__ void rope_kernel() {
    int idx = blockIdx.x * blockDim.x + threadIdx.x;
    if (idx >= TB * NH * 32) return;
    int j = idx & 31;
    int h = (idx >> 5) % NH;
    int t = idx / (32 * NH);
    int s = t % SEQ;
    float inv = powf(10000.0f, -(float)j * (1.0f / 32.0f));
    float ang = (float)s * inv;
    float sn, cs;
    sincosf(ang, &sn, &cs);
    int base = t * DIM + h * HD;
    float a = g_q[base + j], b2 = g_q[base + 32 + j];
    g_q[base + j]      = a * cs - b2 * sn;
    g_q[base + 32 + j] = b2 * cs + a * sn;
    a = g_k[base + j]; b2 = g_k[base + 32 + j];
    g_k[base + j]      = a * cs - b2 * sn;
    g_k[base + 32 + j] = b2 * cs + a * sn;
}

// ---- attention: one warp per (b,h,q), 4 k-positions per iteration ----
__global__ void attn_kernel() {
    int gw = (blockIdx.x * blockDim.x + threadIdx.x) >> 5;
    int lane = threadIdx.x & 31;
    if (gw >= BATCH * NH * SEQ) return;
    int qi = gw % SEQ;
    int h = (gw / SEQ) % NH;
    int b = gw / (SEQ * NH);
    int t = b * SEQ + qi;
    int g = lane >> 3, j = lane & 7;

    const float* qp = g_q + (size_t)t * DIM + h * HD + j * 8;
    float ql[8];
#pragma unroll
    for (int i = 0; i < 8; i++) ql[i] = qp[i] * 0.125f;

    size_t base = (size_t)b * SEQ * DIM + h * HD;
    const float* kb = g_k + base;
    const float* vb = g_v + base;

    float m = -1e30f, l = 0.f, a0 = 0.f, a1 = 0.f;

    for (int s0 = 0; s0 <= qi; s0 += 4) {
        int s = s0 + g;
        int sc = s > qi ? qi : s;
        const float* kp = kb + (size_t)sc * DIM + j * 8;
        float4 k0 = *(const float4*)kp;
        float4 k1 = *(const float4*)(kp + 4);
        float d = ql[0] * k0.x + ql[1] * k0.y + ql[2] * k0.z + ql[3] * k0.w
                + ql[4] * k1.x + ql[5] * k1.y + ql[6] * k1.z + ql[7] * k1.w;
        d += __shfl_xor_sync(0xffffffffu, d, 1);
        d += __shfl_xor_sync(0xffffffffu, d, 2);
        d += __shfl_xor_sync(0xffffffffu, d, 4);
        if (s > qi) d = -1e30f;
        float d0 = __shfl_sync(0xffffffffu, d, j);
        float d1 = __shfl_sync(0xffffffffu, d, 8 + j);
        float d2 = __shfl_sync(0xffffffffu, d, 16 + j);
        float d3 = __shfl_sync(0xffffffffu, d, 24 + j);
        float mn = fmaxf(fmaxf(fmaxf(fmaxf(m, d0), d1), d2), d3);
        float corr = __expf(m - mn);
        float p0 = __expf(d0 - mn);
        float p1 = __expf(d1 - mn);
        float p2 = __expf(d2 - mn);
        float p3 = __expf(d3 - mn);
        int s1 = s0 + 1 > qi ? qi : s0 + 1;
        int s2 = s0 + 2 > qi ? qi : s0 + 2;
        int s3 = s0 + 3 > qi ? qi : s0 + 3;
        const float* v0p = vb + (size_t)s0 * DIM;
        const float* v1p = vb + (size_t)s1 * DIM;
        const float* v2p = vb + (size_t)s2 * DIM;
        const float* v3p = vb + (size_t)s3 * DIM;
        l  = l  * corr + (p0 + p1 + p2 + p3);
        a0 = a0 * corr + p0 * v0p[lane] + p1 * v1p[lane]
                       + p2 * v2p[lane] + p3 * v3p[lane];
        a1 = a1 * corr + p0 * v0p[lane + 32] + p1 * v1p[lane + 32]
                       + p2 * v2p[lane + 32] + p3 * v3p[lane + 32];
        m = mn;
    }
    float inv = 1.0f / l;
    float* op = g_ao + (size_t)t * DIM + h * HD;
    op[lane] = a0 * inv;
    op[lane + 32] = a1 * inv;
}

// ---------------- MoE gate logits: warp per (token,expert) ------------------
__global__ void gate_kernel(const float* __restrict__ Wg) {
    int tok = blockIdx.x;
    int e = threadIdx.x >> 5;
    int lane = threadIdx.x & 31;
    const float* hr = g_h + (size_t)tok * DIM;
    float s = 0.f;
    for (int d = lane; d < DIM; d += 32) s += hr[d] * Wg[d * NE + e];
#pragma unroll
    for (int o = 16; o; o >>= 1) s += __shfl_xor_sync(0xffffffffu, s, o);
    if (lane == 0) g_logits[tok * NE + e] = s;
}

__global__ void zero_kernel() {
    if (threadIdx.x < NE) g_counts[threadIdx.x] = 0;
}

__global__ void topk_kernel() {
    int t = blockIdx.x * blockDim.x + threadIdx.x;
    if (t >= TB) return;
    float lg[NE];
    float m = -1e30f;
#pragma unroll
    for (int e = 0; e < NE; e++) { lg[e] = g_logits[t * NE + e]; m = fmaxf(m, lg[e]); }
    float ssum = 0.f;
#pragma unroll
    for (int e = 0; e < NE; e++) { lg[e] = expf(lg[e] - m); ssum += lg[e]; }
    int i0 = 0;
#pragma unroll
    for (int e = 1; e < NE; e++) if (lg[e] > lg[i0]) i0 = e;
    int i1 = (i0 == 0) ? 1 : 0;
#pragma unroll
    for (int e = 0; e < NE; e++) if (e != i0 && e != i1 && lg[e] > lg[i1]) i1 = e;
    float v0 = lg[i0] / ssum, v1 = lg[i1] / ssum;
    float winv = 1.0f / (v0 + v1);
    g_te[2 * t] = i0; g_te[2 * t + 1] = i1;
    g_tw[2 * t] = v0 * winv; g_tw[2 * t + 1] = v1 * winv;
    atomicAdd(&g_counts[i0], 1);
    atomicAdd(&g_counts[i1], 1);
}

__global__ void scan_kernel() {
    int acc = 0;
    for (int e = 0; e < NE; e++) {
        g_offsets[e] = acc;
        acc += g_counts[e];
        g_cursor[e] = 0;
    }
}

__global__ void assign_kernel() {
    int t = blockIdx.x * blockDim.x + threadIdx.x;
    if (t >= TB) return;
    for (int kk = 0; kk < 2; kk++) {
        int e = g_te[2 * t + kk];
        int pos = g_offsets[e] + atomicAdd(&g_cursor[e], 1);
        g_rowtok[pos] = t;
        g_roww[pos] = g_tw[2 * t + kk];
        g_perm[2 * t + kk] = pos;
    }
}

// x[t] += w0*yff[r0] + w1*yff[r1]
__global__ void scatter_kernel() {
    int t = blockIdx.x;
    int r0 = g_perm[2 * t], r1 = g_perm[2 * t + 1];
    float w0 = g_roww[r0], w1 = g_roww[r1];
    for (int d = threadIdx.x; d < DIM; d += blockDim.x)
        g_x[(size_t)t * DIM + d] += w0 * g_yff[(size_t)r0 * DIM + d]
                                  + w1 * g_yff[(size_t)r1 * DIM + d];
}

// ---------------- host orchestration ----------------
extern "C" void kernel_launch(void* const* d_in, const int* in_sizes, int n_in,
                              void* d_out, int out_size) {
    (void)in_sizes; (void)n_in; (void)out_size;
    const int*   ids   = (const int*)  d_in[0];
    const float* emb   = (const float*)d_in[1];
    const float* ln1_g = (const float*)d_in[2];
    const float* ln1_b = (const float*)d_in[3];
    const float* ln2_g = (const float*)d_in[4];
    const float* ln2_b = (const float*)d_in[5];
    const float* Wq    = (const float*)d_in[6];
    const float* Wkv   = (const float*)d_in[7];
    const float* Wk    = (const float*)d_in[8];
    const float* Wv    = (const float*)d_in[9];
    const float* Wo    = (const float*)d_in[10];
    const float* Wg    = (const float*)d_in[11];
    const float* W1    = (const float*)d_in[12];
    const float* b1    = (const float*)d_in[13];
    const float* W2    = (const float*)d_in[14];
    const float* b2    = (const float*)d_in[15];
    const float* lnf_g = (const float*)d_in[16];
    const float* lnf_b = (const float*)d_in[17];
    const float* Wout  = (const float*)d_in[18];

    cudaFuncSetAttribute(gemm64_kernel,
                         cudaFuncAttributeMaxDynamicSharedMemorySize, SMEM64);
    cudaFuncSetAttribute(gemm128_kernel,
                         cudaFuncAttributeMaxDynamicSharedMemorySize, SMEM128);
    cudaFuncSetAttribute(moe1_kernel,
                         cudaFuncAttributeMaxDynamicSharedMemorySize, SMEM128);
    cudaFuncSetAttribute(moe2_kernel,
                         cudaFuncAttributeMaxDynamicSharedMemorySize, SMEM128);

    float *px, *ph, *pq, *pk, *pv, *plat, *pao, *phff, *pyff;
    cudaGetSymbolAddress((void**)&px,   g_x);
    cudaGetSymbolAddress((void**)&ph,   g_h);
    cudaGetSymbolAddress((void**)&pq,   g_q);
    cudaGetSymbolAddress((void**)&pk,   g_k);
    cudaGetSymbolAddress((void**)&pv,   g_v);
    cudaGetSymbolAddress((void**)&plat, g_lat);
    cudaGetSymbolAddress((void**)&pao,  g_ao);
    cudaGetSymbolAddress((void**)&phff, g_hff);
    cudaGetSymbolAddress((void**)&pyff, g_yff);

    embed_kernel<<<TB, 256>>>(ids, emb);

    for (int l = 0; l < NLAYER; l++) {
        // --- attention block ---
        ln_kernel<<<TB, 256>>>(px, ln1_g + l * DIM, ln1_b + l * DIM, ph);
        gemm64_kernel<<<dim3(DIM / 64, TB / 128), 256, SMEM64>>>(
            ph, Wq + (size_t)l * DIM * DIM, nullptr, pq, TB, DIM, DIM, 0);
        gemm64_kernel<<<dim3(DLAT / 64, TB / 128), 256, SMEM64>>>(
            ph, Wkv + (size_t)l * DIM * DLAT, nullptr, plat, TB, DLAT, DIM, 0);
        gemm64_kernel<<<dim3(DIM / 64, TB / 128), 256, SMEM64>>>(
            plat, Wk + (size_t)l * DLAT * DIM, nullptr, pk, TB, DIM, DLAT, 0);
        gemm64_kernel<<<dim3(DIM / 64, TB / 128), 256, SMEM64>>>(
            plat, Wv + (size_t)l * DLAT * DIM, nullptr, pv, TB, DIM, DLAT, 0);
        rope_kernel<<<(TB * NH * 32 + 255) / 256, 256>>>();
        attn_kernel<<<(BATCH * NH * SEQ * 32 + 255) / 256, 256>>>();
        gemm64_kernel<<<dim3(DIM / 64, TB / 128), 256, SMEM64>>>(
            pao, Wo + (size_t)l * DIM * DIM, nullptr, px, TB, DIM, DIM, FLAG_ACC);

        // --- MoE block ---
        ln_kernel<<<TB, 256>>>(px, ln2_g + l * DIM, ln2_b + l * DIM, ph);
        gate_kernel<<<TB, 256>>>(Wg + (size_t)l * DIM * NE);
        zero_kernel<<<1, 32>>>();
        topk_kernel<<<TB / 256, 256>>>();
        scan_kernel<<<1, 1>>>();
        assign_kernel<<<TB / 256, 256>>>();
        moe1_kernel<<<dim3(DFF / 128, 2 * TB / 128, NE), 256, SMEM128>>>(
            ph, W1 + (size_t)l * NE * DIM * DFF, b1 + (size_t)l * NE * DFF, phff,
            DFF, DIM, FLAG_GELU);
        moe2_kernel<<<dim3(DIM / 128, 2 * TB / 128, NE), 256, SMEM128>>>(
            phff, W2 + (size_t)l * NE * DFF * DIM, b2 + (size_t)l * NE * DIM, pyff,
            DIM, DFF, 0);
        scatter_kernel<<<TB, 256>>>();
    }

    // --- final LN + LM head ---
    ln_kernel<<<TB, 256>>>(px, lnf_g, lnf_b, ph);
    gemm128_kernel<<<dim3(NV / 128, TB / 128), 256, SMEM128>>>(
        ph, Wout, nullptr, (float*)d_out, TB, NV, DIM, 0);
}

// round 7
// speedup vs baseline: 1.9848x; 1.0160x over previous
#include <cuda_runtime.h>
#include <cuda_bf16.h>
#include <math.h>
#include <stdint.h>

// ---------------- problem dims ----------------
#define TB 2048      // B*S tokens
#define SEQ 1024
#define BATCH 2
#define DIM 768
#define NH 12
#define HD 64
#define DLAT 192
#define DFF 3072
#define NE 8
#define NV 32000
#define NLAYER 2

#define FLAG_ACC 1
#define FLAG_GELU 2

// ---------------- scratch (device globals; no allocation) ----------------
__device__ float g_x[TB * DIM];
__device__ float g_h[TB * DIM];
__device__ float g_q[TB * DIM];
__device__ float g_k[TB * DIM];
__device__ float g_v[TB * DIM];
__device__ float g_lat[TB * DLAT];
__device__ float g_ao[TB * DIM];
__device__ float g_logits[TB * NE];
__device__ float g_tw[TB * 2];
__device__ int   g_te[TB * 2];
__device__ int   g_counts[NE];
__device__ int   g_offsets[NE];
__device__ int   g_cursor[NE];
__device__ int   g_rowtok[2 * TB];
__device__ float g_roww[2 * TB];
__device__ int   g_perm[2 * TB];
__device__ float g_hff[2 * TB * DFF];
__device__ float g_yff[2 * TB * DIM];

// ---------------- helpers ----------------
__device__ __forceinline__ uint32_t smem_u32(const void* p) {
    uint32_t a;
    asm("{ .reg .u64 t; cvta.to.shared.u64 t, %1; cvt.u32.u64 %0, t; }" : "=r"(a) : "l"(p));
    return a;
}
__device__ __forceinline__ uint32_t pack_bf2(float a, float b) {
    __nv_bfloat162 h = __floats2bfloat162_rn(a, b);
    return *(uint32_t*)&h;
}
__device__ __forceinline__ void split_bf(float x, float& hi, float& lo) {
    __nv_bfloat16 h = __float2bfloat16_rn(x);
    hi = __bfloat162float(h);
    lo = x - hi;
}
__device__ __forceinline__ float gelu_f(float x) {
    const float k0 = 0.7978845608028654f;
    float x3 = x * x * x;
    return 0.5f * x * (1.0f + tanhf(k0 * (x + 0.044715f * x3)));
}
__device__ __forceinline__ void mma16(float d[4], const uint32_t a[4], const uint32_t b[2]) {
    asm volatile(
        "mma.sync.aligned.m16n8k16.row.col.f32.bf16.bf16.f32 "
        "{%0,%1,%2,%3},{%4,%5,%6,%7},{%8,%9},{%0,%1,%2,%3};"
        : "+f"(d[0]), "+f"(d[1]), "+f"(d[2]), "+f"(d[3])
        : "r"(a[0]), "r"(a[1]), "r"(a[2]), "r"(a[3]),
          "r"(b[0]), "r"(b[1]));
}
__device__ __forceinline__ void ldsm4(uint32_t r[4], uint32_t addr) {
    asm volatile("ldmatrix.sync.aligned.m8n8.x4.shared.b16 {%0,%1,%2,%3}, [%4];"
                 : "=r"(r[0]), "=r"(r[1]), "=r"(r[2]), "=r"(r[3]) : "r"(addr));
}

// =====================================================================
//   bf16x3 mma.sync GEMM (m16n8k16) with ldmatrix fragment loads
// CTA tile 128 x 64, BK=32, 8 warps (4 m x 2 n), warp tile 32 x 32.
// smem rows stride RST=20 u32 (conflict-free LDS *and* LDSM phases).
// 2 CTAs/SM (122 regs, 30KB smem/stage x2).
// =====================================================================
#define RST 20
#define BN2 64
#define NT 4           // n-fragments per warp
#define NIT 4          // B gmem iters
#define AL_U 2560
#define BH_U 5120
#define BL_U (5120 + BN2 * RST)
#define STG_U (5120 + 2 * BN2 * RST)
#define SMEM64 (STG_U * 2 * 4)

__device__ __forceinline__ void bf16x3_tile(
    const float* __restrict__ A, const int* __restrict__ Aidx,
    const float* __restrict__ B,
    const float* __restrict__ bias, float* __restrict__ C,
    int Mv, int N, int K, int m0, int n0, int flags)
{
    extern __shared__ uint32_t smu[];
    const uint32_t sb0 = smem_u32(smu);
    int tid = threadIdx.x, lane = tid & 31, warp = tid >> 5;
    int wm = (warp >> 1) * 32, wn = (warp & 1) * (BN2 / 2);

    float acc[2][NT][4];
#pragma unroll
    for (int i = 0; i < 2; i++)
#pragma unroll
        for (int j = 0; j < NT; j++)
#pragma unroll
            for (int q = 0; q < 4; q++) acc[i][j][q] = 0.f;

    const int nk = K / 32;

    // A row pointers (optional indirection) + validity
    const float* arp[8];
    bool aval[8], bval[NIT];
#pragma unroll
    for (int it = 0; it < 8; it++) {
        int idx = tid + it * 256;
        int mm = idx >> 4;
        int gm = m0 + mm;
        aval[it] = gm < Mv;
        int r = aval[it] ? (Aidx ? Aidx[gm] : gm) : 0;
        arp[it] = A + (size_t)r * K + (idx & 15) * 2;
    }
#pragma unroll
    for (int it = 0; it < NIT; it++) {
        int idx = tid + it * 256;
        bval[it] = (n0 + (idx & (BN2 - 1))) < N;
    }

    float2 pa[8];
    float pb0[NIT], pb1[NIT];

    auto load_gmem = [&](int c) {
        int kc = c * 32;
#pragma unroll
        for (int it = 0; it < 8; it++)
            pa[it] = aval[it] ? *(const float2*)(arp[it] + kc) : make_float2(0.f, 0.f);
#pragma unroll
        for (int it = 0; it < NIT; it++) {
            int idx = tid + it * 256;
            int n = idx & (BN2 - 1), kp = idx / BN2;
            if (bval[it]) {
                const float* bp = B + (size_t)(kc + 2 * kp) * N + n0 + n;
                pb0[it] = bp[0];
                pb1[it] = bp[N];
            } else { pb0[it] = 0.f; pb1[it] = 0.f; }
        }
    };

    auto store_smem = [&](int c) {
        uint32_t* st = smu + (c & 1) * STG_U;
#pragma unroll
        for (int it = 0; it < 8; it++) {
            int idx = tid + it * 256;
            int m = idx >> 4, kp = idx & 15;
            float h0, l0, h1, l1;
            split_bf(pa[it].x, h0, l0);
            split_bf(pa[it].y, h1, l1);
            st[m * RST + kp]        = pack_bf2(h0, h1);
            st[AL_U + m * RST + kp] = pack_bf2(l0, l1);
        }
#pragma unroll
        for (int it = 0; it < NIT; it++) {
            int idx = tid + it * 256;
            int n = idx & (BN2 - 1), kp = idx / BN2;
            float h0, l0, h1, l1;
            split_bf(pb0[it], h0, l0);
            split_bf(pb1[it], h1, l1);
            st[BH_U + n * RST + kp] = pack_bf2(h0, h1);
            st[BL_U + n * RST + kp] = pack_bf2(l0, l1);
        }
    };

    // per-lane ldmatrix address components
    int arow = wm + (lane & 15);
    uint32_t acolx = (lane >> 4) << 2;
    int brow = wn + ((lane & 16) >> 1) + (lane & 7);
    uint32_t bcolx = (lane & 8) >> 1;

    load_gmem(0);
    store_smem(0);

    for (int c = 0; c < nk; c++) {
        __syncthreads();
        if (c + 1 < nk) load_gmem(c + 1);

        uint32_t sbase = sb0 + (c & 1) * (STG_U * 4);
#pragma unroll
        for (int ss = 0; ss < 2; ss++) {
            int kb = ss * 8;
            uint32_t ah[2][4], al[2][4];
#pragma unroll
            for (int mt = 0; mt < 2; mt++) {
                uint32_t aoff = sbase + ((arow + mt * 16) * RST + kb + acolx) * 4;
                ldsm4(ah[mt], aoff);
                ldsm4(al[mt], aoff + AL_U * 4);
            }
            uint32_t bh[NT][2], bl[NT][2];
#pragma unroll
            for (int ntp = 0; ntp < NT / 2; ntp++) {
                uint32_t boff = sbase + (BH_U + (brow + ntp * 16) * RST + kb + bcolx) * 4;
                ldsm4(&bh[2 * ntp][0], boff);
                ldsm4(&bl[2 * ntp][0], boff + (BL_U - BH_U) * 4);
            }
#pragma unroll
            for (int mt = 0; mt < 2; mt++)
#pragma unroll
                for (int nt = 0; nt < NT; nt++) mma16(acc[mt][nt], ah[mt], bh[nt]);
#pragma unroll
            for (int mt = 0; mt < 2; mt++)
#pragma unroll
                for (int nt = 0; nt < NT; nt++) mma16(acc[mt][nt], ah[mt], bl[nt]);
#pragma unroll
            for (int mt = 0; mt < 2; mt++)
#pragma unroll
                for (int nt = 0; nt < NT; nt++) mma16(acc[mt][nt], al[mt], bh[nt]);
        }

        if (c + 1 < nk) store_smem(c + 1);
    }

    // ---- epilogue ----
    int row = lane >> 2, cc = lane & 3;
#pragma unroll
    for (int mt = 0; mt < 2; mt++) {
#pragma unroll
        for (int h = 0; h < 2; h++) {
            int r = m0 + wm + mt * 16 + row + h * 8;
            if (r >= Mv) continue;
#pragma unroll
            for (int nt = 0; nt < NT; nt++) {
#pragma unroll
                for (int j = 0; j < 2; j++) {
                    int cn = n0 + wn + nt * 8 + cc * 2 + j;
                    if (cn >= N) continue;
                    float val = acc[mt][nt][h * 2 + j];
                    if (bias) val += bias[cn];
                    if (flags & FLAG_GELU) val = gelu_f(val);
                    float* cp = C + (size_t)r * N + cn;
                    if (flags & FLAG_ACC) *cp += val; else *cp = val;
                }
            }
        }
    }
}

__global__ void __launch_bounds__(256, 2) gemm64_kernel(
    const float* __restrict__ A, const float* __restrict__ B,
    const float* __restrict__ bias, float* __restrict__ C,
    int M, int N, int K, int flags)
{
    bf16x3_tile(A, nullptr, B, bias, C, M, N, K,
                blockIdx.y * 128, blockIdx.x * 64, flags);
}

// fused Wq (N=768, blocks 0..11) + Wkv (N=192, blocks 12..14); shared A
__global__ void __launch_bounds__(256, 2) qkv1_kernel(
    const float* __restrict__ A, const float* __restrict__ Wq,
    const float* __restrict__ Wkv, float* __restrict__ Cq,
    float* __restrict__ Clat)
{
    int bx = blockIdx.x;
    if (bx < 12)
        bf16x3_tile(A, nullptr, Wq, nullptr, Cq, TB, DIM, DIM,
                    blockIdx.y * 128, bx * 64, 0);
    else
        bf16x3_tile(A, nullptr, Wkv, nullptr, Clat, TB, DLAT, DIM,
                    blockIdx.y * 128, (bx - 12) * 64, 0);
}

// fused Wk (blocks 0..11) + Wv (blocks 12..23); shared A (lat)
__global__ void __launch_bounds__(256, 2) kv2_kernel(
    const float* __restrict__ A, const float* __restrict__ Wk,
    const float* __restrict__ Wv, float* __restrict__ Ck,
    float* __restrict__ Cv)
{
    int bx = blockIdx.x;
    if (bx < 12)
        bf16x3_tile(A, nullptr, Wk, nullptr, Ck, TB, DIM, DLAT,
                    blockIdx.y * 128, bx * 64, 0);
    else
        bf16x3_tile(A, nullptr, Wv, nullptr, Cv, TB, DIM, DLAT,
                    blockIdx.y * 128, (bx - 12) * 64, 0);
}

// MoE GEMM1: A rows gathered from g_h via g_rowtok (fused gather)
__global__ void __launch_bounds__(256, 2) moe1_kernel(
    const float* __restrict__ Ah, const float* __restrict__ Bb,
    const float* __restrict__ biasb, float* __restrict__ Cb,
    int N, int K, int flags)
{
    int e = blockIdx.z;
    int cnt = g_counts[e];
    int m0 = blockIdx.y * 128;
    if (m0 >= cnt) return;
    int off = g_offsets[e];
    bf16x3_tile(Ah, g_rowtok + off, Bb + (size_t)e * K * N,
                biasb + (size_t)e * N, Cb + (size_t)off * N,
                cnt, N, K, m0, blockIdx.x * 64, flags);
}

__global__ void __launch_bounds__(256, 2) moe2_kernel(
    const float* __restrict__ Ab, const float* __restrict__ Bb,
    const float* __restrict__ biasb, float* __restrict__ Cb,
    int N, int K, int flags)
{
    int e = blockIdx.z;
    int cnt = g_counts[e];
    int m0 = blockIdx.y * 128;
    if (m0 >= cnt) return;
    int off = g_offsets[e];
    bf16x3_tile(Ab + (size_t)off * K, nullptr, Bb + (size_t)e * K * N,
                biasb + (size_t)e * N, Cb + (size_t)off * N,
                cnt, N, K, m0, blockIdx.x * 64, flags);
}

// ---------------- embedding gather ----------------
__global__ void embed_kernel(const int* __restrict__ ids, const float* __restrict__ emb) {
    int t = blockIdx.x;
    const float* src = emb + (size_t)ids[t] * DIM;
    for (int d = threadIdx.x; d < DIM; d += blockDim.x)
        g_x[t * DIM + d] = src[d];
}

// ---------------- layernorm ----------------
__global__ void ln_kernel(const float* __restrict__ x, const float* __restrict__ g,
                          const float* __restrict__ b, float* __restrict__ out) {
    int row = blockIdx.x;
    int t = threadIdx.x;
    const float* xr = x + (size_t)row * DIM;
    float v0 = xr[t], v1 = xr[t + 256], v2 = xr[t + 512];
    __shared__ float red[256];
    red[t] = v0 + v1 + v2;
    __syncthreads();
    for (int o = 128; o > 0; o >>= 1) { if (t < o) red[t] += red[t + o]; __syncthreads(); }
    float mean = red[0] * (1.0f / DIM);
    __syncthreads();
    float d0 = v0 - mean, d1 = v1 - mean, d2 = v2 - mean;
    red[t] = d0 * d0 + d1 * d1 + d2 * d2;
    __syncthreads();
    for (int o = 128; o > 0; o >>= 1) { if (t < o) red[t] += red[t + o]; __syncthreads(); }
    float rstd = rsqrtf(red[0] * (1.0f / DIM) + 1e-6f);
    float* orow = out + (size_t)row * DIM;
    orow[t]       = d0 * rstd * g[t]       + b[t];
    orow[t + 256] = d1 * rstd * g[t + 256] + b[t + 256];
    orow[t + 512] = d2 * rstd * g[t + 512] + b[t + 512];
}

// ---------------- RoPE on q and k (in place) ----------------
__global__ void rope_kernel() {
    int idx = blockIdx.x * blockDim.x + threadIdx.x;
    if (idx >= TB * NH * 32) return;
    int j = idx & 31;
    int h = (idx >> 5) % NH;
    int t = idx / (32 * NH);
    int s = t % SEQ;
    float inv = powf(10000.0f, -(float)j * (1.0f / 32.0f));
    float ang = (float)s * inv;
    float sn, cs;
    sincosf(ang, &sn, &cs);
    int base = t * DIM + h * HD;
    float a = g_q[base + j], b2 = g_q[base + 32 + j];
    g_q[base + j]      = a * cs - b2 * sn;
    g_q[base + 32 + j] = b2 * cs + a * sn;
    a = g_k[base + j]; b2 = g_k[base + 32 + j];
    g_k[base + j]      = a * cs - b2 * sn;
    g_k[base + 32 + j] = b2 * cs + a * sn;
}

// ---- attention: one warp per (b,h,q), 4 k-positions per iteration ----
__global__ void attn_kernel() {
    int gw = (blockIdx.x * blockDim.x + threadIdx.x) >> 5;
    int lane = threadIdx.x & 31;
    if (gw >= BATCH * NH * SEQ) return;
    int qi = gw % SEQ;
    int h = (gw / SEQ) % NH;
    int b = gw / (SEQ * NH);
    int t = b * SEQ + qi;
    int g = lane >> 3, j = lane & 7;

    const float* qp = g_q + (size_t)t * DIM + h * HD + j * 8;
    float ql[8];
#pragma unroll
    for (int i = 0; i < 8; i++) ql[i] = qp[i] * 0.125f;

    size_t base = (size_t)b * SEQ * DIM + h * HD;
    const float* kb = g_k + base;
    const float* vb = g_v + base;

    float m = -1e30f, l = 0.f, a0 = 0.f, a1 = 0.f;

    for (int s0 = 0; s0 <= qi; s0 += 4) {
        int s = s0 + g;
        int sc = s > qi ? qi : s;
        const float* kp = kb + (size_t)sc * DIM + j * 8;
        float4 k0 = *(const float4*)kp;
        float4 k1 = *(const float4*)(kp + 4);
        float d = ql[0] * k0.x + ql[1] * k0.y + ql[2] * k0.z + ql[3] * k0.w
                + ql[4] * k1.x + ql[5] * k1.y + ql[6] * k1.z + ql[7] * k1.w;
        d += __shfl_xor_sync(0xffffffffu, d, 1);
        d += __shfl_xor_sync(0xffffffffu, d, 2);
        d += __shfl_xor_sync(0xffffffffu, d, 4);
        if (s > qi) d = -1e30f;
        float d0 = __shfl_sync(0xffffffffu, d, j);
        float d1 = __shfl_sync(0xffffffffu, d, 8 + j);
        float d2 = __shfl_sync(0xffffffffu, d, 16 + j);
        float d3 = __shfl_sync(0xffffffffu, d, 24 + j);
        float mn = fmaxf(fmaxf(fmaxf(fmaxf(m, d0), d1), d2), d3);
        float corr = __expf(m - mn);
        float p0 = __expf(d0 - mn);
        float p1 = __expf(d1 - mn);
        float p2 = __expf(d2 - mn);
        float p3 = __expf(d3 - mn);
        int s1 = s0 + 1 > qi ? qi : s0 + 1;
        int s2 = s0 + 2 > qi ? qi : s0 + 2;
        int s3 = s0 + 3 > qi ? qi : s0 + 3;
        const float* v0p = vb + (size_t)s0 * DIM;
        const float* v1p = vb + (size_t)s1 * DIM;
        const float* v2p = vb + (size_t)s2 * DIM;
        const float* v3p = vb + (size_t)s3 * DIM;
        l  = l  * corr + (p0 + p1 + p2 + p3);
        a0 = a0 * corr + p0 * v0p[lane] + p1 * v1p[lane]
                       + p2 * v2p[lane] + p3 * v3p[lane];
        a1 = a1 * corr + p0 * v0p[lane + 32] + p1 * v1p[lane + 32]
                       + p2 * v2p[lane + 32] + p3 * v3p[lane + 32];
        m = mn;
    }
    float inv = 1.0f / l;
    float* op = g_ao + (size_t)t * DIM + h * HD;
    op[lane] = a0 * inv;
    op[lane + 32] = a1 * inv;
}

// ---------------- MoE gate logits: warp per (token,expert) ------------------
__global__ void gate_kernel(const float* __restrict__ Wg) {
    int tok = blockIdx.x;
    int e = threadIdx.x >> 5;
    int lane = threadIdx.x & 31;
    const float* hr = g_h + (size_t)tok * DIM;
    float s = 0.f;
    for (int d = lane; d < DIM; d += 32) s += hr[d] * Wg[d * NE + e];
#pragma unroll
    for (int o = 16; o; o >>= 1) s += __shfl_xor_sync(0xffffffffu, s, o);
    if (lane == 0) g_logits[tok * NE + e] = s;
}

__global__ void zero_kernel() {
    if (threadIdx.x < NE) g_counts[threadIdx.x] = 0;
}

__global__ void topk_kernel() {
    int t = blockIdx.x * blockDim.x + threadIdx.x;
    if (t >= TB) return;
    float lg[NE];
    float m = -1e30f;
#pragma unroll
    for (int e = 0; e < NE; e++) { lg[e] = g_logits[t * NE + e]; m = fmaxf(m, lg[e]); }
    float ssum = 0.f;
#pragma unroll
    for (int e = 0; e < NE; e++) { lg[e] = expf(lg[e] - m); ssum += lg[e]; }
    int i0 = 0;
#pragma unroll
    for (int e = 1; e < NE; e++) if (lg[e] > lg[i0]) i0 = e;
    int i1 = (i0 == 0) ? 1 : 0;
#pragma unroll
    for (int e = 0; e < NE; e++) if (e != i0 && e != i1 && lg[e] > lg[i1]) i1 = e;
    float v0 = lg[i0] / ssum, v1 = lg[i1] / ssum;
    float winv = 1.0f / (v0 + v1);
    g_te[2 * t] = i0; g_te[2 * t + 1] = i1;
    g_tw[2 * t] = v0 * winv; g_tw[2 * t + 1] = v1 * winv;
    atomicAdd(&g_counts[i0], 1);
    atomicAdd(&g_counts[i1], 1);
}

__global__ void scan_kernel() {
    int acc = 0;
    for (int e = 0; e < NE; e++) {
        g_offsets[e] = acc;
        acc += g_counts[e];
        g_cursor[e] = 0;
    }
}

__global__ void assign_kernel() {
    int t = blockIdx.x * blockDim.x + threadIdx.x;
    if (t >= TB) return;
    for (int kk = 0; kk < 2; kk++) {
        int e = g_te[2 * t + kk];
        int pos = g_offsets[e] + atomicAdd(&g_cursor[e], 1);
        g_rowtok[pos] = t;
        g_roww[pos] = g_tw[2 * t + kk];
        g_perm[2 * t + kk] = pos;
    }
}

// x[t] += w0*yff[r0] + w1*yff[r1]
__global__ void scatter_kernel() {
    int t = blockIdx.x;
    int r0 = g_perm[2 * t], r1 = g_perm[2 * t + 1];
    float w0 = g_roww[r0], w1 = g_roww[r1];
    for (int d = threadIdx.x; d < DIM; d += blockDim.x)
        g_x[(size_t)t * DIM + d] += w0 * g_yff[(size_t)r0 * DIM + d]
                                  + w1 * g_yff[(size_t)r1 * DIM + d];
}

// ---------------- host orchestration ----------------
extern "C" void kernel_launch(void* const* d_in, const int* in_sizes, int n_in,
                              void* d_out, int out_size) {
    (void)in_sizes; (void)n_in; (void)out_size;
    const int*   ids   = (const int*)  d_in[0];
    const float* emb   = (const float*)d_in[1];
    const float* ln1_g = (const float*)d_in[2];
    const float* ln1_b = (const float*)d_in[3];
    const float* ln2_g = (const float*)d_in[4];
    const float* ln2_b = (const float*)d_in[5];
    const float* Wq    = (const float*)d_in[6];
    const float* Wkv   = (const float*)d_in[7];
    const float* Wk    = (const float*)d_in[8];
    const float* Wv    = (const float*)d_in[9];
    const float* Wo    = (const float*)d_in[10];
    const float* Wg    = (const float*)d_in[11];
    const float* W1    = (const float*)d_in[12];
    const float* b1    = (const float*)d_in[13];
    const float* W2    = (const float*)d_in[14];
    const float* b2    = (const float*)d_in[15];
    const float* lnf_g = (const float*)d_in[16];
    const float* lnf_b = (const float*)d_in[17];
    const float* Wout  = (const float*)d_in[18];

    cudaFuncSetAttribute(gemm64_kernel,
                         cudaFuncAttributeMaxDynamicSharedMemorySize, SMEM64);
    cudaFuncSetAttribute(qkv1_kernel,
                         cudaFuncAttributeMaxDynamicSharedMemorySize, SMEM64);
    cudaFuncSetAttribute(kv2_kernel,
                         cudaFuncAttributeMaxDynamicSharedMemorySize, SMEM64);
    cudaFuncSetAttribute(moe1_kernel,
                         cudaFuncAttributeMaxDynamicSharedMemorySize, SMEM64);
    cudaFuncSetAttribute(moe2_kernel,
                         cudaFuncAttributeMaxDynamicSharedMemorySize, SMEM64);

    float *px, *ph, *pq, *pk, *pv, *plat, *pao, *phff, *pyff;
    cudaGetSymbolAddress((void**)&px,   g_x);
    cudaGetSymbolAddress((void**)&ph,   g_h);
    cudaGetSymbolAddress((void**)&pq,   g_q);
    cudaGetSymbolAddress((void**)&pk,   g_k);
    cudaGetSymbolAddress((void**)&pv,   g_v);
    cudaGetSymbolAddress((void**)&plat, g_lat);
    cudaGetSymbolAddress((void**)&pao,  g_ao);
    cudaGetSymbolAddress((void**)&phff, g_hff);
    cudaGetSymbolAddress((void**)&pyff, g_yff);

    embed_kernel<<<TB, 256>>>(ids, emb);

    for (int l = 0; l < NLAYER; l++) {
        // --- attention block ---
        ln_kernel<<<TB, 256>>>(px, ln1_g + l * DIM, ln1_b + l * DIM, ph);
        qkv1_kernel<<<dim3(15, TB / 128), 256, SMEM64>>>(
            ph, Wq + (size_t)l * DIM * DIM, Wkv + (size_t)l * DIM * DLAT, pq, plat);
        kv2_kernel<<<dim3(24, TB / 128), 256, SMEM64>>>(
            plat, Wk + (size_t)l * DLAT * DIM, Wv + (size_t)l * DLAT * DIM, pk, pv);
        rope_kernel<<<(TB * NH * 32 + 255) / 256, 256>>>();
        attn_kernel<<<(BATCH * NH * SEQ * 32 + 255) / 256, 256>>>();
        gemm64_kernel<<<dim3(DIM / 64, TB / 128), 256, SMEM64>>>(
            pao, Wo + (size_t)l * DIM * DIM, nullptr, px, TB, DIM, DIM, FLAG_ACC);

        // --- MoE block ---
        ln_kernel<<<TB, 256>>>(px, ln2_g + l * DIM, ln2_b + l * DIM, ph);
        gate_kernel<<<TB, 256>>>(Wg + (size_t)l * DIM * NE);
        zero_kernel<<<1, 32>>>();
        topk_kernel<<<TB / 256, 256>>>();
        scan_kernel<<<1, 1>>>();
        assign_kernel<<<TB / 256, 256>>>();
        moe1_kernel<<<dim3(DFF / 64, 2 * TB / 128, NE), 256, SMEM64>>>(
            ph, W1 + (size_t)l * NE * DIM * DFF, b1 + (size_t)l * NE * DFF, phff,
            DFF, DIM, FLAG_GELU);
        moe2_kernel<<<dim3(DIM / 64, 2 * TB / 128, NE), 256, SMEM64>>>(
            phff, W2 + (size_t)l * NE * DFF * DIM, b2 + (size_t)l * NE * DIM, pyff,
            DIM, DFF, 0);
        scatter_kernel<<<TB, 256>>>();
    }

    // --- final LN + LM head ---
    ln_kernel<<<TB, 256>>>(px, lnf_g, lnf_b, ph);
    gemm64_kernel<<<dim3(NV / 64, TB / 128), 256, SMEM64>>>(
        ph, Wout, nullptr, (float*)d_out, TB, NV, DIM, 0);
}

// round 8
// speedup vs baseline: 2.2437x; 1.1304x over previous
#include <cuda_runtime.h>
#include <cuda_bf16.h>
#include <math.h>
#include <stdint.h>

// ---------------- problem dims ----------------
#define TB 2048
#define SEQ 1024
#define BATCH 2
#define DIM 768
#define NH 12
#define HD 64
#define DLAT 192
#define DFF 3072
#define NE 8
#define NV 32000
#define NLAYER 2

#define FLAG_ACC 1
#define FLAG_GELU 2

typedef __nv_bfloat16 bf16;

// ---------------- fp32 scratch ----------------
__device__ float g_x[TB * DIM];
__device__ float g_h[TB * DIM];
__device__ float g_q[TB * DIM];
__device__ float g_k[TB * DIM];
__device__ float g_v[TB * DIM];
__device__ float g_yff[2 * TB * DIM];
__device__ float g_logits[TB * NE];
__device__ float g_tw[TB * 2];
__device__ int   g_te[TB * 2];
__device__ int   g_counts[NE];
__device__ int   g_offsets[NE];
__device__ int   g_cursor[NE];
__device__ int   g_rowtok[2 * TB];
__device__ float g_roww[2 * TB];
__device__ int   g_perm[2 * TB];

// ---------------- bf16 hi/lo activations ----------------
__device__ bf16 g_hh[TB * DIM],  g_hl[TB * DIM];
__device__ bf16 g_lath[TB * DLAT], g_latl[TB * DLAT];
__device__ bf16 g_aoh[TB * DIM], g_aol[TB * DIM];
__device__ bf16 g_hffh[2 * TB * DFF], g_hffl[2 * TB * DFF];

// ---------------- bf16 hi/lo weights ----------------
__device__ bf16 g_wqh[NLAYER * DIM * DIM],  g_wql[NLAYER * DIM * DIM];
__device__ bf16 g_wkvh[NLAYER * DIM * DLAT], g_wkvl[NLAYER * DIM * DLAT];
__device__ bf16 g_wkh[NLAYER * DLAT * DIM], g_wkl[NLAYER * DLAT * DIM];
__device__ bf16 g_wvh[NLAYER * DLAT * DIM], g_wvl[NLAYER * DLAT * DIM];
__device__ bf16 g_woh[NLAYER * DIM * DIM],  g_wol[NLAYER * DIM * DIM];
__device__ bf16 g_w1h[NLAYER * NE * DIM * DFF], g_w1l[NLAYER * NE * DIM * DFF];
__device__ bf16 g_w2h[NLAYER * NE * DFF * DIM], g_w2l[NLAYER * NE * DFF * DIM];
__device__ bf16 g_wouth[DIM * NV], g_woutl[DIM * NV];

// ---------------- helpers ----------------
__device__ __forceinline__ uint32_t smem_u32(const void* p) {
    uint32_t a;
    asm("{ .reg .u64 t; cvta.to.shared.u64 t, %1; cvt.u32.u64 %0, t; }" : "=r"(a) : "l"(p));
    return a;
}
__device__ __forceinline__ uint32_t pack_bf2(float a, float b) {
    __nv_bfloat162 h = __floats2bfloat162_rn(a, b);
    return *(uint32_t*)&h;
}
__device__ __forceinline__ void split_bf(float x, float& hi, float& lo) {
    bf16 h = __float2bfloat16_rn(x);
    hi = __bfloat162float(h);
    lo = x - hi;
}
__device__ __forceinline__ float gelu_f(float x) {
    const float k0 = 0.7978845608028654f;
    float x3 = x * x * x;
    return 0.5f * x * (1.0f + tanhf(k0 * (x + 0.044715f * x3)));
}
__device__ __forceinline__ void mma16(float d[4], const uint32_t a[4], const uint32_t b[2]) {
    asm volatile(
        "mma.sync.aligned.m16n8k16.row.col.f32.bf16.bf16.f32 "
        "{%0,%1,%2,%3},{%4,%5,%6,%7},{%8,%9},{%0,%1,%2,%3};"
        : "+f"(d[0]), "+f"(d[1]), "+f"(d[2]), "+f"(d[3])
        : "r"(a[0]), "r"(a[1]), "r"(a[2]), "r"(a[3]),
          "r"(b[0]), "r"(b[1]));
}
__device__ __forceinline__ void ldsm4(uint32_t r[4], uint32_t addr) {
    asm volatile("ldmatrix.sync.aligned.m8n8.x4.shared.b16 {%0,%1,%2,%3}, [%4];"
                 : "=r"(r[0]), "=r"(r[1]), "=r"(r[2]), "=r"(r[3]) : "r"(addr));
}
__device__ __forceinline__ void ldsm4t(uint32_t& r0, uint32_t& r1, uint32_t& r2,
                                       uint32_t& r3, uint32_t addr) {
    asm volatile("ldmatrix.sync.aligned.m8n8.x4.trans.shared.b16 {%0,%1,%2,%3}, [%4];"
                 : "=r"(r0), "=r"(r1), "=r"(r2), "=r"(r3) : "r"(addr));
}
__device__ __forceinline__ void cpa16(uint32_t dst, const void* src, int sz) {
    asm volatile("cp.async.cg.shared.global [%0], [%1], 16, %2;"
                 :: "r"(dst), "l"(src), "r"(sz) : "memory");
}
#define CP_COMMIT() asm volatile("cp.async.commit_group;" ::: "memory")
#define CP_WAIT1()  asm volatile("cp.async.wait_group 1;" ::: "memory")

// ---------------- weight fp32 -> bf16 hi/lo conversion ----------------
__global__ void wconv_kernel(const float* __restrict__ s, bf16* __restrict__ h,
                             bf16* __restrict__ l, int n4) {
    int i = blockIdx.x * blockDim.x + threadIdx.x;
    if (i >= n4) return;
    float4 v = ((const float4*)s)[i];
    float h0, l0, h1, l1, h2, l2, h3, l3;
    split_bf(v.x, h0, l0); split_bf(v.y, h1, l1);
    split_bf(v.z, h2, l2); split_bf(v.w, h3, l3);
    ((uint2*)h)[i] = make_uint2(pack_bf2(h0, h1), pack_bf2(h2, h3));
    ((uint2*)l)[i] = make_uint2(pack_bf2(l0, l1), pack_bf2(l2, l3));
}

// =====================================================================
//   bf16x3 mma.sync GEMM, cp.async 3-stage pipeline, ldmatrix(.trans)
// CTA tile 128x64, BK=32, 8 warps (4m x 2n), warp tile 32x32, 2 CTAs/SM.
// smem/stage: Ah 128x80B, Al, Bh 32x144B (k-major), Bl. Stage 29696B.
// =====================================================================
#define A_ROW_B 80
#define B_ROW_B 144
#define AL_B 10240
#define BH_B 20480
#define BL_B 25088
#define STAGE_B 29696
#define NSTAGE 3
#define GSMEM (STAGE_B * NSTAGE)

__device__ __forceinline__ void gemm_tile(
    const bf16* __restrict__ Ah, const bf16* __restrict__ Al,
    const int* __restrict__ Aidx,
    const bf16* __restrict__ Bh, const bf16* __restrict__ Bl,
    const float* __restrict__ bias,
    float* __restrict__ C, bf16* __restrict__ Chi, bf16* __restrict__ Clo,
    int Mv, int N, int K, int m0, int n0, int flags)
{
    extern __shared__ uint32_t smu[];
    const uint32_t sb0 = smem_u32(smu);
    int tid = threadIdx.x, lane = tid & 31, warp = tid >> 5;
    int wm = (warp >> 1) * 32, wn = (warp & 1) * 32;

    // loader mapping: A rows rA, rA+64 (4 chunks/row -> jA); B row kB chunk jB
    int jA = tid & 3, rA = tid >> 2;
    int kB = tid >> 3, jB = tid & 7;
    int gmr0 = m0 + rA, gmr1 = m0 + rA + 64;
    int szA0 = gmr0 < Mv ? 16 : 0;
    int szA1 = gmr1 < Mv ? 16 : 0;
    int row0 = gmr0 < Mv ? (Aidx ? Aidx[gmr0] : gmr0) : 0;
    int row1 = gmr1 < Mv ? (Aidx ? Aidx[gmr1] : gmr1) : 0;
    const bf16* pAh0 = Ah + (size_t)row0 * K + jA * 8;
    const bf16* pAl0 = Al + (size_t)row0 * K + jA * 8;
    const bf16* pAh1 = Ah + (size_t)row1 * K + jA * 8;
    const bf16* pAl1 = Al + (size_t)row1 * K + jA * 8;
    const bf16* pBh = Bh + (size_t)kB * N + n0 + jB * 8;
    const bf16* pBl = Bl + (size_t)kB * N + n0 + jB * 8;
    uint32_t dA0 = rA * A_ROW_B + jA * 16;
    uint32_t dA1 = dA0 + 64 * A_ROW_B;
    uint32_t dB  = kB * B_ROW_B + jB * 16;

    const int nk = K / 32;

    auto load_stage = [&](int c) {
        if (c < nk) {
            uint32_t st = sb0 + (c % NSTAGE) * STAGE_B;
            int kc = c * 32;
            size_t bo = (size_t)kc * N;
            cpa16(st + dA0, pAh0 + kc, szA0);
            cpa16(st + dA1, pAh1 + kc, szA1);
            cpa16(st + AL_B + dA0, pAl0 + kc, szA0);
            cpa16(st + AL_B + dA1, pAl1 + kc, szA1);
            cpa16(st + BH_B + dB, pBh + bo, 16);
            cpa16(st + BL_B + dB, pBl + bo, 16);
        }
        CP_COMMIT();
    };

    float acc[2][4][4] = {};

    load_stage(0);
    load_stage(1);

    // fragment address components
    uint32_t aAddr = (uint32_t)((wm + (lane & 15)) * A_ROW_B + ((lane >> 4) << 4));
    uint32_t bAddr = (uint32_t)(BH_B + (lane & 15) * B_ROW_B
                                + (wn + ((lane >> 4) << 3)) * 2);

    for (int c = 0; c < nk; c++) {
        CP_WAIT1();
        __syncthreads();
        load_stage(c + 2);

        uint32_t st = sb0 + (c % NSTAGE) * STAGE_B;
#pragma unroll
        for (int ss = 0; ss < 2; ss++) {
            uint32_t ah[2][4], al[2][4], bh[4][2], bl[4][2];
#pragma unroll
            for (int mt = 0; mt < 2; mt++) {
                uint32_t ao = st + aAddr + mt * 16 * A_ROW_B + ss * 32;
                ldsm4(ah[mt], ao);
                ldsm4(al[mt], ao + AL_B);
            }
#pragma unroll
            for (int ntp = 0; ntp < 2; ntp++) {
                uint32_t bo = st + bAddr + ss * 16 * B_ROW_B + ntp * 32;
                ldsm4t(bh[2 * ntp][0], bh[2 * ntp][1],
                       bh[2 * ntp + 1][0], bh[2 * ntp + 1][1], bo);
                ldsm4t(bl[2 * ntp][0], bl[2 * ntp][1],
                       bl[2 * ntp + 1][0], bl[2 * ntp + 1][1], bo + (BL_B - BH_B));
            }
#pragma unroll
            for (int mt = 0; mt < 2; mt++)
#pragma unroll
                for (int nt = 0; nt < 4; nt++) mma16(acc[mt][nt], ah[mt], bh[nt]);
#pragma unroll
            for (int mt = 0; mt < 2; mt++)
#pragma unroll
                for (int nt = 0; nt < 4; nt++) mma16(acc[mt][nt], ah[mt], bl[nt]);
#pragma unroll
            for (int mt = 0; mt < 2; mt++)
#pragma unroll
                for (int nt = 0; nt < 4; nt++) mma16(acc[mt][nt], al[mt], bh[nt]);
        }
    }

    // ---- epilogue ----
    int row = lane >> 2, cc = lane & 3;
#pragma unroll
    for (int mt = 0; mt < 2; mt++) {
#pragma unroll
        for (int h = 0; h < 2; h++) {
            int r = m0 + wm + mt * 16 + row + h * 8;
            if (r >= Mv) continue;
#pragma unroll
            for (int nt = 0; nt < 4; nt++) {
#pragma unroll
                for (int j = 0; j < 2; j++) {
                    int cn = n0 + wn + nt * 8 + cc * 2 + j;
                    float val = acc[mt][nt][h * 2 + j];
                    if (bias) val += bias[cn];
                    if (flags & FLAG_GELU) val = gelu_f(val);
                    size_t ix = (size_t)r * N + cn;
                    if (flags & FLAG_ACC) C[ix] += val;
                    else if (C) C[ix] = val;
                    if (Chi) {
                        bf16 hv = __float2bfloat16_rn(val);
                        Chi[ix] = hv;
                        Clo[ix] = __float2bfloat16_rn(val - __bfloat162float(hv));
                    }
                }
            }
        }
    }
}

// fused Wq (blocks 0..11 -> g_q fp32) + Wkv (12..14 -> lat hi/lo)
__global__ void __launch_bounds__(256, 2) qkv1_kernel(int l) {
    int bx = blockIdx.x;
    size_t wq = (size_t)l * DIM * DIM, wkv = (size_t)l * DIM * DLAT;
    if (bx < 12)
        gemm_tile(g_hh, g_hl, nullptr, g_wqh + wq, g_wql + wq, nullptr,
                  g_q, nullptr, nullptr, TB, DIM, DIM, blockIdx.y * 128, bx * 64, 0);
    else
        gemm_tile(g_hh, g_hl, nullptr, g_wkvh + wkv, g_wkvl + wkv, nullptr,
                  nullptr, g_lath, g_latl, TB, DLAT, DIM,
                  blockIdx.y * 128, (bx - 12) * 64, 0);
}

// fused Wk (0..11 -> g_k) + Wv (12..23 -> g_v); A = lat hi/lo
__global__ void __launch_bounds__(256, 2) kv2_kernel(int l) {
    int bx = blockIdx.x;
    size_t w = (size_t)l * DLAT * DIM;
    if (bx < 12)
        gemm_tile(g_lath, g_latl, nullptr, g_wkh + w, g_wkl + w, nullptr,
                  g_k, nullptr, nullptr, TB, DIM, DLAT, blockIdx.y * 128, bx * 64, 0);
    else
        gemm_tile(g_lath, g_latl, nullptr, g_wvh + w, g_wvl + w, nullptr,
                  g_v, nullptr, nullptr, TB, DIM, DLAT,
                  blockIdx.y * 128, (bx - 12) * 64, 0);
}

__global__ void __launch_bounds__(256, 2) wo_kernel(int l) {
    size_t w = (size_t)l * DIM * DIM;
    gemm_tile(g_aoh, g_aol, nullptr, g_woh + w, g_wol + w, nullptr,
              g_x, nullptr, nullptr, TB, DIM, DIM,
              blockIdx.y * 128, blockIdx.x * 64, FLAG_ACC);
}

__global__ void __launch_bounds__(256, 2) moe1_kernel(const float* __restrict__ b1, int l) {
    int e = blockIdx.z;
    int cnt = g_counts[e];
    int m0 = blockIdx.y * 128;
    if (m0 >= cnt) return;
    int off = g_offsets[e];
    size_t w = ((size_t)l * NE + e) * DIM * DFF;
    gemm_tile(g_hh, g_hl, g_rowtok + off, g_w1h + w, g_w1l + w,
              b1 + ((size_t)l * NE + e) * DFF,
              nullptr, g_hffh + (size_t)off * DFF, g_hffl + (size_t)off * DFF,
              cnt, DFF, DIM, m0, blockIdx.x * 64, FLAG_GELU);
}

__global__ void __launch_bounds__(256, 2) moe2_kernel(const float* __restrict__ b2, int l) {
    int e = blockIdx.z;
    int cnt = g_counts[e];
    int m0 = blockIdx.y * 128;
    if (m0 >= cnt) return;
    int off = g_offsets[e];
    size_t w = ((size_t)l * NE + e) * DFF * DIM;
    gemm_tile(g_hffh + (size_t)off * DFF, g_hffl + (size_t)off * DFF, nullptr,
              g_w2h + w, g_w2l + w, b2 + ((size_t)l * NE + e) * DIM,
              g_yff + (size_t)off * DIM, nullptr, nullptr,
              cnt, DIM, DFF, m0, blockIdx.x * 64, 0);
}

__global__ void __launch_bounds__(256, 2) lmhead_kernel(float* __restrict__ out) {
    gemm_tile(g_hh, g_hl, nullptr, g_wouth, g_woutl, nullptr,
              out, nullptr, nullptr, TB, NV, DIM,
              blockIdx.y * 128, blockIdx.x * 64, 0);
}

// ---------------- embedding gather ----------------
__global__ void embed_kernel(const int* __restrict__ ids, const float* __restrict__ emb) {
    int t = blockIdx.x;
    const float* src = emb + (size_t)ids[t] * DIM;
    for (int d = threadIdx.x; d < DIM; d += blockDim.x)
        g_x[t * DIM + d] = src[d];
}

// ---------------- layernorm: writes fp32 h + bf16 hi/lo ----------------
__global__ void ln_kernel(const float* __restrict__ x, const float* __restrict__ g,
                          const float* __restrict__ b) {
    int row = blockIdx.x;
    int t = threadIdx.x;
    const float* xr = x + (size_t)row * DIM;
    float v0 = xr[t], v1 = xr[t + 256], v2 = xr[t + 512];
    __shared__ float red[256];
    red[t] = v0 + v1 + v2;
    __syncthreads();
    for (int o = 128; o > 0; o >>= 1) { if (t < o) red[t] += red[t + o]; __syncthreads(); }
    float mean = red[0] * (1.0f / DIM);
    __syncthreads();
    float d0 = v0 - mean, d1 = v1 - mean, d2 = v2 - mean;
    red[t] = d0 * d0 + d1 * d1 + d2 * d2;
    __syncthreads();
    for (int o = 128; o > 0; o >>= 1) { if (t < o) red[t] += red[t + o]; __syncthreads(); }
    float rstd = rsqrtf(red[0] * (1.0f / DIM) + 1e-6f);
    size_t base = (size_t)row * DIM;
#pragma unroll
    for (int i = 0; i < 3; i++) {
        int d = t + i * 256;
        float dv = (i == 0 ? d0 : (i == 1 ? d1 : d2));
        float val = dv * rstd * g[d] + b[d];
        g_h[base + d] = val;
        float hi, lo;
        split_bf(val, hi, lo);
        g_hh[base + d] = __float2bfloat16_rn(hi);
        g_hl[base + d] = __float2bfloat16_rn(lo);
    }
}

// ---------------- RoPE on q and k (in place) ----------------
__global__ void rope_kernel() {
    int idx = blockIdx.x * blockDim.x + threadIdx.x;
    if (idx >= TB * NH * 32) return;
    int j = idx & 31;
    int h = (idx >> 5) % NH;
    int t = idx / (32 * NH);
    int s = t % SEQ;
    float inv = powf(10000.0f, -(float)j * (1.0f / 32.0f));
    float ang = (float)s * inv;
    float sn, cs;
    sincosf(ang, &sn, &cs);
    int base = t * DIM + h * HD;
    float a = g_q[base + j], b2 = g_q[base + 32 + j];
    g_q[base + j]      = a * cs - b2 * sn;
    g_q[base + 32 + j] = b2 * cs + a * sn;
    a = g_k[base + j]; b2 = g_k[base + 32 + j];
    g_k[base + j]      = a * cs - b2 * sn;
    g_k[base + 32 + j] = b2 * cs + a * sn;
}

// ---- attention: one warp per (b,h,q), 4 k-positions per iteration ----
// output written as bf16 hi/lo (consumed only by Wo GEMM)
__global__ void attn_kernel() {
    int gw = (blockIdx.x * blockDim.x + threadIdx.x) >> 5;
    int lane = threadIdx.x & 31;
    if (gw >= BATCH * NH * SEQ) return;
    int qi = gw % SEQ;
    int h = (gw / SEQ) % NH;
    int b = gw / (SEQ * NH);
    int t = b * SEQ + qi;
    int g = lane >> 3, j = lane & 7;

    const float* qp = g_q + (size_t)t * DIM + h * HD + j * 8;
    float ql[8];
#pragma unroll
    for (int i = 0; i < 8; i++) ql[i] = qp[i] * 0.125f;

    size_t base = (size_t)b * SEQ * DIM + h * HD;
    const float* kb = g_k + base;
    const float* vb = g_v + base;

    float m = -1e30f, l = 0.f, a0 = 0.f, a1 = 0.f;

    for (int s0 = 0; s0 <= qi; s0 += 4) {
        int s = s0 + g;
        int sc = s > qi ? qi : s;
        const float* kp = kb + (size_t)sc * DIM + j * 8;
        float4 k0 = *(const float4*)kp;
        float4 k1 = *(const float4*)(kp + 4);
        float d = ql[0] * k0.x + ql[1] * k0.y + ql[2] * k0.z + ql[3] * k0.w
                + ql[4] * k1.x + ql[5] * k1.y + ql[6] * k1.z + ql[7] * k1.w;
        d += __shfl_xor_sync(0xffffffffu, d, 1);
        d += __shfl_xor_sync(0xffffffffu, d, 2);
        d += __shfl_xor_sync(0xffffffffu, d, 4);
        if (s > qi) d = -1e30f;
        float d0 = __shfl_sync(0xffffffffu, d, j);
        float d1 = __shfl_sync(0xffffffffu, d, 8 + j);
        float d2 = __shfl_sync(0xffffffffu, d, 16 + j);
        float d3 = __shfl_sync(0xffffffffu, d, 24 + j);
        float mn = fmaxf(fmaxf(fmaxf(fmaxf(m, d0), d1), d2), d3);
        float corr = __expf(m - mn);
        float p0 = __expf(d0 - mn);
        float p1 = __expf(d1 - mn);
        float p2 = __expf(d2 - mn);
        float p3 = __expf(d3 - mn);
        int s1 = s0 + 1 > qi ? qi : s0 + 1;
        int s2 = s0 + 2 > qi ? qi : s0 + 2;
        int s3 = s0 + 3 > qi ? qi : s0 + 3;
        const float* v0p = vb + (size_t)s0 * DIM;
        const float* v1p = vb + (size_t)s1 * DIM;
        const float* v2p = vb + (size_t)s2 * DIM;
        const float* v3p = vb + (size_t)s3 * DIM;
        l  = l  * corr + (p0 + p1 + p2 + p3);
        a0 = a0 * corr + p0 * v0p[lane] + p1 * v1p[lane]
                       + p2 * v2p[lane] + p3 * v3p[lane];
        a1 = a1 * corr + p0 * v0p[lane + 32] + p1 * v1p[lane + 32]
                       + p2 * v2p[lane + 32] + p3 * v3p[lane + 32];
        m = mn;
    }
    float inv = 1.0f / l;
    float o0 = a0 * inv, o1 = a1 * inv;
    size_t ob = (size_t)t * DIM + h * HD;
    bf16 h0 = __float2bfloat16_rn(o0);
    bf16 h1 = __float2bfloat16_rn(o1);
    g_aoh[ob + lane] = h0;
    g_aol[ob + lane] = __float2bfloat16_rn(o0 - __bfloat162float(h0));
    g_aoh[ob + lane + 32] = h1;
    g_aol[ob + lane + 32] = __float2bfloat16_rn(o1 - __bfloat162float(h1));
}

// ---------------- MoE gate logits: warp per (token,expert) ------------------
__global__ void gate_kernel(const float* __restrict__ Wg) {
    int tok = blockIdx.x;
    int e = threadIdx.x >> 5;
    int lane = threadIdx.x & 31;
    const float* hr = g_h + (size_t)tok * DIM;
    float s = 0.f;
    for (int d = lane; d < DIM; d += 32) s += hr[d] * Wg[d * NE + e];
#pragma unroll
    for (int o = 16; o; o >>= 1) s += __shfl_xor_sync(0xffffffffu, s, o);
    if (lane == 0) g_logits[tok * NE + e] = s;
}

__global__ void zero_kernel() {
    if (threadIdx.x < NE) g_counts[threadIdx.x] = 0;
}

__global__ void topk_kernel() {
    int t = blockIdx.x * blockDim.x + threadIdx.x;
    if (t >= TB) return;
    float lg[NE];
    float m = -1e30f;
#pragma unroll
    for (int e = 0; e < NE; e++) { lg[e] = g_logits[t * NE + e]; m = fmaxf(m, lg[e]); }
    float ssum = 0.f;
#pragma unroll
    for (int e = 0; e < NE; e++) { lg[e] = expf(lg[e] - m); ssum += lg[e]; }
    int i0 = 0;
#pragma unroll
    for (int e = 1; e < NE; e++) if (lg[e] > lg[i0]) i0 = e;
    int i1 = (i0 == 0) ? 1 : 0;
#pragma unroll
    for (int e = 0; e < NE; e++) if (e != i0 && e != i1 && lg[e] > lg[i1]) i1 = e;
    float v0 = lg[i0] / ssum, v1 = lg[i1] / ssum;
    float winv = 1.0f / (v0 + v1);
    g_te[2 * t] = i0; g_te[2 * t + 1] = i1;
    g_tw[2 * t] = v0 * winv; g_tw[2 * t + 1] = v1 * winv;
    atomicAdd(&g_counts[i0], 1);
    atomicAdd(&g_counts[i1], 1);
}

__global__ void scan_kernel() {
    int acc = 0;
    for (int e = 0; e < NE; e++) {
        g_offsets[e] = acc;
        acc += g_counts[e];
        g_cursor[e] = 0;
    }
}

__global__ void assign_kernel() {
    int t = blockIdx.x * blockDim.x + threadIdx.x;
    if (t >= TB) return;
    for (int kk = 0; kk < 2; kk++) {
        int e = g_te[2 * t + kk];
        int pos = g_offsets[e] + atomicAdd(&g_cursor[e], 1);
        g_rowtok[pos] = t;
        g_roww[pos] = g_tw[2 * t + kk];
        g_perm[2 * t + kk] = pos;
    }
}

// x[t] += w0*yff[r0] + w1*yff[r1]
__global__ void scatter_kernel() {
    int t = blockIdx.x;
    int r0 = g_perm[2 * t], r1 = g_perm[2 * t + 1];
    float w0 = g_roww[r0], w1 = g_roww[r1];
    for (int d = threadIdx.x; d < DIM; d += blockDim.x)
        g_x[(size_t)t * DIM + d] += w0 * g_yff[(size_t)r0 * DIM + d]
                                  + w1 * g_yff[(size_t)r1 * DIM + d];
}

// ---------------- host orchestration ----------------
extern "C" void kernel_launch(void* const* d_in, const int* in_sizes, int n_in,
                              void* d_out, int out_size) {
    (void)in_sizes; (void)n_in; (void)out_size;
    const int*   ids   = (const int*)  d_in[0];
    const float* emb   = (const float*)d_in[1];
    const float* ln1_g = (const float*)d_in[2];
    const float* ln1_b = (const float*)d_in[3];
    const float* ln2_g = (const float*)d_in[4];
    const float* ln2_b = (const float*)d_in[5];
    const float* Wq    = (const float*)d_in[6];
    const float* Wkv   = (const float*)d_in[7];
    const float* Wk    = (const float*)d_in[8];
    const float* Wv    = (const float*)d_in[9];
    const float* Wo    = (const float*)d_in[10];
    const float* Wg    = (const float*)d_in[11];
    const float* W1    = (const float*)d_in[12];
    const float* b1    = (const float*)d_in[13];
    const float* W2    = (const float*)d_in[14];
    const float* b2    = (const float*)d_in[15];
    const float* lnf_g = (const float*)d_in[16];
    const float* lnf_b = (const float*)d_in[17];
    const float* Wout  = (const float*)d_in[18];

    cudaFuncSetAttribute(qkv1_kernel,  cudaFuncAttributeMaxDynamicSharedMemorySize, GSMEM);
    cudaFuncSetAttribute(kv2_kernel,   cudaFuncAttributeMaxDynamicSharedMemorySize, GSMEM);
    cudaFuncSetAttribute(wo_kernel,    cudaFuncAttributeMaxDynamicSharedMemorySize, GSMEM);
    cudaFuncSetAttribute(moe1_kernel,  cudaFuncAttributeMaxDynamicSharedMemorySize, GSMEM);
    cudaFuncSetAttribute(moe2_kernel,  cudaFuncAttributeMaxDynamicSharedMemorySize, GSMEM);
    cudaFuncSetAttribute(lmhead_kernel, cudaFuncAttributeMaxDynamicSharedMemorySize, GSMEM);

    // weight conversion destinations
    bf16 *wqh, *wql, *wkvh, *wkvl, *wkh, *wkl, *wvh, *wvl, *woh, *wol,
         *w1h, *w1l, *w2h, *w2l, *wouth, *woutl;
    cudaGetSymbolAddress((void**)&wqh,  g_wqh);  cudaGetSymbolAddress((void**)&wql,  g_wql);
    cudaGetSymbolAddress((void**)&wkvh, g_wkvh); cudaGetSymbolAddress((void**)&wkvl, g_wkvl);
    cudaGetSymbolAddress((void**)&wkh,  g_wkh);  cudaGetSymbolAddress((void**)&wkl,  g_wkl);
    cudaGetSymbolAddress((void**)&wvh,  g_wvh);  cudaGetSymbolAddress((void**)&wvl,  g_wvl);
    cudaGetSymbolAddress((void**)&woh,  g_woh);  cudaGetSymbolAddress((void**)&wol,  g_wol);
    cudaGetSymbolAddress((void**)&w1h,  g_w1h);  cudaGetSymbolAddress((void**)&w1l,  g_w1l);
    cudaGetSymbolAddress((void**)&w2h,  g_w2h);  cudaGetSymbolAddress((void**)&w2l,  g_w2l);
    cudaGetSymbolAddress((void**)&wouth, g_wouth); cudaGetSymbolAddress((void**)&woutl, g_woutl);

    float* px;
    cudaGetSymbolAddress((void**)&px, g_x);

    auto wc = [&](const float* s, bf16* h, bf16* l, size_t n) {
        int n4 = (int)(n / 4);
        wconv_kernel<<<(n4 + 255) / 256, 256>>>(s, h, l, n4);
    };
    wc(Wq,   wqh,  wql,  (size_t)NLAYER * DIM * DIM);
    wc(Wkv,  wkvh, wkvl, (size_t)NLAYER * DIM * DLAT);
    wc(Wk,   wkh,  wkl,  (size_t)NLAYER * DLAT * DIM);
    wc(Wv,   wvh,  wvl,  (size_t)NLAYER * DLAT * DIM);
    wc(Wo,   woh,  wol,  (size_t)NLAYER * DIM * DIM);
    wc(W1,   w1h,  w1l,  (size_t)NLAYER * NE * DIM * DFF);
    wc(W2,   w2h,  w2l,  (size_t)NLAYER * NE * DFF * DIM);
    wc(Wout, wouth, woutl, (size_t)DIM * NV);

    embed_kernel<<<TB, 256>>>(ids, emb);

    for (int l = 0; l < NLAYER; l++) {
        // --- attention block ---
        ln_kernel<<<TB, 256>>>(px, ln1_g + l * DIM, ln1_b + l * DIM);
        qkv1_kernel<<<dim3(15, TB / 128), 256, GSMEM>>>(l);
        kv2_kernel<<<dim3(24, TB / 128), 256, GSMEM>>>(l);
        rope_kernel<<<(TB * NH * 32 + 255) / 256, 256>>>();
        attn_kernel<<<(BATCH * NH * SEQ * 32 + 255) / 256, 256>>>();
        wo_kernel<<<dim3(DIM / 64, TB / 128), 256, GSMEM>>>(l);

        // --- MoE block ---
        ln_kernel<<<TB, 256>>>(px, ln2_g + l * DIM, ln2_b + l * DIM);
        gate_kernel<<<TB, 256>>>(Wg + (size_t)l * DIM * NE);
        zero_kernel<<<1, 32>>>();
        topk_kernel<<<TB / 256, 256>>>();
        scan_kernel<<<1, 1>>>();
        assign_kernel<<<TB / 256, 256>>>();
        moe1_kernel<<<dim3(DFF / 64, 2 * TB / 128, NE), 256, GSMEM>>>(b1, l);
        moe2_kernel<<<dim3(DIM / 64, 2 * TB / 128, NE), 256, GSMEM>>>(b2, l);
        scatter_kernel<<<TB, 256>>>();
    }

    // --- final LN + LM head ---
    ln_kernel<<<TB, 256>>>(px, lnf_g, lnf_b);
    lmhead_kernel<<<dim3(NV / 64, TB / 128), 256, GSMEM>>>((float*)d_out);
}

// round 9
// speedup vs baseline: 2.7964x; 1.2464x over previous
#include <cuda_runtime.h>
#include <cuda_bf16.h>
#include <math.h>
#include <stdint.h>

// ---------------- problem dims ----------------
#define TB 2048
#define SEQ 1024
#define BATCH 2
#define DIM 768
#define NH 12
#define HD 64
#define DLAT 192
#define DFF 3072
#define NE 8
#define NV 32000
#define NLAYER 2

#define FLAG_ACC 1
#define FLAG_GELU 2

typedef __nv_bfloat16 bf16;

// ---------------- fp32 scratch ----------------
__device__ float g_x[TB * DIM];
__device__ float g_h[TB * DIM];
__device__ float g_q[TB * DIM];
__device__ float g_k[TB * DIM];
__device__ float g_v[TB * DIM];
__device__ float g_yff[2 * TB * DIM];
__device__ float g_logits[TB * NE];
__device__ float g_tw[TB * 2];
__device__ int   g_te[TB * 2];
__device__ int   g_counts[NE];
__device__ int   g_offsets[NE];
__device__ int   g_cursor[NE];
__device__ int   g_rowtok[2 * TB];
__device__ float g_roww[2 * TB];
__device__ int   g_perm[2 * TB];

// ---------------- bf16 hi/lo activations ----------------
__device__ bf16 g_hh[TB * DIM],  g_hl[TB * DIM];
__device__ bf16 g_lath[TB * DLAT], g_latl[TB * DLAT];
__device__ bf16 g_aoh[TB * DIM], g_aol[TB * DIM];
__device__ bf16 g_hffh[2 * TB * DFF], g_hffl[2 * TB * DFF];

// ---------------- bf16 hi/lo weights ----------------
__device__ bf16 g_wqh[NLAYER * DIM * DIM],  g_wql[NLAYER * DIM * DIM];
__device__ bf16 g_wkvh[NLAYER * DIM * DLAT], g_wkvl[NLAYER * DIM * DLAT];
__device__ bf16 g_wkh[NLAYER * DLAT * DIM], g_wkl[NLAYER * DLAT * DIM];
__device__ bf16 g_wvh[NLAYER * DLAT * DIM], g_wvl[NLAYER * DLAT * DIM];
__device__ bf16 g_woh[NLAYER * DIM * DIM],  g_wol[NLAYER * DIM * DIM];
__device__ bf16 g_w1h[NLAYER * NE * DIM * DFF], g_w1l[NLAYER * NE * DIM * DFF];
__device__ bf16 g_w2h[NLAYER * NE * DFF * DIM], g_w2l[NLAYER * NE * DFF * DIM];
__device__ bf16 g_wouth[DIM * NV], g_woutl[DIM * NV];

// ---------------- helpers ----------------
__device__ __forceinline__ uint32_t smem_u32(const void* p) {
    uint32_t a;
    asm("{ .reg .u64 t; cvta.to.shared.u64 t, %1; cvt.u32.u64 %0, t; }" : "=r"(a) : "l"(p));
    return a;
}
__device__ __forceinline__ uint32_t pack_bf2(float a, float b) {
    __nv_bfloat162 h = __floats2bfloat162_rn(a, b);
    return *(uint32_t*)&h;
}
__device__ __forceinline__ void split_bf(float x, float& hi, float& lo) {
    bf16 h = __float2bfloat16_rn(x);
    hi = __bfloat162float(h);
    lo = x - hi;
}
__device__ __forceinline__ float gelu_f(float x) {
    const float k0 = 0.7978845608028654f;
    float x3 = x * x * x;
    return 0.5f * x * (1.0f + tanhf(k0 * (x + 0.044715f * x3)));
}
__device__ __forceinline__ void mma16(float d[4], const uint32_t a[4], const uint32_t b[2]) {
    asm volatile(
        "mma.sync.aligned.m16n8k16.row.col.f32.bf16.bf16.f32 "
        "{%0,%1,%2,%3},{%4,%5,%6,%7},{%8,%9},{%0,%1,%2,%3};"
        : "+f"(d[0]), "+f"(d[1]), "+f"(d[2]), "+f"(d[3])
        : "r"(a[0]), "r"(a[1]), "r"(a[2]), "r"(a[3]),
          "r"(b[0]), "r"(b[1]));
}
__device__ __forceinline__ void ldsm4(uint32_t r[4], uint32_t addr) {
    asm volatile("ldmatrix.sync.aligned.m8n8.x4.shared.b16 {%0,%1,%2,%3}, [%4];"
                 : "=r"(r[0]), "=r"(r[1]), "=r"(r[2]), "=r"(r[3]) : "r"(addr));
}
__device__ __forceinline__ void ldsm4t(uint32_t& r0, uint32_t& r1, uint32_t& r2,
                                       uint32_t& r3, uint32_t addr) {
    asm volatile("ldmatrix.sync.aligned.m8n8.x4.trans.shared.b16 {%0,%1,%2,%3}, [%4];"
                 : "=r"(r0), "=r"(r1), "=r"(r2), "=r"(r3) : "r"(addr));
}
__device__ __forceinline__ void cpa16(uint32_t dst, const void* src, int sz) {
    asm volatile("cp.async.cg.shared.global [%0], [%1], 16, %2;"
                 :: "r"(dst), "l"(src), "r"(sz) : "memory");
}
__device__ __forceinline__ void cpa16f(uint32_t dst, const void* src) {
    asm volatile("cp.async.cg.shared.global [%0], [%1], 16;"
                 :: "r"(dst), "l"(src) : "memory");
}
#define CP_COMMIT() asm volatile("cp.async.commit_group;" ::: "memory")
#define CP_WAIT1()  asm volatile("cp.async.wait_group 1;" ::: "memory")
#define CP_WAIT0()  asm volatile("cp.async.wait_group 0;" ::: "memory")

// ---------------- weight fp32 -> bf16 hi/lo conversion ----------------
__global__ void wconv_kernel(const float* __restrict__ s, bf16* __restrict__ h,
                             bf16* __restrict__ l, int n4) {
    int i = blockIdx.x * blockDim.x + threadIdx.x;
    if (i >= n4) return;
    float4 v = ((const float4*)s)[i];
    float h0, l0, h1, l1, h2, l2, h3, l3;
    split_bf(v.x, h0, l0); split_bf(v.y, h1, l1);
    split_bf(v.z, h2, l2); split_bf(v.w, h3, l3);
    ((uint2*)h)[i] = make_uint2(pack_bf2(h0, h1), pack_bf2(h2, h3));
    ((uint2*)l)[i] = make_uint2(pack_bf2(l0, l1), pack_bf2(l2, l3));
}

// =====================================================================
//   bf16x3 mma.sync GEMM, cp.async 3-stage pipeline, ldmatrix(.trans)
// =====================================================================
#define A_ROW_B 80
#define B_ROW_B 144
#define AL_B 10240
#define BH_B 20480
#define BL_B 25088
#define STAGE_B 29696
#define NSTAGE 3
#define GSMEM (STAGE_B * NSTAGE)

__device__ __forceinline__ void gemm_tile(
    const bf16* __restrict__ Ah, const bf16* __restrict__ Al,
    const int* __restrict__ Aidx,
    const bf16* __restrict__ Bh, const bf16* __restrict__ Bl,
    const float* __restrict__ bias,
    float* __restrict__ C, bf16* __restrict__ Chi, bf16* __restrict__ Clo,
    int Mv, int N, int K, int m0, int n0, int flags)
{
    extern __shared__ uint32_t smu[];
    const uint32_t sb0 = smem_u32(smu);
    int tid = threadIdx.x, lane = tid & 31, warp = tid >> 5;
    int wm = (warp >> 1) * 32, wn = (warp & 1) * 32;

    int jA = tid & 3, rA = tid >> 2;
    int kB = tid >> 3, jB = tid & 7;
    int gmr0 = m0 + rA, gmr1 = m0 + rA + 64;
    int szA0 = gmr0 < Mv ? 16 : 0;
    int szA1 = gmr1 < Mv ? 16 : 0;
    int row0 = gmr0 < Mv ? (Aidx ? Aidx[gmr0] : gmr0) : 0;
    int row1 = gmr1 < Mv ? (Aidx ? Aidx[gmr1] : gmr1) : 0;
    const bf16* pAh0 = Ah + (size_t)row0 * K + jA * 8;
    const bf16* pAl0 = Al + (size_t)row0 * K + jA * 8;
    const bf16* pAh1 = Ah + (size_t)row1 * K + jA * 8;
    const bf16* pAl1 = Al + (size_t)row1 * K + jA * 8;
    const bf16* pBh = Bh + (size_t)kB * N + n0 + jB * 8;
    const bf16* pBl = Bl + (size_t)kB * N + n0 + jB * 8;
    uint32_t dA0 = rA * A_ROW_B + jA * 16;
    uint32_t dA1 = dA0 + 64 * A_ROW_B;
    uint32_t dB  = kB * B_ROW_B + jB * 16;

    const int nk = K / 32;

    auto load_stage = [&](int c) {
        if (c < nk) {
            uint32_t st = sb0 + (c % NSTAGE) * STAGE_B;
            int kc = c * 32;
            size_t bo = (size_t)kc * N;
            cpa16(st + dA0, pAh0 + kc, szA0);
            cpa16(st + dA1, pAh1 + kc, szA1);
            cpa16(st + AL_B + dA0, pAl0 + kc, szA0);
            cpa16(st + AL_B + dA1, pAl1 + kc, szA1);
            cpa16(st + BH_B + dB, pBh + bo, 16);
            cpa16(st + BL_B + dB, pBl + bo, 16);
        }
        CP_COMMIT();
    };

    float acc[2][4][4] = {};

    load_stage(0);
    load_stage(1);

    uint32_t aAddr = (uint32_t)((wm + (lane & 15)) * A_ROW_B + ((lane >> 4) << 4));
    uint32_t bAddr = (uint32_t)(BH_B + (lane & 15) * B_ROW_B
                                + (wn + ((lane >> 4) << 3)) * 2);

    for (int c = 0; c < nk; c++) {
        CP_WAIT1();
        __syncthreads();
        load_stage(c + 2);

        uint32_t st = sb0 + (c % NSTAGE) * STAGE_B;
#pragma unroll
        for (int ss = 0; ss < 2; ss++) {
            uint32_t ah[2][4], al[2][4], bh[4][2], bl[4][2];
#pragma unroll
            for (int mt = 0; mt < 2; mt++) {
                uint32_t ao = st + aAddr + mt * 16 * A_ROW_B + ss * 32;
                ldsm4(ah[mt], ao);
                ldsm4(al[mt], ao + AL_B);
            }
#pragma unroll
            for (int ntp = 0; ntp < 2; ntp++) {
                uint32_t bo = st + bAddr + ss * 16 * B_ROW_B + ntp * 32;
                ldsm4t(bh[2 * ntp][0], bh[2 * ntp][1],
                       bh[2 * ntp + 1][0], bh[2 * ntp + 1][1], bo);
                ldsm4t(bl[2 * ntp][0], bl[2 * ntp][1],
                       bl[2 * ntp + 1][0], bl[2 * ntp + 1][1], bo + (BL_B - BH_B));
            }
#pragma unroll
            for (int mt = 0; mt < 2; mt++)
#pragma unroll
                for (int nt = 0; nt < 4; nt++) mma16(acc[mt][nt], ah[mt], bh[nt]);
#pragma unroll
            for (int mt = 0; mt < 2; mt++)
#pragma unroll
                for (int nt = 0; nt < 4; nt++) mma16(acc[mt][nt], ah[mt], bl[nt]);
#pragma unroll
            for (int mt = 0; mt < 2; mt++)
#pragma unroll
                for (int nt = 0; nt < 4; nt++) mma16(acc[mt][nt], al[mt], bh[nt]);
        }
    }

    int row = lane >> 2, cc = lane & 3;
#pragma unroll
    for (int mt = 0; mt < 2; mt++) {
#pragma unroll
        for (int h = 0; h < 2; h++) {
            int r = m0 + wm + mt * 16 + row + h * 8;
            if (r >= Mv) continue;
#pragma unroll
            for (int nt = 0; nt < 4; nt++) {
#pragma unroll
                for (int j = 0; j < 2; j++) {
                    int cn = n0 + wn + nt * 8 + cc * 2 + j;
                    float val = acc[mt][nt][h * 2 + j];
                    if (bias) val += bias[cn];
                    if (flags & FLAG_GELU) val = gelu_f(val);
                    size_t ix = (size_t)r * N + cn;
                    if (flags & FLAG_ACC) C[ix] += val;
                    else if (C) C[ix] = val;
                    if (Chi) {
                        bf16 hv = __float2bfloat16_rn(val);
                        Chi[ix] = hv;
                        Clo[ix] = __float2bfloat16_rn(val - __bfloat162float(hv));
                    }
                }
            }
        }
    }
}

__global__ void __launch_bounds__(256, 2) qkv1_kernel(int l) {
    int bx = blockIdx.x;
    size_t wq = (size_t)l * DIM * DIM, wkv = (size_t)l * DIM * DLAT;
    if (bx < 12)
        gemm_tile(g_hh, g_hl, nullptr, g_wqh + wq, g_wql + wq, nullptr,
                  g_q, nullptr, nullptr, TB, DIM, DIM, blockIdx.y * 128, bx * 64, 0);
    else
        gemm_tile(g_hh, g_hl, nullptr, g_wkvh + wkv, g_wkvl + wkv, nullptr,
                  nullptr, g_lath, g_latl, TB, DLAT, DIM,
                  blockIdx.y * 128, (bx - 12) * 64, 0);
}

__global__ void __launch_bounds__(256, 2) kv2_kernel(int l) {
    int bx = blockIdx.x;
    size_t w = (size_t)l * DLAT * DIM;
    if (bx < 12)
        gemm_tile(g_lath, g_latl, nullptr, g_wkh + w, g_wkl + w, nullptr,
                  g_k, nullptr, nullptr, TB, DIM, DLAT, blockIdx.y * 128, bx * 64, 0);
    else
        gemm_tile(g_lath, g_latl, nullptr, g_wvh + w, g_wvl + w, nullptr,
                  g_v, nullptr, nullptr, TB, DIM, DLAT,
                  blockIdx.y * 128, (bx - 12) * 64, 0);
}

__global__ void __launch_bounds__(256, 2) wo_kernel(int l) {
    size_t w = (size_t)l * DIM * DIM;
    gemm_tile(g_aoh, g_aol, nullptr, g_woh + w, g_wol + w, nullptr,
              g_x, nullptr, nullptr, TB, DIM, DIM,
              blockIdx.y * 128, blockIdx.x * 64, FLAG_ACC);
}

__global__ void __launch_bounds__(256, 2) moe1_kernel(const float* __restrict__ b1, int l) {
    int e = blockIdx.z;
    int cnt = g_counts[e];
    int m0 = blockIdx.y * 128;
    if (m0 >= cnt) return;
    int off = g_offsets[e];
    size_t w = ((size_t)l * NE + e) * DIM * DFF;
    gemm_tile(g_hh, g_hl, g_rowtok + off, g_w1h + w, g_w1l + w,
              b1 + ((size_t)l * NE + e) * DFF,
              nullptr, g_hffh + (size_t)off * DFF, g_hffl + (size_t)off * DFF,
              cnt, DFF, DIM, m0, blockIdx.x * 64, FLAG_GELU);
}

__global__ void __launch_bounds__(256, 2) moe2_kernel(const float* __restrict__ b2, int l) {
    int e = blockIdx.z;
    int cnt = g_counts[e];
    int m0 = blockIdx.y * 128;
    if (m0 >= cnt) return;
    int off = g_offsets[e];
    size_t w = ((size_t)l * NE + e) * DFF * DIM;
    gemm_tile(g_hffh + (size_t)off * DFF, g_hffl + (size_t)off * DFF, nullptr,
              g_w2h + w, g_w2l + w, b2 + ((size_t)l * NE + e) * DIM,
              g_yff + (size_t)off * DIM, nullptr, nullptr,
              cnt, DIM, DFF, m0, blockIdx.x * 64, 0);
}

__global__ void __launch_bounds__(256, 2) lmhead_kernel(float* __restrict__ out) {
    gemm_tile(g_hh, g_hl, nullptr, g_wouth, g_woutl, nullptr,
              out, nullptr, nullptr, TB, NV, DIM,
              blockIdx.y * 128, blockIdx.x * 64, 0);
}

// ---------------- embedding gather ----------------
__global__ void embed_kernel(const int* __restrict__ ids, const float* __restrict__ emb) {
    int t = blockIdx.x;
    const float* src = emb + (size_t)ids[t] * DIM;
    for (int d = threadIdx.x; d < DIM; d += blockDim.x)
        g_x[t * DIM + d] = src[d];
}

// ---------------- layernorm ----------------
__global__ void ln_kernel(const float* __restrict__ x, const float* __restrict__ g,
                          const float* __restrict__ b) {
    int row = blockIdx.x;
    int t = threadIdx.x;
    const float* xr = x + (size_t)row * DIM;
    float v0 = xr[t], v1 = xr[t + 256], v2 = xr[t + 512];
    __shared__ float red[256];
    red[t] = v0 + v1 + v2;
    __syncthreads();
    for (int o = 128; o > 0; o >>= 1) { if (t < o) red[t] += red[t + o]; __syncthreads(); }
    float mean = red[0] * (1.0f / DIM);
    __syncthreads();
    float d0 = v0 - mean, d1 = v1 - mean, d2 = v2 - mean;
    red[t] = d0 * d0 + d1 * d1 + d2 * d2;
    __syncthreads();
    for (int o = 128; o > 0; o >>= 1) { if (t < o) red[t] += red[t + o]; __syncthreads(); }
    float rstd = rsqrtf(red[0] * (1.0f / DIM) + 1e-6f);
    size_t base = (size_t)row * DIM;
#pragma unroll
    for (int i = 0; i < 3; i++) {
        int d = t + i * 256;
        float dv = (i == 0 ? d0 : (i == 1 ? d1 : d2));
        float val = dv * rstd * g[d] + b[d];
        g_h[base + d] = val;
        float hi, lo;
        split_bf(val, hi, lo);
        g_hh[base + d] = __float2bfloat16_rn(hi);
        g_hl[base + d] = __float2bfloat16_rn(lo);
    }
}

// ---------------- RoPE on q and k (in place) ----------------
__global__ void rope_kernel() {
    int idx = blockIdx.x * blockDim.x + threadIdx.x;
    if (idx >= TB * NH * 32) return;
    int j = idx & 31;
    int h = (idx >> 5) % NH;
    int t = idx / (32 * NH);
    int s = t % SEQ;
    // 10000^(-j/32) = exp2(-j * log2(10000)/32)
    float inv = exp2f(-(float)j * 0.41524101186092029f);
    float ang = (float)s * inv;
    float sn, cs;
    sincosf(ang, &sn, &cs);
    int base = t * DIM + h * HD;
    float a = g_q[base + j], b2 = g_q[base + 32 + j];
    g_q[base + j]      = a * cs - b2 * sn;
    g_q[base + 32 + j] = b2 * cs + a * sn;
    a = g_k[base + j]; b2 = g_k[base + 32 + j];
    g_k[base + j]      = a * cs - b2 * sn;
    g_k[base + 32 + j] = b2 * cs + a * sn;
}

// =====================================================================
//  flash attention (fp32, smem-tiled): CTA = (b,h, 64-query block),
//  8 warps x 8 queries; K/V streamed in 32-key tiles via cp.async
//  double-buffer. lanes=keys for scores, lanes=dims for AV (shfl probs).
// =====================================================================
#define AQ 64            // queries per CTA
#define AKT 32           // keys per tile
#define KVS 68           // K/V smem row stride in floats (272B, 16B-aligned)
#define AQS_F (AQ * HD)                 // 4096 floats
#define KVBUF_F (AKT * KVS)             // 2176 floats per matrix
#define KVSTG_F (2 * KVBUF_F)           // K+V per buffer
#define ASMEM ((AQS_F + 2 * KVSTG_F) * 4)   // 51200 B

__global__ void __launch_bounds__(256, 2) attn_kernel() {
    extern __shared__ float sm[];
    float* Qs = sm;                       // [64][64]
    float* KV = sm + AQS_F;               // [2][K:2176 | V:2176]
    const uint32_t kvu = smem_u32(KV);

    int tid = threadIdx.x, lane = tid & 31, w = tid >> 5;
    int qb = 15 - blockIdx.x;             // heavy blocks first
    int bh = blockIdx.y;
    int b = bh / NH, h = bh % NH;
    int q0 = qb * AQ;                     // first query of block
    size_t kvbase = ((size_t)b * SEQ) * DIM + h * HD;

    // ---- load Q block (scaled) into smem ----
    {
        const float* qsrc = g_q + ((size_t)(b * SEQ + q0)) * DIM + h * HD;
#pragma unroll
        for (int i = 0; i < 4; i++) {
            int e4 = tid + i * 256;       // 1024 float4 total
            int r = e4 >> 4, dq = (e4 & 15) * 4;
            float4 v = *(const float4*)(qsrc + (size_t)r * DIM + dq);
            v.x *= 0.125f; v.y *= 0.125f; v.z *= 0.125f; v.w *= 0.125f;
            *(float4*)(Qs + r * HD + dq) = v;
        }
    }

    const int nt = 2 * qb + 2;            // key tiles needed (causal)

    // cp.async tile loader: K rows + V rows, natural layout, stride KVS
    int lrow = tid >> 3, loff = (tid & 7) * 2;   // 32 rows x 8 chunks(16B) x2 halves? => 64 floats = 16 chunks
    // each thread loads 2 chunks of K and 2 of V: chunks c = tid, tid+256 over 512
    auto load_tile = [&](int t) {
        uint32_t dstb = kvu + (t & 1) * (KVSTG_F * 4);
#pragma unroll
        for (int i = 0; i < 2; i++) {
            int c = tid + i * 256;        // 0..511
            int r = c >> 4, of = (c & 15) * 4;
            size_t src = kvbase + (size_t)(t * AKT + r) * DIM + of;
            uint32_t d = dstb + (r * KVS + of) * 4;
            cpa16f(d, g_k + src);
            cpa16f(d + KVBUF_F * 4, g_v + src);
        }
        CP_COMMIT();
    };

    float m[8], l[8], a0[8], a1[8], sc[8];
#pragma unroll
    for (int q = 0; q < 8; q++) { m[q] = -1e30f; l[q] = 0.f; a0[q] = 0.f; a1[q] = 0.f; }

    const float* qsw = Qs + (w * 8) * HD;
    int qg0 = q0 + w * 8;                 // first query of this warp

    load_tile(0);

    for (int t = 0; t < nt; t++) {
        if (t + 1 < nt) load_tile(t + 1); else CP_COMMIT();
        CP_WAIT1();
        __syncthreads();

        const float* Ksb = KV + (t & 1) * KVSTG_F;
        const float* Vsb = Ksb + KVBUF_F;

        // ---- scores: lanes = keys ----
#pragma unroll
        for (int q = 0; q < 8; q++) sc[q] = 0.f;
#pragma unroll
        for (int dq = 0; dq < 16; dq++) {
            float4 kv = *(const float4*)(Ksb + lane * KVS + dq * 4);
#pragma unroll
            for (int q = 0; q < 8; q++) {
                float4 qv = *(const float4*)(qsw + q * HD + dq * 4);
                sc[q] += qv.x * kv.x + qv.y * kv.y + qv.z * kv.z + qv.w * kv.w;
            }
        }
        // causal mask (only possibly-diagonal tiles)
        if (t >= nt - 2) {
            int kg = t * AKT + lane;
#pragma unroll
            for (int q = 0; q < 8; q++)
                if (kg > qg0 + q) sc[q] = -1e30f;
        }

        // ---- online softmax per query ----
#pragma unroll
        for (int q = 0; q < 8; q++) {
            float tm = sc[q];
#pragma unroll
            for (int o = 16; o; o >>= 1) tm = fmaxf(tm, __shfl_xor_sync(0xffffffffu, tm, o));
            float mn = fmaxf(m[q], tm);
            float corr = __expf(m[q] - mn);
            float p = __expf(sc[q] - mn);
            float ps = p;
#pragma unroll
            for (int o = 16; o; o >>= 1) ps += __shfl_xor_sync(0xffffffffu, ps, o);
            l[q] = l[q] * corr + ps;
            m[q] = mn;
            a0[q] *= corr;
            a1[q] *= corr;
            sc[q] = p;                    // reuse as prob
        }

        // ---- AV: lanes = dims; probs broadcast via shfl ----
#pragma unroll
        for (int kk = 0; kk < AKT; kk++) {
            float v0 = Vsb[kk * KVS + lane];
            float v1 = Vsb[kk * KVS + lane + 32];
#pragma unroll
            for (int q = 0; q < 8; q++) {
                float pq = __shfl_sync(0xffffffffu, sc[q], kk);
                a0[q] += pq * v0;
                a1[q] += pq * v1;
            }
        }
        __syncthreads();
    }

    // ---- output (bf16 hi/lo for Wo GEMM) ----
#pragma unroll
    for (int q = 0; q < 8; q++) {
        float inv = 1.0f / l[q];
        float o0 = a0[q] * inv, o1 = a1[q] * inv;
        size_t ob = ((size_t)(b * SEQ + qg0 + q)) * DIM + h * HD;
        bf16 h0 = __float2bfloat16_rn(o0);
        bf16 h1 = __float2bfloat16_rn(o1);
        g_aoh[ob + lane] = h0;
        g_aol[ob + lane] = __float2bfloat16_rn(o0 - __bfloat162float(h0));
        g_aoh[ob + lane + 32] = h1;
        g_aol[ob + lane + 32] = __float2bfloat16_rn(o1 - __bfloat162float(h1));
    }
}

// ---------------- MoE gate logits: warp per (token,expert) ------------------
__global__ void gate_kernel(const float* __restrict__ Wg) {
    int tok = blockIdx.x;
    int e = threadIdx.x >> 5;
    int lane = threadIdx.x & 31;
    const float* hr = g_h + (size_t)tok * DIM;
    float s = 0.f;
    for (int d = lane; d < DIM; d += 32) s += hr[d] * Wg[d * NE + e];
#pragma unroll
    for (int o = 16; o; o >>= 1) s += __shfl_xor_sync(0xffffffffu, s, o);
    if (lane == 0) g_logits[tok * NE + e] = s;
}

__global__ void zero_kernel() {
    if (threadIdx.x < NE) g_counts[threadIdx.x] = 0;
}

__global__ void topk_kernel() {
    int t = blockIdx.x * blockDim.x + threadIdx.x;
    if (t >= TB) return;
    float lg[NE];
    float m = -1e30f;
#pragma unroll
    for (int e = 0; e < NE; e++) { lg[e] = g_logits[t * NE + e]; m = fmaxf(m, lg[e]); }
    float ssum = 0.f;
#pragma unroll
    for (int e = 0; e < NE; e++) { lg[e] = expf(lg[e] - m); ssum += lg[e]; }
    int i0 = 0;
#pragma unroll
    for (int e = 1; e < NE; e++) if (lg[e] > lg[i0]) i0 = e;
    int i1 = (i0 == 0) ? 1 : 0;
#pragma unroll
    for (int e = 0; e < NE; e++) if (e != i0 && e != i1 && lg[e] > lg[i1]) i1 = e;
    float v0 = lg[i0] / ssum, v1 = lg[i1] / ssum;
    float winv = 1.0f / (v0 + v1);
    g_te[2 * t] = i0; g_te[2 * t + 1] = i1;
    g_tw[2 * t] = v0 * winv; g_tw[2 * t + 1] = v1 * winv;
    atomicAdd(&g_counts[i0], 1);
    atomicAdd(&g_counts[i1], 1);
}

__global__ void scan_kernel() {
    int acc = 0;
    for (int e = 0; e < NE; e++) {
        g_offsets[e] = acc;
        acc += g_counts[e];
        g_cursor[e] = 0;
    }
}

__global__ void assign_kernel() {
    int t = blockIdx.x * blockDim.x + threadIdx.x;
    if (t >= TB) return;
    for (int kk = 0; kk < 2; kk++) {
        int e = g_te[2 * t + kk];
        int pos = g_offsets[e] + atomicAdd(&g_cursor[e], 1);
        g_rowtok[pos] = t;
        g_roww[pos] = g_tw[2 * t + kk];
        g_perm[2 * t + kk] = pos;
    }
}

__global__ void scatter_kernel() {
    int t = blockIdx.x;
    int r0 = g_perm[2 * t], r1 = g_perm[2 * t + 1];
    float w0 = g_roww[r0], w1 = g_roww[r1];
    for (int d = threadIdx.x; d < DIM; d += blockDim.x)
        g_x[(size_t)t * DIM + d] += w0 * g_yff[(size_t)r0 * DIM + d]
                                  + w1 * g_yff[(size_t)r1 * DIM + d];
}

// ---------------- host orchestration ----------------
extern "C" void kernel_launch(void* const* d_in, const int* in_sizes, int n_in,
                              void* d_out, int out_size) {
    (void)in_sizes; (void)n_in; (void)out_size;
    const int*   ids   = (const int*)  d_in[0];
    const float* emb   = (const float*)d_in[1];
    const float* ln1_g = (const float*)d_in[2];
    const float* ln1_b = (const float*)d_in[3];
    const float* ln2_g = (const float*)d_in[4];
    const float* ln2_b = (const float*)d_in[5];
    const float* Wq    = (const float*)d_in[6];
    const float* Wkv   = (const float*)d_in[7];
    const float* Wk    = (const float*)d_in[8];
    const float* Wv    = (const float*)d_in[9];
    const float* Wo    = (const float*)d_in[10];
    const float* Wg    = (const float*)d_in[11];
    const float* W1    = (const float*)d_in[12];
    const float* b1    = (const float*)d_in[13];
    const float* W2    = (const float*)d_in[14];
    const float* b2    = (const float*)d_in[15];
    const float* lnf_g = (const float*)d_in[16];
    const float* lnf_b = (const float*)d_in[17];
    const float* Wout  = (const float*)d_in[18];

    cudaFuncSetAttribute(qkv1_kernel,  cudaFuncAttributeMaxDynamicSharedMemorySize, GSMEM);
    cudaFuncSetAttribute(kv2_kernel,   cudaFuncAttributeMaxDynamicSharedMemorySize, GSMEM);
    cudaFuncSetAttribute(wo_kernel,    cudaFuncAttributeMaxDynamicSharedMemorySize, GSMEM);
    cudaFuncSetAttribute(moe1_kernel,  cudaFuncAttributeMaxDynamicSharedMemorySize, GSMEM);
    cudaFuncSetAttribute(moe2_kernel,  cudaFuncAttributeMaxDynamicSharedMemorySize, GSMEM);
    cudaFuncSetAttribute(lmhead_kernel, cudaFuncAttributeMaxDynamicSharedMemorySize, GSMEM);
    cudaFuncSetAttribute(attn_kernel,  cudaFuncAttributeMaxDynamicSharedMemorySize, ASMEM);

    bf16 *wqh, *wql, *wkvh, *wkvl, *wkh, *wkl, *wvh, *wvl, *woh, *wol,
         *w1h, *w1l, *w2h, *w2l, *wouth, *woutl;
    cudaGetSymbolAddress((void**)&wqh,  g_wqh);  cudaGetSymbolAddress((void**)&wql,  g_wql);
    cudaGetSymbolAddress((void**)&wkvh, g_wkvh); cudaGetSymbolAddress((void**)&wkvl, g_wkvl);
    cudaGetSymbolAddress((void**)&wkh,  g_wkh);  cudaGetSymbolAddress((void**)&wkl,  g_wkl);
    cudaGetSymbolAddress((void**)&wvh,  g_wvh);  cudaGetSymbolAddress((void**)&wvl,  g_wvl);
    cudaGetSymbolAddress((void**)&woh,  g_woh);  cudaGetSymbolAddress((void**)&wol,  g_wol);
    cudaGetSymbolAddress((void**)&w1h,  g_w1h);  cudaGetSymbolAddress((void**)&w1l,  g_w1l);
    cudaGetSymbolAddress((void**)&w2h,  g_w2h);  cudaGetSymbolAddress((void**)&w2l,  g_w2l);
    cudaGetSymbolAddress((void**)&wouth, g_wouth); cudaGetSymbolAddress((void**)&woutl, g_woutl);

    float* px;
    cudaGetSymbolAddress((void**)&px, g_x);

    auto wc = [&](const float* s, bf16* h, bf16* l, size_t n) {
        int n4 = (int)(n / 4);
        wconv_kernel<<<(n4 + 255) / 256, 256>>>(s, h, l, n4);
    };
    wc(Wq,   wqh,  wql,  (size_t)NLAYER * DIM * DIM);
    wc(Wkv,  wkvh, wkvl, (size_t)NLAYER * DIM * DLAT);
    wc(Wk,   wkh,  wkl,  (size_t)NLAYER * DLAT * DIM);
    wc(Wv,   wvh,  wvl,  (size_t)NLAYER * DLAT * DIM);
    wc(Wo,   woh,  wol,  (size_t)NLAYER * DIM * DIM);
    wc(W1,   w1h,  w1l,  (size_t)NLAYER * NE * DIM * DFF);
    wc(W2,   w2h,  w2l,  (size_t)NLAYER * NE * DFF * DIM);
    wc(Wout, wouth, woutl, (size_t)DIM * NV);

    embed_kernel<<<TB, 256>>>(ids, emb);

    for (int l = 0; l < NLAYER; l++) {
        // --- attention block ---
        ln_kernel<<<TB, 256>>>(px, ln1_g + l * DIM, ln1_b + l * DIM);
        qkv1_kernel<<<dim3(15, TB / 128), 256, GSMEM>>>(l);
        kv2_kernel<<<dim3(24, TB / 128), 256, GSMEM>>>(l);
        rope_kernel<<<(TB * NH * 32 + 255) / 256, 256>>>();
        attn_kernel<<<dim3(SEQ / AQ, BATCH * NH), 256, ASMEM>>>();
        wo_kernel<<<dim3(DIM / 64, TB / 128), 256, GSMEM>>>(l);

        // --- MoE block ---
        ln_kernel<<<TB, 256>>>(px, ln2_g + l * DIM, ln2_b + l * DIM);
        gate_kernel<<<TB, 256>>>(Wg + (size_t)l * DIM * NE);
        zero_kernel<<<1, 32>>>();
        topk_kernel<<<TB / 256, 256>>>();
        scan_kernel<<<1, 1>>>();
        assign_kernel<<<TB / 256, 256>>>();
        moe1_kernel<<<dim3(DFF / 64, 2 * TB / 128, NE), 256, GSMEM>>>(b1, l);
        moe2_kernel<<<dim3(DIM / 64, 2 * TB / 128, NE), 256, GSMEM>>>(b2, l);
        scatter_kernel<<<TB, 256>>>();
    }

    // --- final LN + LM head ---
    ln_kernel<<<TB, 256>>>(px, lnf_g, lnf_b);
    lmhead_kernel<<<dim3(NV / 64, TB / 128), 256, GSMEM>>>((float*)d_out);
}